// round 10
// baseline (speedup 1.0000x reference)
#include <cuda_runtime.h>
#include <cuda_bf16.h>
#include <math.h>
#include <float.h>

// ---------------- problem constants ----------------
#define V_  4096
#define D_  1024
#define H_  16
#define DH_ 64
#define NL_ 12
#define DFF_ 2752
#define B_  2
#define T_  1365
#define BT_ (B_*T_)          // 2730
#define ZLOSSW 1e-4f
#define DD_ ((size_t)D_ * D_)
#define DF_ ((size_t)D_ * DFF_)

typedef __nv_bfloat16 bf16;

__device__ __constant__ int c_bound[7] = {0, 1, 5, 21, 85, 341, 1365};

// ---------------- scratch (static device globals) ----------------
__device__ float g_h[BT_ * D_];
__device__ float g_logits[(size_t)BT_ * V_];
__device__ float g_ce[BT_];
__device__ float g_zl[BT_];
__device__ int   g_tok[BT_];
__device__ int   g_scl[T_];
__device__ float g_cos[T_ * DH_];
__device__ float g_sin[T_ * DH_];

// bf16 operands
__device__ bf16 g_hb[BT_ * D_];
__device__ bf16 g_vb[BT_ * D_];
__device__ bf16 g_qb[BT_ * D_];
__device__ bf16 g_kb[BT_ * D_];
__device__ bf16 g_ob[BT_ * D_];
__device__ bf16 g_tmpb[BT_ * D_];
__device__ bf16 g_ggb[(size_t)BT_ * DFF_];
// transposed bf16 weights ([N][K] k-contiguous for GEMM B operand)
__device__ bf16 g_wqt[NL_ * D_ * D_];
__device__ bf16 g_wkt[NL_ * D_ * D_];
__device__ bf16 g_wvt[NL_ * D_ * D_];
__device__ bf16 g_wot[NL_ * D_ * D_];
__device__ bf16 g_w1t[(size_t)NL_ * DFF_ * D_];
__device__ bf16 g_w3t[(size_t)NL_ * DFF_ * D_];
__device__ bf16 g_w2t[(size_t)NL_ * D_ * DFF_];
__device__ bf16 g_embb[V_ * D_];

// ---------------- helpers ----------------
__device__ __forceinline__ void scale_of(int t, int& s, int& p) {
    if (t < 1)        { s = 0; p = t; }
    else if (t < 5)   { s = 1; p = t - 1; }
    else if (t < 21)  { s = 2; p = t - 5; }
    else if (t < 85)  { s = 3; p = t - 21; }
    else if (t < 341) { s = 4; p = t - 85; }
    else              { s = 5; p = t - 341; }
}

__device__ __forceinline__ float blockReduceSum(float v) {
    __shared__ float sm[32];
    __syncthreads();
    int lane = threadIdx.x & 31, w = threadIdx.x >> 5;
    #pragma unroll
    for (int o = 16; o; o >>= 1) v += __shfl_xor_sync(0xffffffffu, v, o);
    if (lane == 0) sm[w] = v;
    __syncthreads();
    int nw = (blockDim.x + 31) >> 5;
    v = (threadIdx.x < nw) ? sm[threadIdx.x] : 0.f;
    if (w == 0) {
        #pragma unroll
        for (int o = 16; o; o >>= 1) v += __shfl_xor_sync(0xffffffffu, v, o);
        if (lane == 0) sm[0] = v;
    }
    __syncthreads();
    return sm[0];
}

__device__ __forceinline__ float blockReduceMax(float v) {
    __shared__ float sm[32];
    __syncthreads();
    int lane = threadIdx.x & 31, w = threadIdx.x >> 5;
    #pragma unroll
    for (int o = 16; o; o >>= 1) v = fmaxf(v, __shfl_xor_sync(0xffffffffu, v, o));
    if (lane == 0) sm[w] = v;
    __syncthreads();
    int nw = (blockDim.x + 31) >> 5;
    v = (threadIdx.x < nw) ? sm[threadIdx.x] : -FLT_MAX;
    if (w == 0) {
        #pragma unroll
        for (int o = 16; o; o >>= 1) v = fmaxf(v, __shfl_xor_sync(0xffffffffu, v, o));
        if (lane == 0) sm[0] = v;
    }
    __syncthreads();
    return sm[0];
}

__device__ __forceinline__ unsigned smem_u32(const void* p) {
    return (unsigned)__cvta_generic_to_shared(p);
}
__device__ __forceinline__ void cpa16(unsigned dst, const void* src, bool ok) {
    int sz = ok ? 16 : 0;
    asm volatile("cp.async.cg.shared.global [%0], [%1], 16, %2;\n"
                 :: "r"(dst), "l"(src), "r"(sz));
}
#define CP_COMMIT   asm volatile("cp.async.commit_group;\n")
#define CP_WAITG(N) asm volatile("cp.async.wait_group %0;\n" :: "n"(N))

__device__ __forceinline__ void ldm4(unsigned addr, unsigned* r) {
    asm volatile("ldmatrix.sync.aligned.m8n8.x4.shared.b16 {%0,%1,%2,%3}, [%4];"
        : "=r"(r[0]), "=r"(r[1]), "=r"(r[2]), "=r"(r[3]) : "r"(addr));
}
__device__ __forceinline__ void ldm4t(unsigned addr, unsigned* r) {
    asm volatile("ldmatrix.sync.aligned.m8n8.x4.trans.shared.b16 {%0,%1,%2,%3}, [%4];"
        : "=r"(r[0]), "=r"(r[1]), "=r"(r[2]), "=r"(r[3]) : "r"(addr));
}
__device__ __forceinline__ unsigned packbf2(float lo, float hi) {
    unsigned r;
    asm("cvt.rn.bf16x2.f32 %0, %1, %2;" : "=r"(r) : "f"(hi), "f"(lo));
    return r;
}
#define MMA_BF16(d, a, b) asm volatile( \
  "mma.sync.aligned.m16n8k16.row.col.f32.bf16.bf16.f32 " \
  "{%0,%1,%2,%3},{%4,%5,%6,%7},{%8,%9},{%0,%1,%2,%3};\n" \
  : "+f"(d[0]), "+f"(d[1]), "+f"(d[2]), "+f"(d[3]) \
  : "r"(a[0]), "r"(a[1]), "r"(a[2]), "r"(a[3]), "r"(b[0]), "r"(b[1]))

// ---------------- bf16 tensor-core GEMM (4-stage cp.async pipeline) ----------------
// C = alpha * A @ B^T; A [M][lda] k-contig, B [N][ldb] k-contig.
// 128 x 128 x 32 tiles, 256 threads (8 warps, 4Mx2N).
// EPI: 0 fp32 out, 1 bf16 out, 2 fused QKV epilogue (z=0: q rms+rope -> Cq,
//      z=1: k rms+rope -> Ck, z=2: v bf16 -> Cb).
template<int BN, int EPI>
__global__ __launch_bounds__(256, 2) void gemm_bf(
    const bf16* __restrict__ A, const bf16* __restrict__ B0,
    const bf16* __restrict__ B1, const bf16* __restrict__ B2,
    float* __restrict__ Cf, bf16* __restrict__ Cb,
    bf16* __restrict__ Cq, bf16* __restrict__ Ck,
    const float* __restrict__ gq, const float* __restrict__ gk,
    int M, int N, int K, int lda, int ldb, int ldc,
    long long sC0, float alpha)
{
    constexpr int BM = 128, BK = 32;
    constexpr int NI = BN / 16;
    constexpr int RSB = 80;
    constexpr int ABYTES = BM * RSB;
    constexpr int BBYTES = BN * RSB;
    constexpr int STG = ABYTES + BBYTES;
    constexpr int NSTG = 4;

    const int z = blockIdx.z;
    const bf16* Bp;
    if (B1) Bp = (z == 0) ? B0 : ((z == 1) ? B1 : B2);
    else    Bp = B0;
    const long long coff = (long long)z * sC0;

    const int row0 = blockIdx.y * BM, col0 = blockIdx.x * BN;

    extern __shared__ char smdyn[];
    const unsigned sbase = smem_u32(smdyn);
    const int tid = threadIdx.x, lane = tid & 31, warp = tid >> 5;
    const int wm = warp >> 1, wn = warp & 1;

    auto issue = [&](int it, int buf) {
        const int k0 = it * BK;
        const unsigned as = sbase + buf * STG;
        const unsigned bs = as + ABYTES;
        #pragma unroll
        for (int i = 0; i < 2; i++) {
            int c = tid + i * 256;
            int r = c >> 2, kc = c & 3;
            int gk0 = k0 + kc * 8;
            bool ok = (row0 + r < M) && (gk0 < K);
            const bf16* src = ok ? (A + (size_t)(row0 + r) * lda + gk0) : A;
            cpa16(as + r * RSB + kc * 16, src, ok);
        }
        constexpr int BCH = BN * 4;
        #pragma unroll
        for (int i = 0; i < (BCH + 255) / 256; i++) {
            int c = tid + i * 256;
            if (c < BCH) {
                int r = c >> 2, kc = c & 3;
                int gk0 = k0 + kc * 8;
                bool ok = (col0 + r < N) && (gk0 < K);
                const bf16* src = ok ? (Bp + (size_t)(col0 + r) * ldb + gk0) : Bp;
                cpa16(bs + r * RSB + kc * 16, src, ok);
            }
        }
    };

    float acc[2][NI][4] = {};
    const int nIter = (K + BK - 1) / BK;

    issue(0, 0); CP_COMMIT;
    issue(1, 1); CP_COMMIT;
    issue(2, 2); CP_COMMIT;

    const unsigned foff = (unsigned)((lane & 15) * RSB + (lane >> 4) * 16);
    const int gr = lane >> 2, gc = lane & 3;

    for (int it = 0; it < nIter; it++) {
        CP_WAITG(2);
        __syncthreads();
        if (it + 3 < nIter) issue(it + 3, (it + 3) % NSTG);
        CP_COMMIT;
        const unsigned as = sbase + (it % NSTG) * STG;
        const unsigned bs = as + ABYTES;
        #pragma unroll
        for (int ks = 0; ks < 2; ks++) {
            unsigned ra[2][4];
            #pragma unroll
            for (int mi = 0; mi < 2; mi++)
                ldm4(as + (wm * 32 + mi * 16) * RSB + ks * 32 + foff, ra[mi]);
            unsigned rb[NI][2];
            #pragma unroll
            for (int nj = 0; nj < NI / 2; nj++) {
                unsigned t[4];
                ldm4(bs + (wn * (BN / 2) + nj * 16) * RSB + ks * 32 + foff, t);
                rb[nj * 2][0] = t[0]; rb[nj * 2 + 1][0] = t[1];
                rb[nj * 2][1] = t[2]; rb[nj * 2 + 1][1] = t[3];
            }
            #pragma unroll
            for (int mi = 0; mi < 2; mi++)
                #pragma unroll
                for (int ni = 0; ni < NI; ni++)
                    MMA_BF16(acc[mi][ni], ra[mi], rb[ni]);
        }
    }

    if constexpr (EPI == 2) {
        if (z == 2) {
            // V: plain bf16 store
            #pragma unroll
            for (int mi = 0; mi < 2; mi++)
                #pragma unroll
                for (int ni = 0; ni < NI; ni++) {
                    int c = col0 + wn * (BN / 2) + ni * 8 + gc * 2;
                    #pragma unroll
                    for (int rr = 0; rr < 2; rr++) {
                        int r = row0 + wm * 32 + mi * 16 + gr + rr * 8;
                        if (r < M) {
                            unsigned v = packbf2(acc[mi][ni][rr * 2], acc[mi][ni][rr * 2 + 1]);
                            *(unsigned*)(Cb + (size_t)r * ldc + c) = v;
                        }
                    }
                }
        } else {
            // q/k: per-head RMSNorm (64 cols = exactly this warp's tile half) + RoPE.
            const float* gg = (z == 0) ? gq : gk;
            bf16* outp = (z == 0) ? Cq : Ck;
            float gv[8][2];
            #pragma unroll
            for (int ni = 0; ni < 8; ni++) {
                gv[ni][0] = gg[ni * 8 + gc * 2];
                gv[ni][1] = gg[ni * 8 + gc * 2 + 1];
            }
            const int cbase = col0 + wn * 64;
            #pragma unroll
            for (int mi = 0; mi < 2; mi++)
                #pragma unroll
                for (int rr = 0; rr < 2; rr++) {
                    float ss = 0.f;
                    #pragma unroll
                    for (int ni = 0; ni < 8; ni++) {
                        float a0 = acc[mi][ni][rr * 2], a1 = acc[mi][ni][rr * 2 + 1];
                        ss += a0 * a0 + a1 * a1;
                    }
                    ss += __shfl_xor_sync(0xffffffffu, ss, 1);
                    ss += __shfl_xor_sync(0xffffffffu, ss, 2);
                    float rn = rsqrtf(ss * (1.f / 64.f) + 1e-6f);
                    int r = row0 + wm * 32 + mi * 16 + gr + rr * 8;
                    if (r < M) {
                        int t = r % T_;
                        const float* cp = g_cos + t * 64;
                        const float* sp = g_sin + t * 64;
                        #pragma unroll
                        for (int ni = 0; ni < 4; ni++) {
                            int d = ni * 8 + gc * 2;
                            float x1a = acc[mi][ni][rr * 2]     * rn * gv[ni][0];
                            float x1b = acc[mi][ni][rr * 2 + 1] * rn * gv[ni][1];
                            float x2a = acc[mi][ni + 4][rr * 2]     * rn * gv[ni + 4][0];
                            float x2b = acc[mi][ni + 4][rr * 2 + 1] * rn * gv[ni + 4][1];
                            unsigned o1 = packbf2(x1a * cp[d]     - x2a * sp[d],
                                                  x1b * cp[d + 1] - x2b * sp[d + 1]);
                            unsigned o2 = packbf2(x2a * cp[d + 32] + x1a * sp[d + 32],
                                                  x2b * cp[d + 33] + x1b * sp[d + 33]);
                            size_t base = (size_t)r * D_ + cbase + d;
                            *(unsigned*)(outp + base)      = o1;
                            *(unsigned*)(outp + base + 32) = o2;
                        }
                    }
                }
        }
    } else {
        #pragma unroll
        for (int mi = 0; mi < 2; mi++) {
            #pragma unroll
            for (int ni = 0; ni < NI; ni++) {
                int c = col0 + wn * (BN / 2) + ni * 8 + gc * 2;
                #pragma unroll
                for (int rr = 0; rr < 2; rr++) {
                    int r = row0 + wm * 32 + mi * 16 + gr + rr * 8;
                    if (r < M) {
                        long long base = coff + (long long)r * ldc + c;
                        float v0 = alpha * acc[mi][ni][rr * 2];
                        float v1 = alpha * acc[mi][ni][rr * 2 + 1];
                        if (EPI == 0) {
                            if (c < N)     Cf[base]     = v0;
                            if (c + 1 < N) Cf[base + 1] = v1;
                        } else {
                            if (c < N)     Cb[base]     = __float2bfloat16(v0);
                            if (c + 1 < N) Cb[base + 1] = __float2bfloat16(v1);
                        }
                    }
                }
            }
        }
    }
}

// ---------------- bf16 GEMM, 64x128 tiles, 128 threads, 3 CTAs/SM ----------------
__global__ __launch_bounds__(128, 3) void gemm64(
    const bf16* __restrict__ A, const bf16* __restrict__ B0, bf16* __restrict__ Cb,
    int M, int N, int K, int lda, int ldb, int ldc)
{
    constexpr int BM = 64, BN = 128, BK = 32, RSB = 80;
    constexpr int ABYTES = BM * RSB;
    constexpr int BBYTES = BN * RSB;
    constexpr int STG = ABYTES + BBYTES;
    constexpr int NSTG = 4;

    const int row0 = blockIdx.y * BM, col0 = blockIdx.x * BN;
    extern __shared__ char smdyn[];
    const unsigned sbase = smem_u32(smdyn);
    const int tid = threadIdx.x, lane = tid & 31, warp = tid >> 5;
    const int wm = warp >> 1, wn = warp & 1;

    auto issue = [&](int it, int buf) {
        const int k0 = it * BK;
        const unsigned as = sbase + buf * STG;
        const unsigned bs = as + ABYTES;
        #pragma unroll
        for (int i = 0; i < 2; i++) {
            int c = tid + i * 128;
            int r = c >> 2, kc = c & 3;
            int gk = k0 + kc * 8;
            bool ok = (row0 + r < M) && (gk < K);
            cpa16(as + r * RSB + kc * 16, ok ? A + (size_t)(row0 + r) * lda + gk : A, ok);
        }
        #pragma unroll
        for (int i = 0; i < 4; i++) {
            int c = tid + i * 128;
            int r = c >> 2, kc = c & 3;
            int gk = k0 + kc * 8;
            bool ok = (col0 + r < N) && (gk < K);
            cpa16(bs + r * RSB + kc * 16, ok ? B0 + (size_t)(col0 + r) * ldb + gk : B0, ok);
        }
    };

    float acc[2][8][4] = {};
    const int nIter = (K + BK - 1) / BK;
    issue(0, 0); CP_COMMIT;
    issue(1, 1); CP_COMMIT;
    issue(2, 2); CP_COMMIT;

    const unsigned foff = (unsigned)((lane & 15) * RSB + (lane >> 4) * 16);
    const int gr = lane >> 2, gc = lane & 3;

    for (int it = 0; it < nIter; it++) {
        CP_WAITG(2);
        __syncthreads();
        if (it + 3 < nIter) issue(it + 3, (it + 3) % NSTG);
        CP_COMMIT;
        const unsigned as = sbase + (it % NSTG) * STG;
        const unsigned bs = as + ABYTES;
        #pragma unroll
        for (int ks = 0; ks < 2; ks++) {
            unsigned ra[2][4];
            #pragma unroll
            for (int mi = 0; mi < 2; mi++)
                ldm4(as + (wm * 32 + mi * 16) * RSB + ks * 32 + foff, ra[mi]);
            unsigned rb[8][2];
            #pragma unroll
            for (int nj = 0; nj < 4; nj++) {
                unsigned t[4];
                ldm4(bs + (wn * 64 + nj * 16) * RSB + ks * 32 + foff, t);
                rb[nj * 2][0] = t[0]; rb[nj * 2 + 1][0] = t[1];
                rb[nj * 2][1] = t[2]; rb[nj * 2 + 1][1] = t[3];
            }
            #pragma unroll
            for (int mi = 0; mi < 2; mi++)
                #pragma unroll
                for (int ni = 0; ni < 8; ni++)
                    MMA_BF16(acc[mi][ni], ra[mi], rb[ni]);
        }
    }

    #pragma unroll
    for (int mi = 0; mi < 2; mi++)
        #pragma unroll
        for (int ni = 0; ni < 8; ni++) {
            int c = col0 + wn * 64 + ni * 8 + gc * 2;
            #pragma unroll
            for (int rr = 0; rr < 2; rr++) {
                int r = row0 + wm * 32 + mi * 16 + gr + rr * 8;
                if (r < M && c < N) {
                    unsigned v = packbf2(acc[mi][ni][rr * 2], acc[mi][ni][rr * 2 + 1]);
                    *(unsigned*)(Cb + (size_t)r * ldc + c) = v;
                }
            }
        }
}

// ---------------- fused SwiGLU FFN GEMM (4 stages) ----------------
__global__ __launch_bounds__(256, 2) void gemm_ffn(
    const bf16* __restrict__ A, const bf16* __restrict__ W1, const bf16* __restrict__ W3,
    bf16* __restrict__ C, int M, int N, int K)
{
    constexpr int BM = 128, BN = 64, BK = 32, RSB = 80;
    constexpr int ABYTES = BM * RSB, BBYTES = BN * RSB;
    constexpr int STG = ABYTES + 2 * BBYTES;
    constexpr int NSTG = 4;

    const int row0 = blockIdx.y * BM, col0 = blockIdx.x * BN;
    extern __shared__ char smdyn[];
    const unsigned sbase = smem_u32(smdyn);
    const int tid = threadIdx.x, lane = tid & 31, warp = tid >> 5;
    const int wm = warp >> 1, wn = warp & 1;

    auto issue = [&](int it, int buf) {
        const int k0 = it * BK;
        const unsigned as = sbase + buf * STG;
        const unsigned b1s = as + ABYTES, b3s = b1s + BBYTES;
        #pragma unroll
        for (int i = 0; i < 2; i++) {
            int c = tid + i * 256;
            int r = c >> 2, kc = c & 3;
            int gk = k0 + kc * 8;
            bool ok = (row0 + r < M) && (gk < K);
            cpa16(as + r * RSB + kc * 16, ok ? A + (size_t)(row0 + r) * K + gk : A, ok);
        }
        {
            int r = tid >> 2, kc = tid & 3;
            int gk = k0 + kc * 8;
            bool ok = (col0 + r < N) && (gk < K);
            cpa16(b1s + r * RSB + kc * 16, ok ? W1 + (size_t)(col0 + r) * K + gk : W1, ok);
            cpa16(b3s + r * RSB + kc * 16, ok ? W3 + (size_t)(col0 + r) * K + gk : W3, ok);
        }
    };

    float acc1[2][4][4] = {}, acc3[2][4][4] = {};
    const int nIter = (K + BK - 1) / BK;
    issue(0, 0); CP_COMMIT;
    issue(1, 1); CP_COMMIT;
    issue(2, 2); CP_COMMIT;

    const unsigned foff = (unsigned)((lane & 15) * RSB + (lane >> 4) * 16);
    const int gr = lane >> 2, gc = lane & 3;

    for (int it = 0; it < nIter; it++) {
        CP_WAITG(2);
        __syncthreads();
        if (it + 3 < nIter) issue(it + 3, (it + 3) % NSTG);
        CP_COMMIT;
        const unsigned as = sbase + (it % NSTG) * STG;
        const unsigned b1s = as + ABYTES, b3s = b1s + BBYTES;
        #pragma unroll
        for (int ks = 0; ks < 2; ks++) {
            unsigned ra[2][4];
            #pragma unroll
            for (int mi = 0; mi < 2; mi++)
                ldm4(as + (wm * 32 + mi * 16) * RSB + ks * 32 + foff, ra[mi]);
            unsigned r1[4][2], r3[4][2];
            #pragma unroll
            for (int nj = 0; nj < 2; nj++) {
                unsigned t[4];
                ldm4(b1s + (wn * 32 + nj * 16) * RSB + ks * 32 + foff, t);
                r1[nj * 2][0] = t[0]; r1[nj * 2 + 1][0] = t[1];
                r1[nj * 2][1] = t[2]; r1[nj * 2 + 1][1] = t[3];
                ldm4(b3s + (wn * 32 + nj * 16) * RSB + ks * 32 + foff, t);
                r3[nj * 2][0] = t[0]; r3[nj * 2 + 1][0] = t[1];
                r3[nj * 2][1] = t[2]; r3[nj * 2 + 1][1] = t[3];
            }
            #pragma unroll
            for (int mi = 0; mi < 2; mi++)
                #pragma unroll
                for (int ni = 0; ni < 4; ni++) {
                    MMA_BF16(acc1[mi][ni], ra[mi], r1[ni]);
                    MMA_BF16(acc3[mi][ni], ra[mi], r3[ni]);
                }
        }
    }

    #pragma unroll
    for (int mi = 0; mi < 2; mi++)
        #pragma unroll
        for (int ni = 0; ni < 4; ni++) {
            int c = col0 + wn * 32 + ni * 8 + gc * 2;
            #pragma unroll
            for (int rr = 0; rr < 2; rr++) {
                int r = row0 + wm * 32 + mi * 16 + gr + rr * 8;
                if (r < M) {
                    float x0 = acc1[mi][ni][rr * 2],     y0 = acc3[mi][ni][rr * 2];
                    float x1 = acc1[mi][ni][rr * 2 + 1], y1 = acc3[mi][ni][rr * 2 + 1];
                    float g0 = x0 / (1.f + expf(-x0)) * y0;
                    float g1 = x1 / (1.f + expf(-x1)) * y1;
                    size_t base = (size_t)r * N + c;
                    C[base]     = __float2bfloat16(g0);
                    C[base + 1] = __float2bfloat16(g1);
                }
            }
        }
}

// ---------------- fused flash attention (prefix mask, FIXED-max softmax) ----------------
// 2 CTAs/SM: 64-key sub-chunks keep live registers ~<128/thread at 512 threads.
#define FL_ROWB 144
__global__ __launch_bounds__(256, 2) void k_flash() {
    extern __shared__ char smdyn[];
    const unsigned uQ = smem_u32(smdyn);
    const unsigned uK = uQ + 128 * FL_ROWB;
    const unsigned uV = uK + 2 * 128 * FL_ROWB;

    const int z = blockIdx.y;
    const int b = z >> 4, h = z & 15;
    const int row0 = blockIdx.x * 128;
    const int tid = threadIdx.x, lane = tid & 31, warp = tid >> 5;

    int sl, pl; scale_of(min(row0 + 127, T_ - 1), sl, pl);
    const int Lmax = c_bound[sl + 1];
    const int nkb = (Lmax + 127) >> 7;

    const size_t hoff = ((size_t)b * T_) * D_ + h * DH_;
    const bf16* qg = g_qb + hoff;
    const bf16* kg = g_kb + hoff;
    const bf16* vg = g_vb + hoff;
    bf16* og = g_ob + hoff;

    const int lr = tid >> 1, lc0 = (tid & 1) * 4;
    {
        bool ok = (row0 + lr) < T_;
        const bf16* s = qg + (size_t)(row0 + lr) * D_ + lc0 * 8;
        #pragma unroll
        for (int j = 0; j < 4; j++) cpa16(uQ + lr * FL_ROWB + (lc0 + j) * 16, s + j * 8, ok);
    }
    auto issueKV = [&](int kb, int buf) {
        int jr = kb * 128 + lr;
        bool ok = jr < T_;
        const bf16* sk = kg + (size_t)jr * D_ + lc0 * 8;
        const bf16* sv = vg + (size_t)jr * D_ + lc0 * 8;
        unsigned off = buf * (128 * FL_ROWB) + lr * FL_ROWB + lc0 * 16;
        #pragma unroll
        for (int j = 0; j < 4; j++) {
            cpa16(uK + off + j * 16, sk + j * 8, ok);
            cpa16(uV + off + j * 16, sv + j * 8, ok);
        }
    };
    issueKV(0, 0); CP_COMMIT;
    if (nkb > 1) issueKV(1, 1);
    CP_COMMIT;
    CP_WAITG(1);
    __syncthreads();

    const unsigned foff = (unsigned)((lane & 15) * FL_ROWB + (lane >> 4) * 16);
    unsigned aq[4][4];
    #pragma unroll
    for (int ks = 0; ks < 4; ks++)
        ldm4(uQ + (warp * 16) * FL_ROWB + ks * 32 + foff, aq[ks]);

    const int gr = lane >> 2, gc = lane & 3;
    const int r0g = row0 + warp * 16 + gr;
    int Li0 = 0, Li1 = 0;
    if (r0g < T_)     { int s2, p2; scale_of(r0g, s2, p2);     Li0 = c_bound[s2 + 1]; }
    if (r0g + 8 < T_) { int s2, p2; scale_of(r0g + 8, s2, p2); Li1 = c_bound[s2 + 1]; }

    float l0 = 0.f, l1 = 0.f;
    float oacc[8][4] = {};
    const float ALPHA = 0.125f * 1.4426950408889634f;

    for (int kb = 0; kb < nkb; kb++) {
        const unsigned bK = uK + (kb & 1) * (128 * FL_ROWB);
        const unsigned bV = uV + (kb & 1) * (128 * FL_ROWB);

        float sum0 = 0.f, sum1 = 0.f;
        #pragma unroll
        for (int half = 0; half < 2; half++) {
            // S = Q @ K^T over 64 keys
            float s[8][4];
            #pragma unroll
            for (int i = 0; i < 8; i++) { s[i][0] = s[i][1] = s[i][2] = s[i][3] = 0.f; }
            #pragma unroll
            for (int ks = 0; ks < 4; ks++) {
                #pragma unroll
                for (int n2 = 0; n2 < 4; n2++) {
                    unsigned t[4];
                    ldm4(bK + (half * 64 + n2 * 16) * FL_ROWB + ks * 32 + foff, t);
                    unsigned b0[2] = {t[0], t[2]}, b1[2] = {t[1], t[3]};
                    MMA_BF16(s[n2 * 2],     aq[ks], b0);
                    MMA_BF16(s[n2 * 2 + 1], aq[ks], b1);
                }
            }
            // fixed-max masked exp + partial sums
            const int j0 = kb * 128 + half * 64;
            #pragma unroll
            for (int ni = 0; ni < 8; ni++) {
                int jc = j0 + ni * 8 + 2 * gc;
                float p0 = (jc     < Li0) ? exp2f(fmaf(s[ni][0], ALPHA, -12.f)) : 0.f;
                float p1 = (jc + 1 < Li0) ? exp2f(fmaf(s[ni][1], ALPHA, -12.f)) : 0.f;
                float p2 = (jc     < Li1) ? exp2f(fmaf(s[ni][2], ALPHA, -12.f)) : 0.f;
                float p3 = (jc + 1 < Li1) ? exp2f(fmaf(s[ni][3], ALPHA, -12.f)) : 0.f;
                s[ni][0] = p0; s[ni][1] = p1; s[ni][2] = p2; s[ni][3] = p3;
                sum0 += p0 + p1; sum1 += p2 + p3;
            }
            // O += P @ V over this 64-key chunk
            #pragma unroll
            for (int j = 0; j < 4; j++) {
                unsigned pa[4];
                pa[0] = packbf2(s[2 * j][0],     s[2 * j][1]);
                pa[1] = packbf2(s[2 * j][2],     s[2 * j][3]);
                pa[2] = packbf2(s[2 * j + 1][0], s[2 * j + 1][1]);
                pa[3] = packbf2(s[2 * j + 1][2], s[2 * j + 1][3]);
                unsigned vrow = bV + (half * 64 + j * 16 + (lane & 7)
                                       + 8 * ((lane >> 3) & 1)) * FL_ROWB
                                   + (lane >> 4) * 16;
                #pragma unroll
                for (int d2 = 0; d2 < 4; d2++) {
                    unsigned t[4];
                    ldm4t(vrow + d2 * 32, t);
                    unsigned vb0[2] = {t[0], t[1]}, vb1[2] = {t[2], t[3]};
                    MMA_BF16(oacc[d2 * 2],     pa, vb0);
                    MMA_BF16(oacc[d2 * 2 + 1], pa, vb1);
                }
            }
        }
        sum0 += __shfl_xor_sync(0xffffffffu, sum0, 1);
        sum0 += __shfl_xor_sync(0xffffffffu, sum0, 2);
        sum1 += __shfl_xor_sync(0xffffffffu, sum1, 1);
        sum1 += __shfl_xor_sync(0xffffffffu, sum1, 2);
        l0 += sum0; l1 += sum1;

        __syncthreads();
        if (kb + 2 < nkb) issueKV(kb + 2, kb & 1);
        CP_COMMIT;
        CP_WAITG(1);
        __syncthreads();
    }

    float li0 = 1.f / l0, li1 = 1.f / l1;
    #pragma unroll
    for (int t8 = 0; t8 < 8; t8++) {
        int c = t8 * 8 + 2 * gc;
        if (r0g < T_) {
            og[(size_t)r0g * D_ + c]     = __float2bfloat16(oacc[t8][0] * li0);
            og[(size_t)r0g * D_ + c + 1] = __float2bfloat16(oacc[t8][1] * li0);
        }
        if (r0g + 8 < T_) {
            og[(size_t)(r0g + 8) * D_ + c]     = __float2bfloat16(oacc[t8][2] * li1);
            og[(size_t)(r0g + 8) * D_ + c + 1] = __float2bfloat16(oacc[t8][3] * li1);
        }
    }
}

// ---------------- merged weight conversion: 64x64 tiles, vectorized ----------------
__global__ __launch_bounds__(256) void k_convW(
    const float* __restrict__ wq, const float* __restrict__ wk,
    const float* __restrict__ wv, const float* __restrict__ wo,
    const float* __restrict__ w1, const float* __restrict__ w3,
    const float* __restrict__ w2) {
    __shared__ float t[64][65];
    int idx = blockIdx.x;
    const float* src; bf16* dst; int R, C, r0, c0;
    if (idx < 12288) {
        int tsel = idx / 3072, rem = idx % 3072;
        int zz = rem >> 8, tile = rem & 255;
        r0 = (tile >> 4) * 64; c0 = (tile & 15) * 64; R = 1024; C = 1024;
        const float* s4[4] = {wq, wk, wv, wo};
        bf16* d4[4] = {g_wqt, g_wkt, g_wvt, g_wot};
        src = s4[tsel] + (size_t)zz * DD_; dst = d4[tsel] + (size_t)zz * DD_;
    } else if (idx < 28800) {
        int rem = idx - 12288;
        int tsel = rem / 8256; rem %= 8256;
        int zz = rem / 688, tile = rem % 688;
        r0 = (tile / 43) * 64; c0 = (tile % 43) * 64; R = 1024; C = 2752;
        src = (tsel ? w3 : w1) + (size_t)zz * DF_;
        dst = (tsel ? g_w3t : g_w1t) + (size_t)zz * DF_;
    } else {
        int rem = idx - 28800;
        int zz = rem / 688, tile = rem % 688;
        r0 = (tile / 16) * 64; c0 = (tile % 16) * 64; R = 2752; C = 1024;
        src = w2 + (size_t)zz * DF_; dst = g_w2t + (size_t)zz * DF_;
    }
    int tx = threadIdx.x;
    int lr = tx >> 4, lc = (tx & 15) * 4;
    #pragma unroll
    for (int it = 0; it < 4; it++) {
        int r = it * 16 + lr;
        float4 v = *(const float4*)(src + (size_t)(r0 + r) * C + c0 + lc);
        t[r][lc] = v.x; t[r][lc + 1] = v.y; t[r][lc + 2] = v.z; t[r][lc + 3] = v.w;
    }
    __syncthreads();
    int sc = tx >> 5, sr = (tx & 31) * 2;
    #pragma unroll
    for (int it = 0; it < 8; it++) {
        int cc = it * 8 + sc;
        unsigned v = packbf2(t[sr][cc], t[sr + 1][cc]);
        *(unsigned*)(dst + (size_t)(c0 + cc) * R + r0 + sr) = v;
    }
}

// vectorized fp32 -> bf16 convert: 8 elements per thread (n must be mult of 8)
__global__ void k_cvt8(const float* __restrict__ s, bf16* __restrict__ d, long long n8) {
    long long i = (long long)blockIdx.x * blockDim.x + threadIdx.x;
    if (i >= n8) return;
    const float4* s4 = (const float4*)s + i * 2;
    float4 a = s4[0], b = s4[1];
    uint4 o;
    o.x = packbf2(a.x, a.y); o.y = packbf2(a.z, a.w);
    o.z = packbf2(b.x, b.y); o.w = packbf2(b.z, b.w);
    ((uint4*)d)[i] = o;
}

// ---------------- small kernels ----------------
__global__ void k_static() {
    int t = blockIdx.x, d = threadIdx.x;
    int s, p; scale_of(t, s, p);
    if (d == 0) g_scl[t] = s;
    int i = d & 31;
    float inv = powf(10000.f, -(float)(2 * i) / 64.f);
    float ang = (float)p * inv;
    g_cos[t * 64 + d] = cosf(ang);
    g_sin[t * 64 + d] = sinf(ang);
}

__global__ void k_tokens(const int* i0, const int* i1, const int* i2,
                         const int* i3, const int* i4, const int* i5) {
    int idx = blockIdx.x * blockDim.x + threadIdx.x;
    if (idx >= BT_) return;
    int b = idx / T_, t = idx - b * T_;
    int s, p; scale_of(t, s, p);
    const int* arr[6] = {i0, i1, i2, i3, i4, i5};
    int sz = 1 << (2 * s);
    g_tok[idx] = arr[s][b * sz + p];
}

__global__ void k_embed(const float* __restrict__ E, const float* __restrict__ SE,
                        const float* __restrict__ start) {
    int row = blockIdx.x;
    int t = row % T_;
    int s = g_scl[t];
    const float* src = (t == 0) ? start : (E + (long long)g_tok[row] * D_);
    const float* se = SE + s * D_;
    float* hp = g_h + (size_t)row * D_;
    bf16* hb = g_hb + (size_t)row * D_;
    for (int d = threadIdx.x; d < D_; d += blockDim.x) {
        float x = src[d] + se[d];
        hp[d] = x;
        hb[d] = __float2bfloat16(x);
    }
}

// h = RMSNorm(h + delta) * gain, delta bf16
__global__ void k_rms(float* __restrict__ h, const bf16* __restrict__ delta,
                      const float* __restrict__ gain) {
    int row = blockIdx.x;
    float* hp = h + (size_t)row * D_;
    bf16* hb = g_hb + (size_t)row * D_;
    const bf16* dp = delta + (size_t)row * D_;
    float ss = 0.f;
    for (int d = threadIdx.x; d < D_; d += blockDim.x) {
        float x = hp[d] + __bfloat162float(dp[d]);
        ss += x * x;
    }
    ss = blockReduceSum(ss);
    float r = rsqrtf(ss / (float)D_ + 1e-6f);
    for (int d = threadIdx.x; d < D_; d += blockDim.x) {
        float x = (hp[d] + __bfloat162float(dp[d])) * r * gain[d];
        hp[d] = x;
        hb[d] = __float2bfloat16(x);
    }
}

__global__ void k_loss_row() {
    int row = blockIdx.x;
    const float* lp = g_logits + (size_t)row * V_;
    float m = -FLT_MAX;
    for (int j = threadIdx.x; j < V_; j += blockDim.x) m = fmaxf(m, lp[j]);
    m = blockReduceMax(m);
    float s = 0.f;
    for (int j = threadIdx.x; j < V_; j += blockDim.x) s += expf(lp[j] - m);
    s = blockReduceSum(s);
    if (threadIdx.x == 0) {
        float lse = m + logf(s);
        g_ce[row] = lse - lp[g_tok[row]];
        g_zl[row] = lse * lse;
    }
}

__global__ void k_loss_final(float* out) {
    float s1 = 0.f, s2 = 0.f;
    for (int j = threadIdx.x; j < BT_; j += blockDim.x) { s1 += g_ce[j]; s2 += g_zl[j]; }
    s1 = blockReduceSum(s1);
    s2 = blockReduceSum(s2);
    if (threadIdx.x == 0) out[0] = s1 / (float)BT_ + ZLOSSW * (s2 / (float)BT_);
}

// ---------------- entry point ----------------
extern "C" void kernel_launch(void* const* d_in, const int* in_sizes, int n_in,
                              void* d_out, int out_size) {
    const int* i0 = (const int*)d_in[0];
    const int* i1 = (const int*)d_in[1];
    const int* i2 = (const int*)d_in[2];
    const int* i3 = (const int*)d_in[3];
    const int* i4 = (const int*)d_in[4];
    const int* i5 = (const int*)d_in[5];
    const float* token_embed = (const float*)d_in[6];
    const float* scale_embed = (const float*)d_in[7];
    const float* start_token = (const float*)d_in[8];
    const float* wq = (const float*)d_in[9];
    const float* wk = (const float*)d_in[10];
    const float* wv = (const float*)d_in[11];
    const float* wo = (const float*)d_in[12];
    const float* qn = (const float*)d_in[13];
    const float* kn = (const float*)d_in[14];
    const float* n1 = (const float*)d_in[15];
    const float* n2 = (const float*)d_in[16];
    const float* w1 = (const float*)d_in[17];
    const float* w3 = (const float*)d_in[18];
    const float* w2 = (const float*)d_in[19];

    cudaFuncSetAttribute((const void*)gemm_bf<128, 0>,
                         cudaFuncAttributeMaxDynamicSharedMemorySize, 81920);
    cudaFuncSetAttribute((const void*)gemm_bf<128, 2>,
                         cudaFuncAttributeMaxDynamicSharedMemorySize, 81920);
    cudaFuncSetAttribute((const void*)gemm64,
                         cudaFuncAttributeMaxDynamicSharedMemorySize, 61440);
    cudaFuncSetAttribute((const void*)gemm_ffn,
                         cudaFuncAttributeMaxDynamicSharedMemorySize, 81920);
    cudaFuncSetAttribute((const void*)k_flash,
                         cudaFuncAttributeMaxDynamicSharedMemorySize, 92160);

    void* p;
    cudaGetSymbolAddress(&p, g_h);      float* h    = (float*)p;
    cudaGetSymbolAddress(&p, g_logits); float* lg   = (float*)p;
    cudaGetSymbolAddress(&p, g_hb);     bf16* hb    = (bf16*)p;
    cudaGetSymbolAddress(&p, g_vb);     bf16* vb    = (bf16*)p;
    cudaGetSymbolAddress(&p, g_qb);     bf16* qb    = (bf16*)p;
    cudaGetSymbolAddress(&p, g_kb);     bf16* kb    = (bf16*)p;
    cudaGetSymbolAddress(&p, g_ob);     bf16* ob    = (bf16*)p;
    cudaGetSymbolAddress(&p, g_tmpb);   bf16* tmpb  = (bf16*)p;
    cudaGetSymbolAddress(&p, g_ggb);    bf16* ggb   = (bf16*)p;
    cudaGetSymbolAddress(&p, g_wqt);    bf16* wqt   = (bf16*)p;
    cudaGetSymbolAddress(&p, g_wkt);    bf16* wkt   = (bf16*)p;
    cudaGetSymbolAddress(&p, g_wvt);    bf16* wvt   = (bf16*)p;
    cudaGetSymbolAddress(&p, g_wot);    bf16* wot   = (bf16*)p;
    cudaGetSymbolAddress(&p, g_w1t);    bf16* w1t   = (bf16*)p;
    cudaGetSymbolAddress(&p, g_w3t);    bf16* w3t   = (bf16*)p;
    cudaGetSymbolAddress(&p, g_w2t);    bf16* w2t   = (bf16*)p;
    cudaGetSymbolAddress(&p, g_embb);   bf16* embb  = (bf16*)p;

    const long long DD = (long long)D_ * D_;
    const long long DF = (long long)D_ * DFF_;

    k_tokens<<<(BT_ + 255) / 256, 256>>>(i0, i1, i2, i3, i4, i5);
    k_static<<<T_, 64>>>();
    k_convW<<<37056, 256>>>(wq, wk, wv, wo, w1, w3, w2);
    k_cvt8<<<((long long)V_ * D_ / 8 + 255) / 256, 256>>>(token_embed, embb,
                                                          (long long)V_ * D_ / 8);
    k_embed<<<BT_, 256>>>(token_embed, scale_embed, start_token);

    for (int l = 0; l < NL_; l++) {
        // fused QKV + per-head RMSNorm + RoPE epilogue (q->qb, k->kb, v->vb)
        gemm_bf<128, 2><<<dim3(8, 22, 3), 256, 81920>>>(
            hb, wqt + l * DD, wkt + l * DD, wvt + l * DD, nullptr, vb,
            qb, kb, qn + l * DH_, kn + l * DH_,
            BT_, D_, D_, D_, D_, D_, 0, 1.f);

        k_flash<<<dim3(11, B_ * H_), 256, 92160>>>();

        // attn output projection — 64x128 tiles, single balanced wave
        gemm64<<<dim3(8, 43), 128, 61440>>>(
            ob, wot + l * DD, tmpb, BT_, D_, D_, D_, D_, D_);

        k_rms<<<BT_, 256>>>(h, tmpb, n1 + l * D_);

        // fused SwiGLU
        gemm_ffn<<<dim3(43, 22, 1), 256, 81920>>>(
            hb, w1t + l * DF, w3t + l * DF, ggb, BT_, DFF_, D_);

        // down projection — 64x128 tiles
        gemm64<<<dim3(8, 43), 128, 61440>>>(
            ggb, w2t + l * DF, tmpb, BT_, D_, DFF_, DFF_, DFF_, D_);

        k_rms<<<BT_, 256>>>(h, tmpb, n2 + l * D_);
    }

    // logits = h @ token_embed^T
    gemm_bf<128, 0><<<dim3(32, 22, 1), 256, 81920>>>(
        hb, embb, nullptr, nullptr, lg, nullptr, nullptr, nullptr, nullptr, nullptr,
        BT_, V_, D_, D_, D_, V_, 0, 1.f);

    // loss
    k_loss_row<<<BT_, 256>>>();
    k_loss_final<<<1, 256>>>((float*)d_out);
}

// round 11
// speedup vs baseline: 1.0010x; 1.0010x over previous
#include <cuda_runtime.h>
#include <cuda_bf16.h>
#include <math.h>
#include <float.h>

// ---------------- problem constants ----------------
#define V_  4096
#define D_  1024
#define H_  16
#define DH_ 64
#define NL_ 12
#define DFF_ 2752
#define B_  2
#define T_  1365
#define BT_ (B_*T_)          // 2730
#define ZLOSSW 1e-4f
#define DD_ ((size_t)D_ * D_)
#define DF_ ((size_t)D_ * DFF_)

typedef __nv_bfloat16 bf16;

__device__ __constant__ int c_bound[7] = {0, 1, 5, 21, 85, 341, 1365};

// ---------------- scratch (static device globals) ----------------
__device__ float g_h[BT_ * D_];
__device__ float g_part[(size_t)BT_ * 32];   // per-row per-colblock partial sumexp
__device__ float g_tgt[BT_];                 // target logit per row
__device__ float g_ce[BT_];
__device__ float g_zl[BT_];
__device__ int   g_tok[BT_];
__device__ int   g_scl[T_];
__device__ float g_cos[T_ * DH_];
__device__ float g_sin[T_ * DH_];

// bf16 operands
__device__ bf16 g_hb[BT_ * D_];
__device__ bf16 g_vb[BT_ * D_];
__device__ bf16 g_qb[BT_ * D_];
__device__ bf16 g_kb[BT_ * D_];
__device__ bf16 g_ob[BT_ * D_];
__device__ bf16 g_tmpb[BT_ * D_];
__device__ bf16 g_ggb[(size_t)BT_ * DFF_];
// transposed bf16 weights ([N][K] k-contiguous for GEMM B operand)
__device__ bf16 g_wqt[NL_ * D_ * D_];
__device__ bf16 g_wkt[NL_ * D_ * D_];
__device__ bf16 g_wvt[NL_ * D_ * D_];
__device__ bf16 g_wot[NL_ * D_ * D_];
__device__ bf16 g_w1t[(size_t)NL_ * DFF_ * D_];
__device__ bf16 g_w3t[(size_t)NL_ * DFF_ * D_];
__device__ bf16 g_w2t[(size_t)NL_ * D_ * DFF_];
__device__ bf16 g_embb[V_ * D_];

// ---------------- helpers ----------------
__device__ __forceinline__ void scale_of(int t, int& s, int& p) {
    if (t < 1)        { s = 0; p = t; }
    else if (t < 5)   { s = 1; p = t - 1; }
    else if (t < 21)  { s = 2; p = t - 5; }
    else if (t < 85)  { s = 3; p = t - 21; }
    else if (t < 341) { s = 4; p = t - 85; }
    else              { s = 5; p = t - 341; }
}

__device__ __forceinline__ float blockReduceSum(float v) {
    __shared__ float sm[32];
    __syncthreads();
    int lane = threadIdx.x & 31, w = threadIdx.x >> 5;
    #pragma unroll
    for (int o = 16; o; o >>= 1) v += __shfl_xor_sync(0xffffffffu, v, o);
    if (lane == 0) sm[w] = v;
    __syncthreads();
    int nw = (blockDim.x + 31) >> 5;
    v = (threadIdx.x < nw) ? sm[threadIdx.x] : 0.f;
    if (w == 0) {
        #pragma unroll
        for (int o = 16; o; o >>= 1) v += __shfl_xor_sync(0xffffffffu, v, o);
        if (lane == 0) sm[0] = v;
    }
    __syncthreads();
    return sm[0];
}

__device__ __forceinline__ unsigned smem_u32(const void* p) {
    return (unsigned)__cvta_generic_to_shared(p);
}
__device__ __forceinline__ void cpa16(unsigned dst, const void* src, bool ok) {
    int sz = ok ? 16 : 0;
    asm volatile("cp.async.cg.shared.global [%0], [%1], 16, %2;\n"
                 :: "r"(dst), "l"(src), "r"(sz));
}
#define CP_COMMIT   asm volatile("cp.async.commit_group;\n")
#define CP_WAITG(N) asm volatile("cp.async.wait_group %0;\n" :: "n"(N))

__device__ __forceinline__ void ldm4(unsigned addr, unsigned* r) {
    asm volatile("ldmatrix.sync.aligned.m8n8.x4.shared.b16 {%0,%1,%2,%3}, [%4];"
        : "=r"(r[0]), "=r"(r[1]), "=r"(r[2]), "=r"(r[3]) : "r"(addr));
}
__device__ __forceinline__ void ldm4t(unsigned addr, unsigned* r) {
    asm volatile("ldmatrix.sync.aligned.m8n8.x4.trans.shared.b16 {%0,%1,%2,%3}, [%4];"
        : "=r"(r[0]), "=r"(r[1]), "=r"(r[2]), "=r"(r[3]) : "r"(addr));
}
__device__ __forceinline__ unsigned packbf2(float lo, float hi) {
    unsigned r;
    asm("cvt.rn.bf16x2.f32 %0, %1, %2;" : "=r"(r) : "f"(hi), "f"(lo));
    return r;
}
#define MMA_BF16(d, a, b) asm volatile( \
  "mma.sync.aligned.m16n8k16.row.col.f32.bf16.bf16.f32 " \
  "{%0,%1,%2,%3},{%4,%5,%6,%7},{%8,%9},{%0,%1,%2,%3};\n" \
  : "+f"(d[0]), "+f"(d[1]), "+f"(d[2]), "+f"(d[3]) \
  : "r"(a[0]), "r"(a[1]), "r"(a[2]), "r"(a[3]), "r"(b[0]), "r"(b[1]))

// ---------------- bf16 tensor-core GEMM (4-stage cp.async pipeline) ----------------
// C = alpha * A @ B^T; A [M][lda] k-contig, B [N][ldb] k-contig.
// 128 x 128 x 32 tiles, 256 threads (8 warps, 4Mx2N).
// EPI: 0 fp32 out, 1 bf16 out, 2 fused QKV (q rms+rope, k rms+rope, v bf16),
//      3 fused logits loss (partial fixed-shift sumexp + target-logit capture).
template<int BN, int EPI>
__global__ __launch_bounds__(256, 2) void gemm_bf(
    const bf16* __restrict__ A, const bf16* __restrict__ B0,
    const bf16* __restrict__ B1, const bf16* __restrict__ B2,
    float* __restrict__ Cf, bf16* __restrict__ Cb,
    bf16* __restrict__ Cq, bf16* __restrict__ Ck,
    const float* __restrict__ gq, const float* __restrict__ gk,
    int M, int N, int K, int lda, int ldb, int ldc,
    long long sC0, float alpha)
{
    constexpr int BM = 128, BK = 32;
    constexpr int NI = BN / 16;
    constexpr int RSB = 80;
    constexpr int ABYTES = BM * RSB;
    constexpr int BBYTES = BN * RSB;
    constexpr int STG = ABYTES + BBYTES;
    constexpr int NSTG = 4;

    const int z = blockIdx.z;
    const bf16* Bp;
    if (B1) Bp = (z == 0) ? B0 : ((z == 1) ? B1 : B2);
    else    Bp = B0;
    const long long coff = (long long)z * sC0;

    const int row0 = blockIdx.y * BM, col0 = blockIdx.x * BN;

    extern __shared__ char smdyn[];
    const unsigned sbase = smem_u32(smdyn);
    const int tid = threadIdx.x, lane = tid & 31, warp = tid >> 5;
    const int wm = warp >> 1, wn = warp & 1;

    auto issue = [&](int it, int buf) {
        const int k0 = it * BK;
        const unsigned as = sbase + buf * STG;
        const unsigned bs = as + ABYTES;
        #pragma unroll
        for (int i = 0; i < 2; i++) {
            int c = tid + i * 256;
            int r = c >> 2, kc = c & 3;
            int gk0 = k0 + kc * 8;
            bool ok = (row0 + r < M) && (gk0 < K);
            const bf16* src = ok ? (A + (size_t)(row0 + r) * lda + gk0) : A;
            cpa16(as + r * RSB + kc * 16, src, ok);
        }
        constexpr int BCH = BN * 4;
        #pragma unroll
        for (int i = 0; i < (BCH + 255) / 256; i++) {
            int c = tid + i * 256;
            if (c < BCH) {
                int r = c >> 2, kc = c & 3;
                int gk0 = k0 + kc * 8;
                bool ok = (col0 + r < N) && (gk0 < K);
                const bf16* src = ok ? (Bp + (size_t)(col0 + r) * ldb + gk0) : Bp;
                cpa16(bs + r * RSB + kc * 16, src, ok);
            }
        }
    };

    float acc[2][NI][4] = {};
    const int nIter = (K + BK - 1) / BK;

    issue(0, 0); CP_COMMIT;
    issue(1, 1); CP_COMMIT;
    issue(2, 2); CP_COMMIT;

    const unsigned foff = (unsigned)((lane & 15) * RSB + (lane >> 4) * 16);
    const int gr = lane >> 2, gc = lane & 3;

    for (int it = 0; it < nIter; it++) {
        CP_WAITG(2);
        __syncthreads();
        if (it + 3 < nIter) issue(it + 3, (it + 3) % NSTG);
        CP_COMMIT;
        const unsigned as = sbase + (it % NSTG) * STG;
        const unsigned bs = as + ABYTES;
        #pragma unroll
        for (int ks = 0; ks < 2; ks++) {
            unsigned ra[2][4];
            #pragma unroll
            for (int mi = 0; mi < 2; mi++)
                ldm4(as + (wm * 32 + mi * 16) * RSB + ks * 32 + foff, ra[mi]);
            unsigned rb[NI][2];
            #pragma unroll
            for (int nj = 0; nj < NI / 2; nj++) {
                unsigned t[4];
                ldm4(bs + (wn * (BN / 2) + nj * 16) * RSB + ks * 32 + foff, t);
                rb[nj * 2][0] = t[0]; rb[nj * 2 + 1][0] = t[1];
                rb[nj * 2][1] = t[2]; rb[nj * 2 + 1][1] = t[3];
            }
            #pragma unroll
            for (int mi = 0; mi < 2; mi++)
                #pragma unroll
                for (int ni = 0; ni < NI; ni++)
                    MMA_BF16(acc[mi][ni], ra[mi], rb[ni]);
        }
    }

    if constexpr (EPI == 2) {
        if (z == 2) {
            #pragma unroll
            for (int mi = 0; mi < 2; mi++)
                #pragma unroll
                for (int ni = 0; ni < NI; ni++) {
                    int c = col0 + wn * (BN / 2) + ni * 8 + gc * 2;
                    #pragma unroll
                    for (int rr = 0; rr < 2; rr++) {
                        int r = row0 + wm * 32 + mi * 16 + gr + rr * 8;
                        if (r < M) {
                            unsigned v = packbf2(acc[mi][ni][rr * 2], acc[mi][ni][rr * 2 + 1]);
                            *(unsigned*)(Cb + (size_t)r * ldc + c) = v;
                        }
                    }
                }
        } else {
            // q/k: per-head RMSNorm (64 cols = this warp's tile half) + RoPE.
            const float* gg = (z == 0) ? gq : gk;
            bf16* outp = (z == 0) ? Cq : Ck;
            float gv[8][2];
            #pragma unroll
            for (int ni = 0; ni < 8; ni++) {
                gv[ni][0] = gg[ni * 8 + gc * 2];
                gv[ni][1] = gg[ni * 8 + gc * 2 + 1];
            }
            const int cbase = col0 + wn * 64;
            #pragma unroll
            for (int mi = 0; mi < 2; mi++)
                #pragma unroll
                for (int rr = 0; rr < 2; rr++) {
                    float ss = 0.f;
                    #pragma unroll
                    for (int ni = 0; ni < 8; ni++) {
                        float a0 = acc[mi][ni][rr * 2], a1 = acc[mi][ni][rr * 2 + 1];
                        ss += a0 * a0 + a1 * a1;
                    }
                    ss += __shfl_xor_sync(0xffffffffu, ss, 1);
                    ss += __shfl_xor_sync(0xffffffffu, ss, 2);
                    float rn = rsqrtf(ss * (1.f / 64.f) + 1e-6f);
                    int r = row0 + wm * 32 + mi * 16 + gr + rr * 8;
                    if (r < M) {
                        int t = r % T_;
                        const float* cp = g_cos + t * 64;
                        const float* sp = g_sin + t * 64;
                        #pragma unroll
                        for (int ni = 0; ni < 4; ni++) {
                            int d = ni * 8 + gc * 2;
                            float x1a = acc[mi][ni][rr * 2]     * rn * gv[ni][0];
                            float x1b = acc[mi][ni][rr * 2 + 1] * rn * gv[ni][1];
                            float x2a = acc[mi][ni + 4][rr * 2]     * rn * gv[ni + 4][0];
                            float x2b = acc[mi][ni + 4][rr * 2 + 1] * rn * gv[ni + 4][1];
                            unsigned o1 = packbf2(x1a * cp[d]     - x2a * sp[d],
                                                  x1b * cp[d + 1] - x2b * sp[d + 1]);
                            unsigned o2 = packbf2(x2a * cp[d + 32] + x1a * sp[d + 32],
                                                  x2b * cp[d + 33] + x1b * sp[d + 33]);
                            size_t base = (size_t)r * D_ + cbase + d;
                            *(unsigned*)(outp + base)      = o1;
                            *(unsigned*)(outp + base + 32) = o2;
                        }
                    }
                }
        }
    } else if constexpr (EPI == 3) {
        // fused loss: per-row partial sumexp (fixed shift -32 in base-2 after *log2e)
        // plus target-logit capture. Deterministic: each smem row cell receives
        // exactly 2 commutative float adds (wn=0,1).
        __shared__ float smr[128];
        if (tid < 128) smr[tid] = 0.f;
        __syncthreads();
        const float LOG2E = 1.4426950408889634f;
        #pragma unroll
        for (int mi = 0; mi < 2; mi++)
            #pragma unroll
            for (int rr = 0; rr < 2; rr++) {
                float rs = 0.f;
                #pragma unroll
                for (int ni = 0; ni < NI; ni++) {
                    rs += exp2f(fmaf(acc[mi][ni][rr * 2],     LOG2E, -32.f));
                    rs += exp2f(fmaf(acc[mi][ni][rr * 2 + 1], LOG2E, -32.f));
                }
                rs += __shfl_xor_sync(0xffffffffu, rs, 1);
                rs += __shfl_xor_sync(0xffffffffu, rs, 2);
                int rl = wm * 32 + mi * 16 + gr + rr * 8;
                if (gc == 0) atomicAdd(&smr[rl], rs);
                // target capture
                int r = row0 + rl;
                if (r < M) {
                    int t = g_tok[r];
                    int rel = t - (col0 + wn * (BN / 2));
                    if (rel >= 0 && rel < BN / 2) {
                        int ni = rel >> 3, within = rel & 7;
                        if ((within >> 1) == gc)
                            g_tgt[r] = acc[mi][ni][rr * 2 + (within & 1)];
                    }
                }
            }
        __syncthreads();
        if (tid < 128) {
            int r = row0 + tid;
            if (r < M) g_part[(size_t)r * 32 + blockIdx.x] = smr[tid];
        }
    } else {
        #pragma unroll
        for (int mi = 0; mi < 2; mi++) {
            #pragma unroll
            for (int ni = 0; ni < NI; ni++) {
                int c = col0 + wn * (BN / 2) + ni * 8 + gc * 2;
                #pragma unroll
                for (int rr = 0; rr < 2; rr++) {
                    int r = row0 + wm * 32 + mi * 16 + gr + rr * 8;
                    if (r < M) {
                        long long base = coff + (long long)r * ldc + c;
                        float v0 = alpha * acc[mi][ni][rr * 2];
                        float v1 = alpha * acc[mi][ni][rr * 2 + 1];
                        if (EPI == 0) {
                            if (c < N)     Cf[base]     = v0;
                            if (c + 1 < N) Cf[base + 1] = v1;
                        } else {
                            if (c < N)     Cb[base]     = __float2bfloat16(v0);
                            if (c + 1 < N) Cb[base + 1] = __float2bfloat16(v1);
                        }
                    }
                }
            }
        }
    }
}

// ---------------- bf16 GEMM, 64x128 tiles, 128 threads, 3 CTAs/SM ----------------
__global__ __launch_bounds__(128, 3) void gemm64(
    const bf16* __restrict__ A, const bf16* __restrict__ B0, bf16* __restrict__ Cb,
    int M, int N, int K, int lda, int ldb, int ldc)
{
    constexpr int BM = 64, BN = 128, BK = 32, RSB = 80;
    constexpr int ABYTES = BM * RSB;
    constexpr int BBYTES = BN * RSB;
    constexpr int STG = ABYTES + BBYTES;
    constexpr int NSTG = 4;

    const int row0 = blockIdx.y * BM, col0 = blockIdx.x * BN;
    extern __shared__ char smdyn[];
    const unsigned sbase = smem_u32(smdyn);
    const int tid = threadIdx.x, lane = tid & 31, warp = tid >> 5;
    const int wm = warp >> 1, wn = warp & 1;

    auto issue = [&](int it, int buf) {
        const int k0 = it * BK;
        const unsigned as = sbase + buf * STG;
        const unsigned bs = as + ABYTES;
        #pragma unroll
        for (int i = 0; i < 2; i++) {
            int c = tid + i * 128;
            int r = c >> 2, kc = c & 3;
            int gk = k0 + kc * 8;
            bool ok = (row0 + r < M) && (gk < K);
            cpa16(as + r * RSB + kc * 16, ok ? A + (size_t)(row0 + r) * lda + gk : A, ok);
        }
        #pragma unroll
        for (int i = 0; i < 4; i++) {
            int c = tid + i * 128;
            int r = c >> 2, kc = c & 3;
            int gk = k0 + kc * 8;
            bool ok = (col0 + r < N) && (gk < K);
            cpa16(bs + r * RSB + kc * 16, ok ? B0 + (size_t)(col0 + r) * ldb + gk : B0, ok);
        }
    };

    float acc[2][8][4] = {};
    const int nIter = (K + BK - 1) / BK;
    issue(0, 0); CP_COMMIT;
    issue(1, 1); CP_COMMIT;
    issue(2, 2); CP_COMMIT;

    const unsigned foff = (unsigned)((lane & 15) * RSB + (lane >> 4) * 16);
    const int gr = lane >> 2, gc = lane & 3;

    for (int it = 0; it < nIter; it++) {
        CP_WAITG(2);
        __syncthreads();
        if (it + 3 < nIter) issue(it + 3, (it + 3) % NSTG);
        CP_COMMIT;
        const unsigned as = sbase + (it % NSTG) * STG;
        const unsigned bs = as + ABYTES;
        #pragma unroll
        for (int ks = 0; ks < 2; ks++) {
            unsigned ra[2][4];
            #pragma unroll
            for (int mi = 0; mi < 2; mi++)
                ldm4(as + (wm * 32 + mi * 16) * RSB + ks * 32 + foff, ra[mi]);
            unsigned rb[8][2];
            #pragma unroll
            for (int nj = 0; nj < 4; nj++) {
                unsigned t[4];
                ldm4(bs + (wn * 64 + nj * 16) * RSB + ks * 32 + foff, t);
                rb[nj * 2][0] = t[0]; rb[nj * 2 + 1][0] = t[1];
                rb[nj * 2][1] = t[2]; rb[nj * 2 + 1][1] = t[3];
            }
            #pragma unroll
            for (int mi = 0; mi < 2; mi++)
                #pragma unroll
                for (int ni = 0; ni < 8; ni++)
                    MMA_BF16(acc[mi][ni], ra[mi], rb[ni]);
        }
    }

    #pragma unroll
    for (int mi = 0; mi < 2; mi++)
        #pragma unroll
        for (int ni = 0; ni < 8; ni++) {
            int c = col0 + wn * 64 + ni * 8 + gc * 2;
            #pragma unroll
            for (int rr = 0; rr < 2; rr++) {
                int r = row0 + wm * 32 + mi * 16 + gr + rr * 8;
                if (r < M && c < N) {
                    unsigned v = packbf2(acc[mi][ni][rr * 2], acc[mi][ni][rr * 2 + 1]);
                    *(unsigned*)(Cb + (size_t)r * ldc + c) = v;
                }
            }
        }
}

// ---------------- fused SwiGLU FFN GEMM (4 stages) ----------------
__global__ __launch_bounds__(256, 2) void gemm_ffn(
    const bf16* __restrict__ A, const bf16* __restrict__ W1, const bf16* __restrict__ W3,
    bf16* __restrict__ C, int M, int N, int K)
{
    constexpr int BM = 128, BN = 64, BK = 32, RSB = 80;
    constexpr int ABYTES = BM * RSB, BBYTES = BN * RSB;
    constexpr int STG = ABYTES + 2 * BBYTES;
    constexpr int NSTG = 4;

    const int row0 = blockIdx.y * BM, col0 = blockIdx.x * BN;
    extern __shared__ char smdyn[];
    const unsigned sbase = smem_u32(smdyn);
    const int tid = threadIdx.x, lane = tid & 31, warp = tid >> 5;
    const int wm = warp >> 1, wn = warp & 1;

    auto issue = [&](int it, int buf) {
        const int k0 = it * BK;
        const unsigned as = sbase + buf * STG;
        const unsigned b1s = as + ABYTES, b3s = b1s + BBYTES;
        #pragma unroll
        for (int i = 0; i < 2; i++) {
            int c = tid + i * 256;
            int r = c >> 2, kc = c & 3;
            int gk = k0 + kc * 8;
            bool ok = (row0 + r < M) && (gk < K);
            cpa16(as + r * RSB + kc * 16, ok ? A + (size_t)(row0 + r) * K + gk : A, ok);
        }
        {
            int r = tid >> 2, kc = tid & 3;
            int gk = k0 + kc * 8;
            bool ok = (col0 + r < N) && (gk < K);
            cpa16(b1s + r * RSB + kc * 16, ok ? W1 + (size_t)(col0 + r) * K + gk : W1, ok);
            cpa16(b3s + r * RSB + kc * 16, ok ? W3 + (size_t)(col0 + r) * K + gk : W3, ok);
        }
    };

    float acc1[2][4][4] = {}, acc3[2][4][4] = {};
    const int nIter = (K + BK - 1) / BK;
    issue(0, 0); CP_COMMIT;
    issue(1, 1); CP_COMMIT;
    issue(2, 2); CP_COMMIT;

    const unsigned foff = (unsigned)((lane & 15) * RSB + (lane >> 4) * 16);
    const int gr = lane >> 2, gc = lane & 3;

    for (int it = 0; it < nIter; it++) {
        CP_WAITG(2);
        __syncthreads();
        if (it + 3 < nIter) issue(it + 3, (it + 3) % NSTG);
        CP_COMMIT;
        const unsigned as = sbase + (it % NSTG) * STG;
        const unsigned b1s = as + ABYTES, b3s = b1s + BBYTES;
        #pragma unroll
        for (int ks = 0; ks < 2; ks++) {
            unsigned ra[2][4];
            #pragma unroll
            for (int mi = 0; mi < 2; mi++)
                ldm4(as + (wm * 32 + mi * 16) * RSB + ks * 32 + foff, ra[mi]);
            unsigned r1[4][2], r3[4][2];
            #pragma unroll
            for (int nj = 0; nj < 2; nj++) {
                unsigned t[4];
                ldm4(b1s + (wn * 32 + nj * 16) * RSB + ks * 32 + foff, t);
                r1[nj * 2][0] = t[0]; r1[nj * 2 + 1][0] = t[1];
                r1[nj * 2][1] = t[2]; r1[nj * 2 + 1][1] = t[3];
                ldm4(b3s + (wn * 32 + nj * 16) * RSB + ks * 32 + foff, t);
                r3[nj * 2][0] = t[0]; r3[nj * 2 + 1][0] = t[1];
                r3[nj * 2][1] = t[2]; r3[nj * 2 + 1][1] = t[3];
            }
            #pragma unroll
            for (int mi = 0; mi < 2; mi++)
                #pragma unroll
                for (int ni = 0; ni < 4; ni++) {
                    MMA_BF16(acc1[mi][ni], ra[mi], r1[ni]);
                    MMA_BF16(acc3[mi][ni], ra[mi], r3[ni]);
                }
        }
    }

    #pragma unroll
    for (int mi = 0; mi < 2; mi++)
        #pragma unroll
        for (int ni = 0; ni < 4; ni++) {
            int c = col0 + wn * 32 + ni * 8 + gc * 2;
            #pragma unroll
            for (int rr = 0; rr < 2; rr++) {
                int r = row0 + wm * 32 + mi * 16 + gr + rr * 8;
                if (r < M) {
                    float x0 = acc1[mi][ni][rr * 2],     y0 = acc3[mi][ni][rr * 2];
                    float x1 = acc1[mi][ni][rr * 2 + 1], y1 = acc3[mi][ni][rr * 2 + 1];
                    float g0 = x0 / (1.f + expf(-x0)) * y0;
                    float g1 = x1 / (1.f + expf(-x1)) * y1;
                    size_t base = (size_t)r * N + c;
                    C[base]     = __float2bfloat16(g0);
                    C[base + 1] = __float2bfloat16(g1);
                }
            }
        }
}

// ---------------- fused flash attention (prefix mask, FIXED-max softmax) ----------------
#define FL_ROWB 144
__global__ __launch_bounds__(256, 2) void k_flash() {
    extern __shared__ char smdyn[];
    const unsigned uQ = smem_u32(smdyn);
    const unsigned uK = uQ + 128 * FL_ROWB;
    const unsigned uV = uK + 2 * 128 * FL_ROWB;

    const int z = blockIdx.y;
    const int b = z >> 4, h = z & 15;
    const int row0 = blockIdx.x * 128;
    const int tid = threadIdx.x, lane = tid & 31, warp = tid >> 5;

    int sl, pl; scale_of(min(row0 + 127, T_ - 1), sl, pl);
    const int Lmax = c_bound[sl + 1];
    const int nkb = (Lmax + 127) >> 7;

    const size_t hoff = ((size_t)b * T_) * D_ + h * DH_;
    const bf16* qg = g_qb + hoff;
    const bf16* kg = g_kb + hoff;
    const bf16* vg = g_vb + hoff;
    bf16* og = g_ob + hoff;

    const int lr = tid >> 1, lc0 = (tid & 1) * 4;
    {
        bool ok = (row0 + lr) < T_;
        const bf16* s = qg + (size_t)(row0 + lr) * D_ + lc0 * 8;
        #pragma unroll
        for (int j = 0; j < 4; j++) cpa16(uQ + lr * FL_ROWB + (lc0 + j) * 16, s + j * 8, ok);
    }
    auto issueKV = [&](int kb, int buf) {
        int jr = kb * 128 + lr;
        bool ok = jr < T_;
        const bf16* sk = kg + (size_t)jr * D_ + lc0 * 8;
        const bf16* sv = vg + (size_t)jr * D_ + lc0 * 8;
        unsigned off = buf * (128 * FL_ROWB) + lr * FL_ROWB + lc0 * 16;
        #pragma unroll
        for (int j = 0; j < 4; j++) {
            cpa16(uK + off + j * 16, sk + j * 8, ok);
            cpa16(uV + off + j * 16, sv + j * 8, ok);
        }
    };
    issueKV(0, 0); CP_COMMIT;
    if (nkb > 1) issueKV(1, 1);
    CP_COMMIT;
    CP_WAITG(1);
    __syncthreads();

    const unsigned foff = (unsigned)((lane & 15) * FL_ROWB + (lane >> 4) * 16);
    unsigned aq[4][4];
    #pragma unroll
    for (int ks = 0; ks < 4; ks++)
        ldm4(uQ + (warp * 16) * FL_ROWB + ks * 32 + foff, aq[ks]);

    const int gr = lane >> 2, gc = lane & 3;
    const int r0g = row0 + warp * 16 + gr;
    int Li0 = 0, Li1 = 0;
    if (r0g < T_)     { int s2, p2; scale_of(r0g, s2, p2);     Li0 = c_bound[s2 + 1]; }
    if (r0g + 8 < T_) { int s2, p2; scale_of(r0g + 8, s2, p2); Li1 = c_bound[s2 + 1]; }

    float l0 = 0.f, l1 = 0.f;
    float oacc[8][4] = {};
    const float ALPHA = 0.125f * 1.4426950408889634f;

    for (int kb = 0; kb < nkb; kb++) {
        const unsigned bK = uK + (kb & 1) * (128 * FL_ROWB);
        const unsigned bV = uV + (kb & 1) * (128 * FL_ROWB);

        float sum0 = 0.f, sum1 = 0.f;
        #pragma unroll
        for (int half = 0; half < 2; half++) {
            float s[8][4];
            #pragma unroll
            for (int i = 0; i < 8; i++) { s[i][0] = s[i][1] = s[i][2] = s[i][3] = 0.f; }
            #pragma unroll
            for (int ks = 0; ks < 4; ks++) {
                #pragma unroll
                for (int n2 = 0; n2 < 4; n2++) {
                    unsigned t[4];
                    ldm4(bK + (half * 64 + n2 * 16) * FL_ROWB + ks * 32 + foff, t);
                    unsigned b0[2] = {t[0], t[2]}, b1[2] = {t[1], t[3]};
                    MMA_BF16(s[n2 * 2],     aq[ks], b0);
                    MMA_BF16(s[n2 * 2 + 1], aq[ks], b1);
                }
            }
            const int j0 = kb * 128 + half * 64;
            #pragma unroll
            for (int ni = 0; ni < 8; ni++) {
                int jc = j0 + ni * 8 + 2 * gc;
                float p0 = (jc     < Li0) ? exp2f(fmaf(s[ni][0], ALPHA, -12.f)) : 0.f;
                float p1 = (jc + 1 < Li0) ? exp2f(fmaf(s[ni][1], ALPHA, -12.f)) : 0.f;
                float p2 = (jc     < Li1) ? exp2f(fmaf(s[ni][2], ALPHA, -12.f)) : 0.f;
                float p3 = (jc + 1 < Li1) ? exp2f(fmaf(s[ni][3], ALPHA, -12.f)) : 0.f;
                s[ni][0] = p0; s[ni][1] = p1; s[ni][2] = p2; s[ni][3] = p3;
                sum0 += p0 + p1; sum1 += p2 + p3;
            }
            #pragma unroll
            for (int j = 0; j < 4; j++) {
                unsigned pa[4];
                pa[0] = packbf2(s[2 * j][0],     s[2 * j][1]);
                pa[1] = packbf2(s[2 * j][2],     s[2 * j][3]);
                pa[2] = packbf2(s[2 * j + 1][0], s[2 * j + 1][1]);
                pa[3] = packbf2(s[2 * j + 1][2], s[2 * j + 1][3]);
                unsigned vrow = bV + (half * 64 + j * 16 + (lane & 7)
                                       + 8 * ((lane >> 3) & 1)) * FL_ROWB
                                   + (lane >> 4) * 16;
                #pragma unroll
                for (int d2 = 0; d2 < 4; d2++) {
                    unsigned t[4];
                    ldm4t(vrow + d2 * 32, t);
                    unsigned vb0[2] = {t[0], t[1]}, vb1[2] = {t[2], t[3]};
                    MMA_BF16(oacc[d2 * 2],     pa, vb0);
                    MMA_BF16(oacc[d2 * 2 + 1], pa, vb1);
                }
            }
        }
        sum0 += __shfl_xor_sync(0xffffffffu, sum0, 1);
        sum0 += __shfl_xor_sync(0xffffffffu, sum0, 2);
        sum1 += __shfl_xor_sync(0xffffffffu, sum1, 1);
        sum1 += __shfl_xor_sync(0xffffffffu, sum1, 2);
        l0 += sum0; l1 += sum1;

        __syncthreads();
        if (kb + 2 < nkb) issueKV(kb + 2, kb & 1);
        CP_COMMIT;
        CP_WAITG(1);
        __syncthreads();
    }

    float li0 = 1.f / l0, li1 = 1.f / l1;
    #pragma unroll
    for (int t8 = 0; t8 < 8; t8++) {
        int c = t8 * 8 + 2 * gc;
        if (r0g < T_) {
            og[(size_t)r0g * D_ + c]     = __float2bfloat16(oacc[t8][0] * li0);
            og[(size_t)r0g * D_ + c + 1] = __float2bfloat16(oacc[t8][1] * li0);
        }
        if (r0g + 8 < T_) {
            og[(size_t)(r0g + 8) * D_ + c]     = __float2bfloat16(oacc[t8][2] * li1);
            og[(size_t)(r0g + 8) * D_ + c + 1] = __float2bfloat16(oacc[t8][3] * li1);
        }
    }
}

// ---------------- merged weight conversion: 64x64 tiles, vectorized ----------------
__global__ __launch_bounds__(256) void k_convW(
    const float* __restrict__ wq, const float* __restrict__ wk,
    const float* __restrict__ wv, const float* __restrict__ wo,
    const float* __restrict__ w1, const float* __restrict__ w3,
    const float* __restrict__ w2) {
    __shared__ float t[64][65];
    int idx = blockIdx.x;
    const float* src; bf16* dst; int R, C, r0, c0;
    if (idx < 12288) {
        int tsel = idx / 3072, rem = idx % 3072;
        int zz = rem >> 8, tile = rem & 255;
        r0 = (tile >> 4) * 64; c0 = (tile & 15) * 64; R = 1024; C = 1024;
        const float* s4[4] = {wq, wk, wv, wo};
        bf16* d4[4] = {g_wqt, g_wkt, g_wvt, g_wot};
        src = s4[tsel] + (size_t)zz * DD_; dst = d4[tsel] + (size_t)zz * DD_;
    } else if (idx < 28800) {
        int rem = idx - 12288;
        int tsel = rem / 8256; rem %= 8256;
        int zz = rem / 688, tile = rem % 688;
        r0 = (tile / 43) * 64; c0 = (tile % 43) * 64; R = 1024; C = 2752;
        src = (tsel ? w3 : w1) + (size_t)zz * DF_;
        dst = (tsel ? g_w3t : g_w1t) + (size_t)zz * DF_;
    } else {
        int rem = idx - 28800;
        int zz = rem / 688, tile = rem % 688;
        r0 = (tile / 16) * 64; c0 = (tile % 16) * 64; R = 2752; C = 1024;
        src = w2 + (size_t)zz * DF_; dst = g_w2t + (size_t)zz * DF_;
    }
    int tx = threadIdx.x;
    int lr = tx >> 4, lc = (tx & 15) * 4;
    #pragma unroll
    for (int it = 0; it < 4; it++) {
        int r = it * 16 + lr;
        float4 v = *(const float4*)(src + (size_t)(r0 + r) * C + c0 + lc);
        t[r][lc] = v.x; t[r][lc + 1] = v.y; t[r][lc + 2] = v.z; t[r][lc + 3] = v.w;
    }
    __syncthreads();
    int sc = tx >> 5, sr = (tx & 31) * 2;
    #pragma unroll
    for (int it = 0; it < 8; it++) {
        int cc = it * 8 + sc;
        unsigned v = packbf2(t[sr][cc], t[sr + 1][cc]);
        *(unsigned*)(dst + (size_t)(c0 + cc) * R + r0 + sr) = v;
    }
}

// vectorized fp32 -> bf16 convert
__global__ void k_cvt8(const float* __restrict__ s, bf16* __restrict__ d, long long n8) {
    long long i = (long long)blockIdx.x * blockDim.x + threadIdx.x;
    if (i >= n8) return;
    const float4* s4 = (const float4*)s + i * 2;
    float4 a = s4[0], b = s4[1];
    uint4 o;
    o.x = packbf2(a.x, a.y); o.y = packbf2(a.z, a.w);
    o.z = packbf2(b.x, b.y); o.w = packbf2(b.z, b.w);
    ((uint4*)d)[i] = o;
}

// ---------------- merged setup: tokens + scale ids + rope tables ----------------
__global__ void k_setup(const int* i0, const int* i1, const int* i2,
                        const int* i3, const int* i4, const int* i5) {
    int t = blockIdx.x, d = threadIdx.x;
    int s, p; scale_of(t, s, p);
    if (d == 0) g_scl[t] = s;
    if (d < 2) {
        const int* arr[6] = {i0, i1, i2, i3, i4, i5};
        int sz = 1 << (2 * s);
        g_tok[d * T_ + t] = arr[s][d * sz + p];
    }
    int i = d & 31;
    float inv = powf(10000.f, -(float)(2 * i) / 64.f);
    float ang = (float)p * inv;
    g_cos[t * 64 + d] = cosf(ang);
    g_sin[t * 64 + d] = sinf(ang);
}

__global__ void k_embed(const float* __restrict__ E, const float* __restrict__ SE,
                        const float* __restrict__ start) {
    int row = blockIdx.x;
    int t = row % T_;
    int s = g_scl[t];
    const float* src = (t == 0) ? start : (E + (long long)g_tok[row] * D_);
    const float* se = SE + s * D_;
    float* hp = g_h + (size_t)row * D_;
    bf16* hb = g_hb + (size_t)row * D_;
    for (int d = threadIdx.x; d < D_; d += blockDim.x) {
        float x = src[d] + se[d];
        hp[d] = x;
        hb[d] = __float2bfloat16(x);
    }
}

// h = RMSNorm(h + delta) * gain, delta bf16
__global__ void k_rms(float* __restrict__ h, const bf16* __restrict__ delta,
                      const float* __restrict__ gain) {
    int row = blockIdx.x;
    float* hp = h + (size_t)row * D_;
    bf16* hb = g_hb + (size_t)row * D_;
    const bf16* dp = delta + (size_t)row * D_;
    float ss = 0.f;
    for (int d = threadIdx.x; d < D_; d += blockDim.x) {
        float x = hp[d] + __bfloat162float(dp[d]);
        ss += x * x;
    }
    ss = blockReduceSum(ss);
    float r = rsqrtf(ss / (float)D_ + 1e-6f);
    for (int d = threadIdx.x; d < D_; d += blockDim.x) {
        float x = (hp[d] + __bfloat162float(dp[d])) * r * gain[d];
        hp[d] = x;
        hb[d] = __float2bfloat16(x);
    }
}

// per-row loss from fused-logits partials
__global__ void k_loss_row() {
    int row = blockIdx.x * blockDim.x + threadIdx.x;
    if (row >= BT_) return;
    const float* pp = g_part + (size_t)row * 32;
    float s = 0.f;
    #pragma unroll
    for (int i = 0; i < 32; i++) s += pp[i];
    float lse = logf(s) + 32.f * 0.6931471805599453f;
    g_ce[row] = lse - g_tgt[row];
    g_zl[row] = lse * lse;
}

__global__ void k_loss_final(float* out) {
    float s1 = 0.f, s2 = 0.f;
    for (int j = threadIdx.x; j < BT_; j += blockDim.x) { s1 += g_ce[j]; s2 += g_zl[j]; }
    s1 = blockReduceSum(s1);
    s2 = blockReduceSum(s2);
    if (threadIdx.x == 0) out[0] = s1 / (float)BT_ + ZLOSSW * (s2 / (float)BT_);
}

// ---------------- entry point ----------------
extern "C" void kernel_launch(void* const* d_in, const int* in_sizes, int n_in,
                              void* d_out, int out_size) {
    const int* i0 = (const int*)d_in[0];
    const int* i1 = (const int*)d_in[1];
    const int* i2 = (const int*)d_in[2];
    const int* i3 = (const int*)d_in[3];
    const int* i4 = (const int*)d_in[4];
    const int* i5 = (const int*)d_in[5];
    const float* token_embed = (const float*)d_in[6];
    const float* scale_embed = (const float*)d_in[7];
    const float* start_token = (const float*)d_in[8];
    const float* wq = (const float*)d_in[9];
    const float* wk = (const float*)d_in[10];
    const float* wv = (const float*)d_in[11];
    const float* wo = (const float*)d_in[12];
    const float* qn = (const float*)d_in[13];
    const float* kn = (const float*)d_in[14];
    const float* n1 = (const float*)d_in[15];
    const float* n2 = (const float*)d_in[16];
    const float* w1 = (const float*)d_in[17];
    const float* w3 = (const float*)d_in[18];
    const float* w2 = (const float*)d_in[19];

    cudaFuncSetAttribute((const void*)gemm_bf<128, 2>,
                         cudaFuncAttributeMaxDynamicSharedMemorySize, 81920);
    cudaFuncSetAttribute((const void*)gemm_bf<128, 3>,
                         cudaFuncAttributeMaxDynamicSharedMemorySize, 81920);
    cudaFuncSetAttribute((const void*)gemm64,
                         cudaFuncAttributeMaxDynamicSharedMemorySize, 61440);
    cudaFuncSetAttribute((const void*)gemm_ffn,
                         cudaFuncAttributeMaxDynamicSharedMemorySize, 81920);
    cudaFuncSetAttribute((const void*)k_flash,
                         cudaFuncAttributeMaxDynamicSharedMemorySize, 92160);

    void* p;
    cudaGetSymbolAddress(&p, g_h);      float* h    = (float*)p;
    cudaGetSymbolAddress(&p, g_hb);     bf16* hb    = (bf16*)p;
    cudaGetSymbolAddress(&p, g_vb);     bf16* vb    = (bf16*)p;
    cudaGetSymbolAddress(&p, g_qb);     bf16* qb    = (bf16*)p;
    cudaGetSymbolAddress(&p, g_kb);     bf16* kb    = (bf16*)p;
    cudaGetSymbolAddress(&p, g_ob);     bf16* ob    = (bf16*)p;
    cudaGetSymbolAddress(&p, g_tmpb);   bf16* tmpb  = (bf16*)p;
    cudaGetSymbolAddress(&p, g_ggb);    bf16* ggb   = (bf16*)p;
    cudaGetSymbolAddress(&p, g_wqt);    bf16* wqt   = (bf16*)p;
    cudaGetSymbolAddress(&p, g_wkt);    bf16* wkt   = (bf16*)p;
    cudaGetSymbolAddress(&p, g_wvt);    bf16* wvt   = (bf16*)p;
    cudaGetSymbolAddress(&p, g_wot);    bf16* wot   = (bf16*)p;
    cudaGetSymbolAddress(&p, g_w1t);    bf16* w1t   = (bf16*)p;
    cudaGetSymbolAddress(&p, g_w3t);    bf16* w3t   = (bf16*)p;
    cudaGetSymbolAddress(&p, g_w2t);    bf16* w2t   = (bf16*)p;
    cudaGetSymbolAddress(&p, g_embb);   bf16* embb  = (bf16*)p;

    const long long DD = (long long)D_ * D_;
    const long long DF = (long long)D_ * DFF_;

    // setup (4 launches; with one harness launch ahead, QKV gemm = global #6 for ncu)
    k_setup<<<T_, 64>>>(i0, i1, i2, i3, i4, i5);
    k_convW<<<37056, 256>>>(wq, wk, wv, wo, w1, w3, w2);
    k_cvt8<<<((long long)V_ * D_ / 8 + 255) / 256, 256>>>(token_embed, embb,
                                                          (long long)V_ * D_ / 8);
    k_embed<<<BT_, 256>>>(token_embed, scale_embed, start_token);

    for (int l = 0; l < NL_; l++) {
        // fused QKV + per-head RMSNorm + RoPE epilogue (q->qb, k->kb, v->vb)
        gemm_bf<128, 2><<<dim3(8, 22, 3), 256, 81920>>>(
            hb, wqt + l * DD, wkt + l * DD, wvt + l * DD, nullptr, vb,
            qb, kb, qn + l * DH_, kn + l * DH_,
            BT_, D_, D_, D_, D_, D_, 0, 1.f);

        k_flash<<<dim3(11, B_ * H_), 256, 92160>>>();

        gemm64<<<dim3(8, 43), 128, 61440>>>(
            ob, wot + l * DD, tmpb, BT_, D_, D_, D_, D_, D_);

        k_rms<<<BT_, 256>>>(h, tmpb, n1 + l * D_);

        gemm_ffn<<<dim3(43, 22, 1), 256, 81920>>>(
            hb, w1t + l * DF, w3t + l * DF, ggb, BT_, DFF_, D_);

        gemm64<<<dim3(8, 43), 128, 61440>>>(
            ggb, w2t + l * DF, tmpb, BT_, D_, DFF_, DFF_, DFF_, D_);

        k_rms<<<BT_, 256>>>(h, tmpb, n2 + l * D_);
    }

    // logits + fused loss partials (no logits matrix materialized)
    gemm_bf<128, 3><<<dim3(32, 22, 1), 256, 81920>>>(
        hb, embb, nullptr, nullptr, nullptr, nullptr, nullptr, nullptr, nullptr, nullptr,
        BT_, V_, D_, D_, D_, V_, 0, 1.f);

    k_loss_row<<<(BT_ + 255) / 256, 256>>>();
    k_loss_final<<<1, 256>>>((float*)d_out);
}

// round 12
// speedup vs baseline: 1.0124x; 1.0115x over previous
#include <cuda_runtime.h>
#include <cuda_bf16.h>
#include <math.h>
#include <float.h>

// ---------------- problem constants ----------------
#define V_  4096
#define D_  1024
#define H_  16
#define DH_ 64
#define NL_ 12
#define DFF_ 2752
#define B_  2
#define T_  1365
#define BT_ (B_*T_)          // 2730
#define ZLOSSW 1e-4f
#define DD_ ((size_t)D_ * D_)
#define DF_ ((size_t)D_ * DFF_)

typedef __nv_bfloat16 bf16;

__device__ __constant__ int c_bound[7] = {0, 1, 5, 21, 85, 341, 1365};

// ---------------- scratch (static device globals) ----------------
__device__ float g_part[(size_t)BT_ * 32];   // per-row per-colblock partial sumexp
__device__ float g_tgt[BT_];                 // target logit per row
__device__ float g_ce[BT_];
__device__ float g_zl[BT_];
__device__ int   g_tok[BT_];
__device__ int   g_scl[T_];
__device__ float g_cos[T_ * DH_];
__device__ float g_sin[T_ * DH_];

// bf16 operands (hb is the residual trunk; no fp32 copy)
__device__ bf16 g_hb[BT_ * D_];
__device__ bf16 g_vb[BT_ * D_];
__device__ bf16 g_qb[BT_ * D_];
__device__ bf16 g_kb[BT_ * D_];
__device__ bf16 g_ob[BT_ * D_];
__device__ bf16 g_tmpb[BT_ * D_];
__device__ bf16 g_ggb[(size_t)BT_ * DFF_];
// transposed bf16 weights ([N][K] k-contiguous for GEMM B operand)
__device__ bf16 g_wqt[NL_ * D_ * D_];
__device__ bf16 g_wkt[NL_ * D_ * D_];
__device__ bf16 g_wvt[NL_ * D_ * D_];
__device__ bf16 g_wot[NL_ * D_ * D_];
__device__ bf16 g_w1t[(size_t)NL_ * DFF_ * D_];
__device__ bf16 g_w3t[(size_t)NL_ * DFF_ * D_];
__device__ bf16 g_w2t[(size_t)NL_ * D_ * DFF_];
__device__ bf16 g_embb[V_ * D_];

// ---------------- helpers ----------------
__device__ __forceinline__ void scale_of(int t, int& s, int& p) {
    if (t < 1)        { s = 0; p = t; }
    else if (t < 5)   { s = 1; p = t - 1; }
    else if (t < 21)  { s = 2; p = t - 5; }
    else if (t < 85)  { s = 3; p = t - 21; }
    else if (t < 341) { s = 4; p = t - 85; }
    else              { s = 5; p = t - 341; }
}

__device__ __forceinline__ float blockReduceSum(float v) {
    __shared__ float sm[32];
    __syncthreads();
    int lane = threadIdx.x & 31, w = threadIdx.x >> 5;
    #pragma unroll
    for (int o = 16; o; o >>= 1) v += __shfl_xor_sync(0xffffffffu, v, o);
    if (lane == 0) sm[w] = v;
    __syncthreads();
    int nw = (blockDim.x + 31) >> 5;
    v = (threadIdx.x < nw) ? sm[threadIdx.x] : 0.f;
    if (w == 0) {
        #pragma unroll
        for (int o = 16; o; o >>= 1) v += __shfl_xor_sync(0xffffffffu, v, o);
        if (lane == 0) sm[0] = v;
    }
    __syncthreads();
    return sm[0];
}

__device__ __forceinline__ unsigned smem_u32(const void* p) {
    return (unsigned)__cvta_generic_to_shared(p);
}
__device__ __forceinline__ void cpa16(unsigned dst, const void* src, bool ok) {
    int sz = ok ? 16 : 0;
    asm volatile("cp.async.cg.shared.global [%0], [%1], 16, %2;\n"
                 :: "r"(dst), "l"(src), "r"(sz));
}
#define CP_COMMIT   asm volatile("cp.async.commit_group;\n")
#define CP_WAITG(N) asm volatile("cp.async.wait_group %0;\n" :: "n"(N))

__device__ __forceinline__ void ldm4(unsigned addr, unsigned* r) {
    asm volatile("ldmatrix.sync.aligned.m8n8.x4.shared.b16 {%0,%1,%2,%3}, [%4];"
        : "=r"(r[0]), "=r"(r[1]), "=r"(r[2]), "=r"(r[3]) : "r"(addr));
}
__device__ __forceinline__ void ldm4t(unsigned addr, unsigned* r) {
    asm volatile("ldmatrix.sync.aligned.m8n8.x4.trans.shared.b16 {%0,%1,%2,%3}, [%4];"
        : "=r"(r[0]), "=r"(r[1]), "=r"(r[2]), "=r"(r[3]) : "r"(addr));
}
__device__ __forceinline__ unsigned packbf2(float lo, float hi) {
    unsigned r;
    asm("cvt.rn.bf16x2.f32 %0, %1, %2;" : "=r"(r) : "f"(hi), "f"(lo));
    return r;
}
#define MMA_BF16(d, a, b) asm volatile( \
  "mma.sync.aligned.m16n8k16.row.col.f32.bf16.bf16.f32 " \
  "{%0,%1,%2,%3},{%4,%5,%6,%7},{%8,%9},{%0,%1,%2,%3};\n" \
  : "+f"(d[0]), "+f"(d[1]), "+f"(d[2]), "+f"(d[3]) \
  : "r"(a[0]), "r"(a[1]), "r"(a[2]), "r"(a[3]), "r"(b[0]), "r"(b[1]))

// ---------------- bf16 tensor-core GEMM (4-stage cp.async pipeline) ----------------
// EPI: 2 fused QKV (q rms+rope, k rms+rope, v bf16),
//      3 fused logits loss (partial fixed-shift sumexp + target-logit capture).
template<int BN, int EPI>
__global__ __launch_bounds__(256, 2) void gemm_bf(
    const bf16* __restrict__ A, const bf16* __restrict__ B0,
    const bf16* __restrict__ B1, const bf16* __restrict__ B2,
    bf16* __restrict__ Cb, bf16* __restrict__ Cq, bf16* __restrict__ Ck,
    const float* __restrict__ gq, const float* __restrict__ gk,
    int M, int N, int K, int lda, int ldb, int ldc)
{
    constexpr int BM = 128, BK = 32;
    constexpr int NI = BN / 16;
    constexpr int RSB = 80;
    constexpr int ABYTES = BM * RSB;
    constexpr int BBYTES = BN * RSB;
    constexpr int STG = ABYTES + BBYTES;
    constexpr int NSTG = 4;

    const int z = blockIdx.z;
    const bf16* Bp;
    if (B1) Bp = (z == 0) ? B0 : ((z == 1) ? B1 : B2);
    else    Bp = B0;

    const int row0 = blockIdx.y * BM, col0 = blockIdx.x * BN;

    extern __shared__ char smdyn[];
    const unsigned sbase = smem_u32(smdyn);
    const int tid = threadIdx.x, lane = tid & 31, warp = tid >> 5;
    const int wm = warp >> 1, wn = warp & 1;

    auto issue = [&](int it, int buf) {
        const int k0 = it * BK;
        const unsigned as = sbase + buf * STG;
        const unsigned bs = as + ABYTES;
        #pragma unroll
        for (int i = 0; i < 2; i++) {
            int c = tid + i * 256;
            int r = c >> 2, kc = c & 3;
            int gk0 = k0 + kc * 8;
            bool ok = (row0 + r < M) && (gk0 < K);
            const bf16* src = ok ? (A + (size_t)(row0 + r) * lda + gk0) : A;
            cpa16(as + r * RSB + kc * 16, src, ok);
        }
        constexpr int BCH = BN * 4;
        #pragma unroll
        for (int i = 0; i < (BCH + 255) / 256; i++) {
            int c = tid + i * 256;
            if (c < BCH) {
                int r = c >> 2, kc = c & 3;
                int gk0 = k0 + kc * 8;
                bool ok = (col0 + r < N) && (gk0 < K);
                const bf16* src = ok ? (Bp + (size_t)(col0 + r) * ldb + gk0) : Bp;
                cpa16(bs + r * RSB + kc * 16, src, ok);
            }
        }
    };

    float acc[2][NI][4] = {};
    const int nIter = (K + BK - 1) / BK;

    issue(0, 0); CP_COMMIT;
    issue(1, 1); CP_COMMIT;
    issue(2, 2); CP_COMMIT;

    const unsigned foff = (unsigned)((lane & 15) * RSB + (lane >> 4) * 16);
    const int gr = lane >> 2, gc = lane & 3;

    for (int it = 0; it < nIter; it++) {
        CP_WAITG(2);
        __syncthreads();
        if (it + 3 < nIter) issue(it + 3, (it + 3) % NSTG);
        CP_COMMIT;
        const unsigned as = sbase + (it % NSTG) * STG;
        const unsigned bs = as + ABYTES;
        #pragma unroll
        for (int ks = 0; ks < 2; ks++) {
            unsigned ra[2][4];
            #pragma unroll
            for (int mi = 0; mi < 2; mi++)
                ldm4(as + (wm * 32 + mi * 16) * RSB + ks * 32 + foff, ra[mi]);
            unsigned rb[NI][2];
            #pragma unroll
            for (int nj = 0; nj < NI / 2; nj++) {
                unsigned t[4];
                ldm4(bs + (wn * (BN / 2) + nj * 16) * RSB + ks * 32 + foff, t);
                rb[nj * 2][0] = t[0]; rb[nj * 2 + 1][0] = t[1];
                rb[nj * 2][1] = t[2]; rb[nj * 2 + 1][1] = t[3];
            }
            #pragma unroll
            for (int mi = 0; mi < 2; mi++)
                #pragma unroll
                for (int ni = 0; ni < NI; ni++)
                    MMA_BF16(acc[mi][ni], ra[mi], rb[ni]);
        }
    }

    if constexpr (EPI == 2) {
        if (z == 2) {
            #pragma unroll
            for (int mi = 0; mi < 2; mi++)
                #pragma unroll
                for (int ni = 0; ni < NI; ni++) {
                    int c = col0 + wn * (BN / 2) + ni * 8 + gc * 2;
                    #pragma unroll
                    for (int rr = 0; rr < 2; rr++) {
                        int r = row0 + wm * 32 + mi * 16 + gr + rr * 8;
                        if (r < M) {
                            unsigned v = packbf2(acc[mi][ni][rr * 2], acc[mi][ni][rr * 2 + 1]);
                            *(unsigned*)(Cb + (size_t)r * ldc + c) = v;
                        }
                    }
                }
        } else {
            const float* gg = (z == 0) ? gq : gk;
            bf16* outp = (z == 0) ? Cq : Ck;
            float gv[8][2];
            #pragma unroll
            for (int ni = 0; ni < 8; ni++) {
                gv[ni][0] = gg[ni * 8 + gc * 2];
                gv[ni][1] = gg[ni * 8 + gc * 2 + 1];
            }
            const int cbase = col0 + wn * 64;
            #pragma unroll
            for (int mi = 0; mi < 2; mi++)
                #pragma unroll
                for (int rr = 0; rr < 2; rr++) {
                    float ss = 0.f;
                    #pragma unroll
                    for (int ni = 0; ni < 8; ni++) {
                        float a0 = acc[mi][ni][rr * 2], a1 = acc[mi][ni][rr * 2 + 1];
                        ss += a0 * a0 + a1 * a1;
                    }
                    ss += __shfl_xor_sync(0xffffffffu, ss, 1);
                    ss += __shfl_xor_sync(0xffffffffu, ss, 2);
                    float rn = rsqrtf(ss * (1.f / 64.f) + 1e-6f);
                    int r = row0 + wm * 32 + mi * 16 + gr + rr * 8;
                    if (r < M) {
                        int t = r % T_;
                        const float* cp = g_cos + t * 64;
                        const float* sp = g_sin + t * 64;
                        #pragma unroll
                        for (int ni = 0; ni < 4; ni++) {
                            int d = ni * 8 + gc * 2;
                            float x1a = acc[mi][ni][rr * 2]     * rn * gv[ni][0];
                            float x1b = acc[mi][ni][rr * 2 + 1] * rn * gv[ni][1];
                            float x2a = acc[mi][ni + 4][rr * 2]     * rn * gv[ni + 4][0];
                            float x2b = acc[mi][ni + 4][rr * 2 + 1] * rn * gv[ni + 4][1];
                            unsigned o1 = packbf2(x1a * cp[d]     - x2a * sp[d],
                                                  x1b * cp[d + 1] - x2b * sp[d + 1]);
                            unsigned o2 = packbf2(x2a * cp[d + 32] + x1a * sp[d + 32],
                                                  x2b * cp[d + 33] + x1b * sp[d + 33]);
                            size_t base = (size_t)r * D_ + cbase + d;
                            *(unsigned*)(outp + base)      = o1;
                            *(unsigned*)(outp + base + 32) = o2;
                        }
                    }
                }
        }
    } else if constexpr (EPI == 3) {
        __shared__ float smr[128];
        if (tid < 128) smr[tid] = 0.f;
        __syncthreads();
        const float LOG2E = 1.4426950408889634f;
        #pragma unroll
        for (int mi = 0; mi < 2; mi++)
            #pragma unroll
            for (int rr = 0; rr < 2; rr++) {
                float rs = 0.f;
                #pragma unroll
                for (int ni = 0; ni < NI; ni++) {
                    rs += exp2f(fmaf(acc[mi][ni][rr * 2],     LOG2E, -32.f));
                    rs += exp2f(fmaf(acc[mi][ni][rr * 2 + 1], LOG2E, -32.f));
                }
                rs += __shfl_xor_sync(0xffffffffu, rs, 1);
                rs += __shfl_xor_sync(0xffffffffu, rs, 2);
                int rl = wm * 32 + mi * 16 + gr + rr * 8;
                if (gc == 0) atomicAdd(&smr[rl], rs);
                int r = row0 + rl;
                if (r < M) {
                    int t = g_tok[r];
                    int rel = t - (col0 + wn * (BN / 2));
                    if (rel >= 0 && rel < BN / 2) {
                        int ni = rel >> 3, within = rel & 7;
                        if ((within >> 1) == gc)
                            g_tgt[r] = acc[mi][ni][rr * 2 + (within & 1)];
                    }
                }
            }
        __syncthreads();
        if (tid < 128) {
            int r = row0 + tid;
            if (r < M) g_part[(size_t)r * 32 + blockIdx.x] = smr[tid];
        }
    }
}

// ---------------- bf16 GEMM, 64x128 tiles, 128 threads, 3 CTAs/SM ----------------
__global__ __launch_bounds__(128, 3) void gemm64(
    const bf16* __restrict__ A, const bf16* __restrict__ B0, bf16* __restrict__ Cb,
    int M, int N, int K, int lda, int ldb, int ldc)
{
    constexpr int BM = 64, BN = 128, BK = 32, RSB = 80;
    constexpr int ABYTES = BM * RSB;
    constexpr int BBYTES = BN * RSB;
    constexpr int STG = ABYTES + BBYTES;
    constexpr int NSTG = 4;

    const int row0 = blockIdx.y * BM, col0 = blockIdx.x * BN;
    extern __shared__ char smdyn[];
    const unsigned sbase = smem_u32(smdyn);
    const int tid = threadIdx.x, lane = tid & 31, warp = tid >> 5;
    const int wm = warp >> 1, wn = warp & 1;

    auto issue = [&](int it, int buf) {
        const int k0 = it * BK;
        const unsigned as = sbase + buf * STG;
        const unsigned bs = as + ABYTES;
        #pragma unroll
        for (int i = 0; i < 2; i++) {
            int c = tid + i * 128;
            int r = c >> 2, kc = c & 3;
            int gk = k0 + kc * 8;
            bool ok = (row0 + r < M) && (gk < K);
            cpa16(as + r * RSB + kc * 16, ok ? A + (size_t)(row0 + r) * lda + gk : A, ok);
        }
        #pragma unroll
        for (int i = 0; i < 4; i++) {
            int c = tid + i * 128;
            int r = c >> 2, kc = c & 3;
            int gk = k0 + kc * 8;
            bool ok = (col0 + r < N) && (gk < K);
            cpa16(bs + r * RSB + kc * 16, ok ? B0 + (size_t)(col0 + r) * ldb + gk : B0, ok);
        }
    };

    float acc[2][8][4] = {};
    const int nIter = (K + BK - 1) / BK;
    issue(0, 0); CP_COMMIT;
    issue(1, 1); CP_COMMIT;
    issue(2, 2); CP_COMMIT;

    const unsigned foff = (unsigned)((lane & 15) * RSB + (lane >> 4) * 16);
    const int gr = lane >> 2, gc = lane & 3;

    for (int it = 0; it < nIter; it++) {
        CP_WAITG(2);
        __syncthreads();
        if (it + 3 < nIter) issue(it + 3, (it + 3) % NSTG);
        CP_COMMIT;
        const unsigned as = sbase + (it % NSTG) * STG;
        const unsigned bs = as + ABYTES;
        #pragma unroll
        for (int ks = 0; ks < 2; ks++) {
            unsigned ra[2][4];
            #pragma unroll
            for (int mi = 0; mi < 2; mi++)
                ldm4(as + (wm * 32 + mi * 16) * RSB + ks * 32 + foff, ra[mi]);
            unsigned rb[8][2];
            #pragma unroll
            for (int nj = 0; nj < 4; nj++) {
                unsigned t[4];
                ldm4(bs + (wn * 64 + nj * 16) * RSB + ks * 32 + foff, t);
                rb[nj * 2][0] = t[0]; rb[nj * 2 + 1][0] = t[1];
                rb[nj * 2][1] = t[2]; rb[nj * 2 + 1][1] = t[3];
            }
            #pragma unroll
            for (int mi = 0; mi < 2; mi++)
                #pragma unroll
                for (int ni = 0; ni < 8; ni++)
                    MMA_BF16(acc[mi][ni], ra[mi], rb[ni]);
        }
    }

    #pragma unroll
    for (int mi = 0; mi < 2; mi++)
        #pragma unroll
        for (int ni = 0; ni < 8; ni++) {
            int c = col0 + wn * 64 + ni * 8 + gc * 2;
            #pragma unroll
            for (int rr = 0; rr < 2; rr++) {
                int r = row0 + wm * 32 + mi * 16 + gr + rr * 8;
                if (r < M && c < N) {
                    unsigned v = packbf2(acc[mi][ni][rr * 2], acc[mi][ni][rr * 2 + 1]);
                    *(unsigned*)(Cb + (size_t)r * ldc + c) = v;
                }
            }
        }
}

// ---------------- fused SwiGLU FFN GEMM (4 stages) ----------------
__global__ __launch_bounds__(256, 2) void gemm_ffn(
    const bf16* __restrict__ A, const bf16* __restrict__ W1, const bf16* __restrict__ W3,
    bf16* __restrict__ C, int M, int N, int K)
{
    constexpr int BM = 128, BN = 64, BK = 32, RSB = 80;
    constexpr int ABYTES = BM * RSB, BBYTES = BN * RSB;
    constexpr int STG = ABYTES + 2 * BBYTES;
    constexpr int NSTG = 4;

    const int row0 = blockIdx.y * BM, col0 = blockIdx.x * BN;
    extern __shared__ char smdyn[];
    const unsigned sbase = smem_u32(smdyn);
    const int tid = threadIdx.x, lane = tid & 31, warp = tid >> 5;
    const int wm = warp >> 1, wn = warp & 1;

    auto issue = [&](int it, int buf) {
        const int k0 = it * BK;
        const unsigned as = sbase + buf * STG;
        const unsigned b1s = as + ABYTES, b3s = b1s + BBYTES;
        #pragma unroll
        for (int i = 0; i < 2; i++) {
            int c = tid + i * 256;
            int r = c >> 2, kc = c & 3;
            int gk = k0 + kc * 8;
            bool ok = (row0 + r < M) && (gk < K);
            cpa16(as + r * RSB + kc * 16, ok ? A + (size_t)(row0 + r) * K + gk : A, ok);
        }
        {
            int r = tid >> 2, kc = tid & 3;
            int gk = k0 + kc * 8;
            bool ok = (col0 + r < N) && (gk < K);
            cpa16(b1s + r * RSB + kc * 16, ok ? W1 + (size_t)(col0 + r) * K + gk : W1, ok);
            cpa16(b3s + r * RSB + kc * 16, ok ? W3 + (size_t)(col0 + r) * K + gk : W3, ok);
        }
    };

    float acc1[2][4][4] = {}, acc3[2][4][4] = {};
    const int nIter = (K + BK - 1) / BK;
    issue(0, 0); CP_COMMIT;
    issue(1, 1); CP_COMMIT;
    issue(2, 2); CP_COMMIT;

    const unsigned foff = (unsigned)((lane & 15) * RSB + (lane >> 4) * 16);
    const int gr = lane >> 2, gc = lane & 3;

    for (int it = 0; it < nIter; it++) {
        CP_WAITG(2);
        __syncthreads();
        if (it + 3 < nIter) issue(it + 3, (it + 3) % NSTG);
        CP_COMMIT;
        const unsigned as = sbase + (it % NSTG) * STG;
        const unsigned b1s = as + ABYTES, b3s = b1s + BBYTES;
        #pragma unroll
        for (int ks = 0; ks < 2; ks++) {
            unsigned ra[2][4];
            #pragma unroll
            for (int mi = 0; mi < 2; mi++)
                ldm4(as + (wm * 32 + mi * 16) * RSB + ks * 32 + foff, ra[mi]);
            unsigned r1[4][2], r3[4][2];
            #pragma unroll
            for (int nj = 0; nj < 2; nj++) {
                unsigned t[4];
                ldm4(b1s + (wn * 32 + nj * 16) * RSB + ks * 32 + foff, t);
                r1[nj * 2][0] = t[0]; r1[nj * 2 + 1][0] = t[1];
                r1[nj * 2][1] = t[2]; r1[nj * 2 + 1][1] = t[3];
                ldm4(b3s + (wn * 32 + nj * 16) * RSB + ks * 32 + foff, t);
                r3[nj * 2][0] = t[0]; r3[nj * 2 + 1][0] = t[1];
                r3[nj * 2][1] = t[2]; r3[nj * 2 + 1][1] = t[3];
            }
            #pragma unroll
            for (int mi = 0; mi < 2; mi++)
                #pragma unroll
                for (int ni = 0; ni < 4; ni++) {
                    MMA_BF16(acc1[mi][ni], ra[mi], r1[ni]);
                    MMA_BF16(acc3[mi][ni], ra[mi], r3[ni]);
                }
        }
    }

    #pragma unroll
    for (int mi = 0; mi < 2; mi++)
        #pragma unroll
        for (int ni = 0; ni < 4; ni++) {
            int c = col0 + wn * 32 + ni * 8 + gc * 2;
            #pragma unroll
            for (int rr = 0; rr < 2; rr++) {
                int r = row0 + wm * 32 + mi * 16 + gr + rr * 8;
                if (r < M) {
                    float x0 = acc1[mi][ni][rr * 2],     y0 = acc3[mi][ni][rr * 2];
                    float x1 = acc1[mi][ni][rr * 2 + 1], y1 = acc3[mi][ni][rr * 2 + 1];
                    float g0 = x0 / (1.f + expf(-x0)) * y0;
                    float g1 = x1 / (1.f + expf(-x1)) * y1;
                    size_t base = (size_t)r * N + c;
                    C[base]     = __float2bfloat16(g0);
                    C[base + 1] = __float2bfloat16(g1);
                }
            }
        }
}

// ---------------- fused flash attention (prefix mask, FIXED-max softmax) ----------------
#define FL_ROWB 144
__global__ __launch_bounds__(256, 2) void k_flash() {
    extern __shared__ char smdyn[];
    const unsigned uQ = smem_u32(smdyn);
    const unsigned uK = uQ + 128 * FL_ROWB;
    const unsigned uV = uK + 2 * 128 * FL_ROWB;

    const int z = blockIdx.y;
    const int b = z >> 4, h = z & 15;
    const int row0 = blockIdx.x * 128;
    const int tid = threadIdx.x, lane = tid & 31, warp = tid >> 5;

    int sl, pl; scale_of(min(row0 + 127, T_ - 1), sl, pl);
    const int Lmax = c_bound[sl + 1];
    const int nkb = (Lmax + 127) >> 7;

    const size_t hoff = ((size_t)b * T_) * D_ + h * DH_;
    const bf16* qg = g_qb + hoff;
    const bf16* kg = g_kb + hoff;
    const bf16* vg = g_vb + hoff;
    bf16* og = g_ob + hoff;

    const int lr = tid >> 1, lc0 = (tid & 1) * 4;
    {
        bool ok = (row0 + lr) < T_;
        const bf16* s = qg + (size_t)(row0 + lr) * D_ + lc0 * 8;
        #pragma unroll
        for (int j = 0; j < 4; j++) cpa16(uQ + lr * FL_ROWB + (lc0 + j) * 16, s + j * 8, ok);
    }
    auto issueKV = [&](int kb, int buf) {
        int jr = kb * 128 + lr;
        bool ok = jr < T_;
        const bf16* sk = kg + (size_t)jr * D_ + lc0 * 8;
        const bf16* sv = vg + (size_t)jr * D_ + lc0 * 8;
        unsigned off = buf * (128 * FL_ROWB) + lr * FL_ROWB + lc0 * 16;
        #pragma unroll
        for (int j = 0; j < 4; j++) {
            cpa16(uK + off + j * 16, sk + j * 8, ok);
            cpa16(uV + off + j * 16, sv + j * 8, ok);
        }
    };
    issueKV(0, 0); CP_COMMIT;
    if (nkb > 1) issueKV(1, 1);
    CP_COMMIT;
    CP_WAITG(1);
    __syncthreads();

    const unsigned foff = (unsigned)((lane & 15) * FL_ROWB + (lane >> 4) * 16);
    unsigned aq[4][4];
    #pragma unroll
    for (int ks = 0; ks < 4; ks++)
        ldm4(uQ + (warp * 16) * FL_ROWB + ks * 32 + foff, aq[ks]);

    const int gr = lane >> 2, gc = lane & 3;
    const int r0g = row0 + warp * 16 + gr;
    int Li0 = 0, Li1 = 0;
    if (r0g < T_)     { int s2, p2; scale_of(r0g, s2, p2);     Li0 = c_bound[s2 + 1]; }
    if (r0g + 8 < T_) { int s2, p2; scale_of(r0g + 8, s2, p2); Li1 = c_bound[s2 + 1]; }

    float l0 = 0.f, l1 = 0.f;
    float oacc[8][4] = {};
    const float ALPHA = 0.125f * 1.4426950408889634f;

    for (int kb = 0; kb < nkb; kb++) {
        const unsigned bK = uK + (kb & 1) * (128 * FL_ROWB);
        const unsigned bV = uV + (kb & 1) * (128 * FL_ROWB);

        float sum0 = 0.f, sum1 = 0.f;
        #pragma unroll
        for (int half = 0; half < 2; half++) {
            float s[8][4];
            #pragma unroll
            for (int i = 0; i < 8; i++) { s[i][0] = s[i][1] = s[i][2] = s[i][3] = 0.f; }
            #pragma unroll
            for (int ks = 0; ks < 4; ks++) {
                #pragma unroll
                for (int n2 = 0; n2 < 4; n2++) {
                    unsigned t[4];
                    ldm4(bK + (half * 64 + n2 * 16) * FL_ROWB + ks * 32 + foff, t);
                    unsigned b0[2] = {t[0], t[2]}, b1[2] = {t[1], t[3]};
                    MMA_BF16(s[n2 * 2],     aq[ks], b0);
                    MMA_BF16(s[n2 * 2 + 1], aq[ks], b1);
                }
            }
            const int j0 = kb * 128 + half * 64;
            #pragma unroll
            for (int ni = 0; ni < 8; ni++) {
                int jc = j0 + ni * 8 + 2 * gc;
                float p0 = (jc     < Li0) ? exp2f(fmaf(s[ni][0], ALPHA, -12.f)) : 0.f;
                float p1 = (jc + 1 < Li0) ? exp2f(fmaf(s[ni][1], ALPHA, -12.f)) : 0.f;
                float p2 = (jc     < Li1) ? exp2f(fmaf(s[ni][2], ALPHA, -12.f)) : 0.f;
                float p3 = (jc + 1 < Li1) ? exp2f(fmaf(s[ni][3], ALPHA, -12.f)) : 0.f;
                s[ni][0] = p0; s[ni][1] = p1; s[ni][2] = p2; s[ni][3] = p3;
                sum0 += p0 + p1; sum1 += p2 + p3;
            }
            #pragma unroll
            for (int j = 0; j < 4; j++) {
                unsigned pa[4];
                pa[0] = packbf2(s[2 * j][0],     s[2 * j][1]);
                pa[1] = packbf2(s[2 * j][2],     s[2 * j][3]);
                pa[2] = packbf2(s[2 * j + 1][0], s[2 * j + 1][1]);
                pa[3] = packbf2(s[2 * j + 1][2], s[2 * j + 1][3]);
                unsigned vrow = bV + (half * 64 + j * 16 + (lane & 7)
                                       + 8 * ((lane >> 3) & 1)) * FL_ROWB
                                   + (lane >> 4) * 16;
                #pragma unroll
                for (int d2 = 0; d2 < 4; d2++) {
                    unsigned t[4];
                    ldm4t(vrow + d2 * 32, t);
                    unsigned vb0[2] = {t[0], t[1]}, vb1[2] = {t[2], t[3]};
                    MMA_BF16(oacc[d2 * 2],     pa, vb0);
                    MMA_BF16(oacc[d2 * 2 + 1], pa, vb1);
                }
            }
        }
        sum0 += __shfl_xor_sync(0xffffffffu, sum0, 1);
        sum0 += __shfl_xor_sync(0xffffffffu, sum0, 2);
        sum1 += __shfl_xor_sync(0xffffffffu, sum1, 1);
        sum1 += __shfl_xor_sync(0xffffffffu, sum1, 2);
        l0 += sum0; l1 += sum1;

        __syncthreads();
        if (kb + 2 < nkb) issueKV(kb + 2, kb & 1);
        CP_COMMIT;
        CP_WAITG(1);
        __syncthreads();
    }

    float li0 = 1.f / l0, li1 = 1.f / l1;
    #pragma unroll
    for (int t8 = 0; t8 < 8; t8++) {
        int c = t8 * 8 + 2 * gc;
        if (r0g < T_) {
            og[(size_t)r0g * D_ + c]     = __float2bfloat16(oacc[t8][0] * li0);
            og[(size_t)r0g * D_ + c + 1] = __float2bfloat16(oacc[t8][1] * li0);
        }
        if (r0g + 8 < T_) {
            og[(size_t)(r0g + 8) * D_ + c]     = __float2bfloat16(oacc[t8][2] * li1);
            og[(size_t)(r0g + 8) * D_ + c + 1] = __float2bfloat16(oacc[t8][3] * li1);
        }
    }
}

// ---------------- merged weight + embedding conversion ----------------
// blocks: [0,12288) wq/wk/wv/wo; [12288,28800) w1/w3; [28800,37056) w2;
// [37056,39104) token_embed plain convert (2048 blocks x 2048 elems).
__global__ __launch_bounds__(256) void k_convW(
    const float* __restrict__ wq, const float* __restrict__ wk,
    const float* __restrict__ wv, const float* __restrict__ wo,
    const float* __restrict__ w1, const float* __restrict__ w3,
    const float* __restrict__ w2, const float* __restrict__ te) {
    __shared__ float t[64][65];
    int idx = blockIdx.x;
    int tx = threadIdx.x;
    if (idx >= 37056) {
        long long i = (long long)(idx - 37056) * 256 + tx;
        const float4* s4 = (const float4*)te + i * 2;
        float4 a = s4[0], b = s4[1];
        uint4 o;
        o.x = packbf2(a.x, a.y); o.y = packbf2(a.z, a.w);
        o.z = packbf2(b.x, b.y); o.w = packbf2(b.z, b.w);
        ((uint4*)g_embb)[i] = o;
        return;
    }
    const float* src; bf16* dst; int R, C, r0, c0;
    if (idx < 12288) {
        int tsel = idx / 3072, rem = idx % 3072;
        int zz = rem >> 8, tile = rem & 255;
        r0 = (tile >> 4) * 64; c0 = (tile & 15) * 64; R = 1024; C = 1024;
        const float* s4[4] = {wq, wk, wv, wo};
        bf16* d4[4] = {g_wqt, g_wkt, g_wvt, g_wot};
        src = s4[tsel] + (size_t)zz * DD_; dst = d4[tsel] + (size_t)zz * DD_;
    } else if (idx < 28800) {
        int rem = idx - 12288;
        int tsel = rem / 8256; rem %= 8256;
        int zz = rem / 688, tile = rem % 688;
        r0 = (tile / 43) * 64; c0 = (tile % 43) * 64; R = 1024; C = 2752;
        src = (tsel ? w3 : w1) + (size_t)zz * DF_;
        dst = (tsel ? g_w3t : g_w1t) + (size_t)zz * DF_;
    } else {
        int rem = idx - 28800;
        int zz = rem / 688, tile = rem % 688;
        r0 = (tile / 16) * 64; c0 = (tile % 16) * 64; R = 2752; C = 1024;
        src = w2 + (size_t)zz * DF_; dst = g_w2t + (size_t)zz * DF_;
    }
    int lr = tx >> 4, lc = (tx & 15) * 4;
    #pragma unroll
    for (int it = 0; it < 4; it++) {
        int r = it * 16 + lr;
        float4 v = *(const float4*)(src + (size_t)(r0 + r) * C + c0 + lc);
        t[r][lc] = v.x; t[r][lc + 1] = v.y; t[r][lc + 2] = v.z; t[r][lc + 3] = v.w;
    }
    __syncthreads();
    int sc = tx >> 5, sr = (tx & 31) * 2;
    #pragma unroll
    for (int it = 0; it < 8; it++) {
        int cc = it * 8 + sc;
        unsigned v = packbf2(t[sr][cc], t[sr + 1][cc]);
        *(unsigned*)(dst + (size_t)(c0 + cc) * R + r0 + sr) = v;
    }
}

// ---------------- merged setup: tokens + scale ids + rope tables ----------------
__global__ void k_setup(const int* i0, const int* i1, const int* i2,
                        const int* i3, const int* i4, const int* i5) {
    int t = blockIdx.x, d = threadIdx.x;
    int s, p; scale_of(t, s, p);
    if (d == 0) g_scl[t] = s;
    if (d < 2) {
        const int* arr[6] = {i0, i1, i2, i3, i4, i5};
        int sz = 1 << (2 * s);
        g_tok[d * T_ + t] = arr[s][d * sz + p];
    }
    int i = d & 31;
    float inv = powf(10000.f, -(float)(2 * i) / 64.f);
    float ang = (float)p * inv;
    g_cos[t * 64 + d] = cosf(ang);
    g_sin[t * 64 + d] = sinf(ang);
}

__global__ void k_embed(const float* __restrict__ E, const float* __restrict__ SE,
                        const float* __restrict__ start) {
    int row = blockIdx.x;
    int t = row % T_;
    int s = g_scl[t];
    const float* src = (t == 0) ? start : (E + (long long)g_tok[row] * D_);
    const float* se = SE + s * D_;
    bf16* hb = g_hb + (size_t)row * D_;
    for (int d = threadIdx.x; d < D_; d += blockDim.x)
        hb[d] = __float2bfloat16(src[d] + se[d]);
}

// hb = RMSNorm(hb + delta) * gain, all bf16 trunk, fp32 math
__global__ void k_rms(const bf16* __restrict__ delta, const float* __restrict__ gain) {
    int row = blockIdx.x;
    bf16* hb = g_hb + (size_t)row * D_;
    const bf16* dp = delta + (size_t)row * D_;
    int tid = threadIdx.x;
    float x[4];
    float ss = 0.f;
    #pragma unroll
    for (int i = 0; i < 4; i++) {
        int d = tid + i * 256;
        x[i] = __bfloat162float(hb[d]) + __bfloat162float(dp[d]);
        ss += x[i] * x[i];
    }
    ss = blockReduceSum(ss);
    float r = rsqrtf(ss / (float)D_ + 1e-6f);
    #pragma unroll
    for (int i = 0; i < 4; i++) {
        int d = tid + i * 256;
        hb[d] = __float2bfloat16(x[i] * r * gain[d]);
    }
}

// per-row loss from fused-logits partials
__global__ void k_loss_row() {
    int row = blockIdx.x * blockDim.x + threadIdx.x;
    if (row >= BT_) return;
    const float* pp = g_part + (size_t)row * 32;
    float s = 0.f;
    #pragma unroll
    for (int i = 0; i < 32; i++) s += pp[i];
    float lse = logf(s) + 32.f * 0.6931471805599453f;
    g_ce[row] = lse - g_tgt[row];
    g_zl[row] = lse * lse;
}

__global__ void k_loss_final(float* out) {
    float s1 = 0.f, s2 = 0.f;
    for (int j = threadIdx.x; j < BT_; j += blockDim.x) { s1 += g_ce[j]; s2 += g_zl[j]; }
    s1 = blockReduceSum(s1);
    s2 = blockReduceSum(s2);
    if (threadIdx.x == 0) out[0] = s1 / (float)BT_ + ZLOSSW * (s2 / (float)BT_);
}

// ---------------- entry point ----------------
extern "C" void kernel_launch(void* const* d_in, const int* in_sizes, int n_in,
                              void* d_out, int out_size) {
    const int* i0 = (const int*)d_in[0];
    const int* i1 = (const int*)d_in[1];
    const int* i2 = (const int*)d_in[2];
    const int* i3 = (const int*)d_in[3];
    const int* i4 = (const int*)d_in[4];
    const int* i5 = (const int*)d_in[5];
    const float* token_embed = (const float*)d_in[6];
    const float* scale_embed = (const float*)d_in[7];
    const float* start_token = (const float*)d_in[8];
    const float* wq = (const float*)d_in[9];
    const float* wk = (const float*)d_in[10];
    const float* wv = (const float*)d_in[11];
    const float* wo = (const float*)d_in[12];
    const float* qn = (const float*)d_in[13];
    const float* kn = (const float*)d_in[14];
    const float* n1 = (const float*)d_in[15];
    const float* n2 = (const float*)d_in[16];
    const float* w1 = (const float*)d_in[17];
    const float* w3 = (const float*)d_in[18];
    const float* w2 = (const float*)d_in[19];

    cudaFuncSetAttribute((const void*)gemm_bf<128, 2>,
                         cudaFuncAttributeMaxDynamicSharedMemorySize, 81920);
    cudaFuncSetAttribute((const void*)gemm_bf<128, 3>,
                         cudaFuncAttributeMaxDynamicSharedMemorySize, 81920);
    cudaFuncSetAttribute((const void*)gemm64,
                         cudaFuncAttributeMaxDynamicSharedMemorySize, 61440);
    cudaFuncSetAttribute((const void*)gemm_ffn,
                         cudaFuncAttributeMaxDynamicSharedMemorySize, 81920);
    cudaFuncSetAttribute((const void*)k_flash,
                         cudaFuncAttributeMaxDynamicSharedMemorySize, 92160);

    void* p;
    cudaGetSymbolAddress(&p, g_hb);     bf16* hb    = (bf16*)p;
    cudaGetSymbolAddress(&p, g_vb);     bf16* vb    = (bf16*)p;
    cudaGetSymbolAddress(&p, g_qb);     bf16* qb    = (bf16*)p;
    cudaGetSymbolAddress(&p, g_kb);     bf16* kb    = (bf16*)p;
    cudaGetSymbolAddress(&p, g_ob);     bf16* ob    = (bf16*)p;
    cudaGetSymbolAddress(&p, g_tmpb);   bf16* tmpb  = (bf16*)p;
    cudaGetSymbolAddress(&p, g_ggb);    bf16* ggb   = (bf16*)p;
    cudaGetSymbolAddress(&p, g_wqt);    bf16* wqt   = (bf16*)p;
    cudaGetSymbolAddress(&p, g_wkt);    bf16* wkt   = (bf16*)p;
    cudaGetSymbolAddress(&p, g_wvt);    bf16* wvt   = (bf16*)p;
    cudaGetSymbolAddress(&p, g_wot);    bf16* wot   = (bf16*)p;
    cudaGetSymbolAddress(&p, g_w1t);    bf16* w1t   = (bf16*)p;
    cudaGetSymbolAddress(&p, g_w3t);    bf16* w3t   = (bf16*)p;
    cudaGetSymbolAddress(&p, g_w2t);    bf16* w2t   = (bf16*)p;
    cudaGetSymbolAddress(&p, g_embb);   bf16* embb  = (bf16*)p;

    const long long DD = (long long)D_ * D_;
    const long long DF = (long long)D_ * DFF_;

    // 3 setup launches (harness has 2 ahead; QKV gemm = global #6 for ncu -s 5 -c 1)
    k_setup<<<T_, 64>>>(i0, i1, i2, i3, i4, i5);
    k_convW<<<39104, 256>>>(wq, wk, wv, wo, w1, w3, w2, token_embed);
    k_embed<<<BT_, 256>>>(token_embed, scale_embed, start_token);

    for (int l = 0; l < NL_; l++) {
        // fused QKV + per-head RMSNorm + RoPE epilogue (q->qb, k->kb, v->vb)
        gemm_bf<128, 2><<<dim3(8, 22, 3), 256, 81920>>>(
            hb, wqt + l * DD, wkt + l * DD, wvt + l * DD, vb,
            qb, kb, qn + l * DH_, kn + l * DH_,
            BT_, D_, D_, D_, D_, D_);

        k_flash<<<dim3(11, B_ * H_), 256, 92160>>>();

        gemm64<<<dim3(8, 43), 128, 61440>>>(
            ob, wot + l * DD, tmpb, BT_, D_, D_, D_, D_, D_);

        k_rms<<<BT_, 256>>>(tmpb, n1 + l * D_);

        gemm_ffn<<<dim3(43, 22, 1), 256, 81920>>>(
            hb, w1t + l * DF, w3t + l * DF, ggb, BT_, DFF_, D_);

        gemm64<<<dim3(8, 43), 128, 61440>>>(
            ggb, w2t + l * DF, tmpb, BT_, D_, DFF_, DFF_, DFF_, D_);

        k_rms<<<BT_, 256>>>(tmpb, n2 + l * D_);
    }

    // logits + fused loss partials (no logits matrix materialized)
    gemm_bf<128, 3><<<dim3(32, 22, 1), 256, 81920>>>(
        hb, embb, nullptr, nullptr, nullptr, nullptr, nullptr, nullptr, nullptr,
        BT_, V_, D_, D_, D_, V_);

    k_loss_row<<<(BT_ + 255) / 256, 256>>>();
    k_loss_final<<<1, 256>>>((float*)d_out);
}

// round 13
// speedup vs baseline: 1.0688x; 1.0556x over previous
#include <cuda_runtime.h>
#include <cuda_bf16.h>
#include <math.h>
#include <float.h>

// ---------------- problem constants ----------------
#define V_  4096
#define D_  1024
#define H_  16
#define DH_ 64
#define NL_ 12
#define DFF_ 2752
#define B_  2
#define T_  1365
#define BT_ (B_*T_)          // 2730
#define ZLOSSW 1e-4f
#define DD_ ((size_t)D_ * D_)
#define DF_ ((size_t)D_ * DFF_)

typedef __nv_bfloat16 bf16;

__device__ __constant__ int c_bound[7] = {0, 1, 5, 21, 85, 341, 1365};

// ---------------- scratch (static device globals) ----------------
__device__ float g_part[(size_t)BT_ * 32];
__device__ float g_tgt[BT_];
__device__ float g_ce[BT_];
__device__ float g_zl[BT_];
__device__ int   g_tok[BT_];
__device__ int   g_scl[T_];
__device__ float g_cos[T_ * DH_];
__device__ float g_sin[T_ * DH_];

__device__ bf16 g_hb[BT_ * D_];
__device__ bf16 g_vb[BT_ * D_];
__device__ bf16 g_qb[BT_ * D_];
__device__ bf16 g_kb[BT_ * D_];
__device__ bf16 g_ob[BT_ * D_];
__device__ bf16 g_tmpb[BT_ * D_];
__device__ bf16 g_ggb[(size_t)BT_ * DFF_];
__device__ bf16 g_wqt[NL_ * D_ * D_];
__device__ bf16 g_wkt[NL_ * D_ * D_];
__device__ bf16 g_wvt[NL_ * D_ * D_];
__device__ bf16 g_wot[NL_ * D_ * D_];
__device__ bf16 g_w1t[(size_t)NL_ * DFF_ * D_];
__device__ bf16 g_w3t[(size_t)NL_ * DFF_ * D_];
__device__ bf16 g_w2t[(size_t)NL_ * D_ * DFF_];
__device__ bf16 g_embb[V_ * D_];

// ---------------- helpers ----------------
__device__ __forceinline__ void scale_of(int t, int& s, int& p) {
    if (t < 1)        { s = 0; p = t; }
    else if (t < 5)   { s = 1; p = t - 1; }
    else if (t < 21)  { s = 2; p = t - 5; }
    else if (t < 85)  { s = 3; p = t - 21; }
    else if (t < 341) { s = 4; p = t - 85; }
    else              { s = 5; p = t - 341; }
}

__device__ __forceinline__ float blockReduceSum(float v) {
    __shared__ float sm[32];
    __syncthreads();
    int lane = threadIdx.x & 31, w = threadIdx.x >> 5;
    #pragma unroll
    for (int o = 16; o; o >>= 1) v += __shfl_xor_sync(0xffffffffu, v, o);
    if (lane == 0) sm[w] = v;
    __syncthreads();
    int nw = (blockDim.x + 31) >> 5;
    v = (threadIdx.x < nw) ? sm[threadIdx.x] : 0.f;
    if (w == 0) {
        #pragma unroll
        for (int o = 16; o; o >>= 1) v += __shfl_xor_sync(0xffffffffu, v, o);
        if (lane == 0) sm[0] = v;
    }
    __syncthreads();
    return sm[0];
}

__device__ __forceinline__ unsigned smem_u32(const void* p) {
    return (unsigned)__cvta_generic_to_shared(p);
}
__device__ __forceinline__ void cpa16(unsigned dst, const void* src, bool ok) {
    int sz = ok ? 16 : 0;
    asm volatile("cp.async.cg.shared.global [%0], [%1], 16, %2;\n"
                 :: "r"(dst), "l"(src), "r"(sz));
}
#define CP_COMMIT   asm volatile("cp.async.commit_group;\n")
#define CP_WAITG(N) asm volatile("cp.async.wait_group %0;\n" :: "n"(N))

__device__ __forceinline__ void ldm4(unsigned addr, unsigned* r) {
    asm volatile("ldmatrix.sync.aligned.m8n8.x4.shared.b16 {%0,%1,%2,%3}, [%4];"
        : "=r"(r[0]), "=r"(r[1]), "=r"(r[2]), "=r"(r[3]) : "r"(addr));
}
__device__ __forceinline__ void ldm4t(unsigned addr, unsigned* r) {
    asm volatile("ldmatrix.sync.aligned.m8n8.x4.trans.shared.b16 {%0,%1,%2,%3}, [%4];"
        : "=r"(r[0]), "=r"(r[1]), "=r"(r[2]), "=r"(r[3]) : "r"(addr));
}
__device__ __forceinline__ unsigned packbf2(float lo, float hi) {
    unsigned r;
    asm("cvt.rn.bf16x2.f32 %0, %1, %2;" : "=r"(r) : "f"(hi), "f"(lo));
    return r;
}
#define MMA_BF16(d, a, b) asm volatile( \
  "mma.sync.aligned.m16n8k16.row.col.f32.bf16.bf16.f32 " \
  "{%0,%1,%2,%3},{%4,%5,%6,%7},{%8,%9},{%0,%1,%2,%3};\n" \
  : "+f"(d[0]), "+f"(d[1]), "+f"(d[2]), "+f"(d[3]) \
  : "r"(a[0]), "r"(a[1]), "r"(a[2]), "r"(a[3]), "r"(b[0]), "r"(b[1]))

// ---------------- bf16 tensor-core GEMM: BK=64, 3-stage cp.async pipeline ----------------
// 128 x 128 x 64 tiles, 256 threads (8 warps, 4Mx2N). One sync per 64-K.
// EPI: 2 fused QKV (q rms+rope, k rms+rope, v bf16), 3 fused logits loss.
template<int BN, int EPI>
__global__ __launch_bounds__(256, 2) void gemm_bf(
    const bf16* __restrict__ A, const bf16* __restrict__ B0,
    const bf16* __restrict__ B1, const bf16* __restrict__ B2,
    bf16* __restrict__ Cb, bf16* __restrict__ Cq, bf16* __restrict__ Ck,
    const float* __restrict__ gq, const float* __restrict__ gk,
    int M, int N, int K, int lda, int ldb, int ldc)
{
    constexpr int BM = 128, BK = 64;
    constexpr int NI = BN / 16;
    constexpr int RSB = 144;                 // 64 bf16 = 128B + 16B pad
    constexpr int ABYTES = BM * RSB;         // 18432
    constexpr int BBYTES = BN * RSB;         // 18432
    constexpr int STG = ABYTES + BBYTES;     // 36864
    constexpr int NSTG = 3;

    const int z = blockIdx.z;
    const bf16* Bp;
    if (B1) Bp = (z == 0) ? B0 : ((z == 1) ? B1 : B2);
    else    Bp = B0;

    const int row0 = blockIdx.y * BM, col0 = blockIdx.x * BN;

    extern __shared__ char smdyn[];
    const unsigned sbase = smem_u32(smdyn);
    const int tid = threadIdx.x, lane = tid & 31, warp = tid >> 5;
    const int wm = warp >> 1, wn = warp & 1;

    auto issue = [&](int it, int buf) {
        const int k0 = it * BK;
        const unsigned as = sbase + buf * STG;
        const unsigned bs = as + ABYTES;
        #pragma unroll
        for (int i = 0; i < 4; i++) {          // A: 1024 chunks of 16B
            int c = tid + i * 256;
            int r = c >> 3, kc = c & 7;
            int gk0 = k0 + kc * 8;
            bool ok = (row0 + r < M) && (gk0 < K);
            const bf16* src = ok ? (A + (size_t)(row0 + r) * lda + gk0) : A;
            cpa16(as + r * RSB + kc * 16, src, ok);
        }
        constexpr int BCH = BN * 8;
        #pragma unroll
        for (int i = 0; i < BCH / 256; i++) {  // B: BN*8 chunks
            int c = tid + i * 256;
            int r = c >> 3, kc = c & 7;
            int gk0 = k0 + kc * 8;
            bool ok = (col0 + r < N) && (gk0 < K);
            const bf16* src = ok ? (Bp + (size_t)(col0 + r) * ldb + gk0) : Bp;
            cpa16(bs + r * RSB + kc * 16, src, ok);
        }
    };

    float acc[2][NI][4] = {};
    const int nIter = (K + BK - 1) / BK;

    issue(0, 0); CP_COMMIT;
    issue(1, 1); CP_COMMIT;

    const unsigned foff = (unsigned)((lane & 15) * RSB + (lane >> 4) * 16);
    const int gr = lane >> 2, gc = lane & 3;

    for (int it = 0; it < nIter; it++) {
        CP_WAITG(1);
        __syncthreads();
        if (it + 2 < nIter) issue(it + 2, (it + 2) % NSTG);
        CP_COMMIT;
        const unsigned as = sbase + (it % NSTG) * STG;
        const unsigned bs = as + ABYTES;
        #pragma unroll
        for (int ks = 0; ks < 4; ks++) {
            unsigned ra[2][4];
            #pragma unroll
            for (int mi = 0; mi < 2; mi++)
                ldm4(as + (wm * 32 + mi * 16) * RSB + ks * 32 + foff, ra[mi]);
            unsigned rb[NI][2];
            #pragma unroll
            for (int nj = 0; nj < NI / 2; nj++) {
                unsigned t[4];
                ldm4(bs + (wn * (BN / 2) + nj * 16) * RSB + ks * 32 + foff, t);
                rb[nj * 2][0] = t[0]; rb[nj * 2 + 1][0] = t[1];
                rb[nj * 2][1] = t[2]; rb[nj * 2 + 1][1] = t[3];
            }
            #pragma unroll
            for (int mi = 0; mi < 2; mi++)
                #pragma unroll
                for (int ni = 0; ni < NI; ni++)
                    MMA_BF16(acc[mi][ni], ra[mi], rb[ni]);
        }
    }

    if constexpr (EPI == 2) {
        if (z == 2) {
            #pragma unroll
            for (int mi = 0; mi < 2; mi++)
                #pragma unroll
                for (int ni = 0; ni < NI; ni++) {
                    int c = col0 + wn * (BN / 2) + ni * 8 + gc * 2;
                    #pragma unroll
                    for (int rr = 0; rr < 2; rr++) {
                        int r = row0 + wm * 32 + mi * 16 + gr + rr * 8;
                        if (r < M) {
                            unsigned v = packbf2(acc[mi][ni][rr * 2], acc[mi][ni][rr * 2 + 1]);
                            *(unsigned*)(Cb + (size_t)r * ldc + c) = v;
                        }
                    }
                }
        } else {
            const float* gg = (z == 0) ? gq : gk;
            bf16* outp = (z == 0) ? Cq : Ck;
            float gv[8][2];
            #pragma unroll
            for (int ni = 0; ni < 8; ni++) {
                gv[ni][0] = gg[ni * 8 + gc * 2];
                gv[ni][1] = gg[ni * 8 + gc * 2 + 1];
            }
            const int cbase = col0 + wn * 64;
            #pragma unroll
            for (int mi = 0; mi < 2; mi++)
                #pragma unroll
                for (int rr = 0; rr < 2; rr++) {
                    float ss = 0.f;
                    #pragma unroll
                    for (int ni = 0; ni < 8; ni++) {
                        float a0 = acc[mi][ni][rr * 2], a1 = acc[mi][ni][rr * 2 + 1];
                        ss += a0 * a0 + a1 * a1;
                    }
                    ss += __shfl_xor_sync(0xffffffffu, ss, 1);
                    ss += __shfl_xor_sync(0xffffffffu, ss, 2);
                    float rn = rsqrtf(ss * (1.f / 64.f) + 1e-6f);
                    int r = row0 + wm * 32 + mi * 16 + gr + rr * 8;
                    if (r < M) {
                        int t = r % T_;
                        const float* cp = g_cos + t * 64;
                        const float* sp = g_sin + t * 64;
                        #pragma unroll
                        for (int ni = 0; ni < 4; ni++) {
                            int d = ni * 8 + gc * 2;
                            float x1a = acc[mi][ni][rr * 2]     * rn * gv[ni][0];
                            float x1b = acc[mi][ni][rr * 2 + 1] * rn * gv[ni][1];
                            float x2a = acc[mi][ni + 4][rr * 2]     * rn * gv[ni + 4][0];
                            float x2b = acc[mi][ni + 4][rr * 2 + 1] * rn * gv[ni + 4][1];
                            unsigned o1 = packbf2(x1a * cp[d]     - x2a * sp[d],
                                                  x1b * cp[d + 1] - x2b * sp[d + 1]);
                            unsigned o2 = packbf2(x2a * cp[d + 32] + x1a * sp[d + 32],
                                                  x2b * cp[d + 33] + x1b * sp[d + 33]);
                            size_t base = (size_t)r * D_ + cbase + d;
                            *(unsigned*)(outp + base)      = o1;
                            *(unsigned*)(outp + base + 32) = o2;
                        }
                    }
                }
        }
    } else if constexpr (EPI == 3) {
        __shared__ float smr[128];
        if (tid < 128) smr[tid] = 0.f;
        __syncthreads();
        const float LOG2E = 1.4426950408889634f;
        #pragma unroll
        for (int mi = 0; mi < 2; mi++)
            #pragma unroll
            for (int rr = 0; rr < 2; rr++) {
                float rs = 0.f;
                #pragma unroll
                for (int ni = 0; ni < NI; ni++) {
                    rs += exp2f(fmaf(acc[mi][ni][rr * 2],     LOG2E, -32.f));
                    rs += exp2f(fmaf(acc[mi][ni][rr * 2 + 1], LOG2E, -32.f));
                }
                rs += __shfl_xor_sync(0xffffffffu, rs, 1);
                rs += __shfl_xor_sync(0xffffffffu, rs, 2);
                int rl = wm * 32 + mi * 16 + gr + rr * 8;
                if (gc == 0) atomicAdd(&smr[rl], rs);
                int r = row0 + rl;
                if (r < M) {
                    int t = g_tok[r];
                    int rel = t - (col0 + wn * (BN / 2));
                    if (rel >= 0 && rel < BN / 2) {
                        int ni = rel >> 3, within = rel & 7;
                        if ((within >> 1) == gc)
                            g_tgt[r] = acc[mi][ni][rr * 2 + (within & 1)];
                    }
                }
            }
        __syncthreads();
        if (tid < 128) {
            int r = row0 + tid;
            if (r < M) g_part[(size_t)r * 32 + blockIdx.x] = smr[tid];
        }
    }
}

// ---------------- fused SwiGLU FFN GEMM: BK=64, 3-stage ----------------
__global__ __launch_bounds__(256, 2) void gemm_ffn(
    const bf16* __restrict__ A, const bf16* __restrict__ W1, const bf16* __restrict__ W3,
    bf16* __restrict__ C, int M, int N, int K)
{
    constexpr int BM = 128, BN = 64, BK = 64, RSB = 144;
    constexpr int ABYTES = BM * RSB;          // 18432
    constexpr int BBYTES = BN * RSB;          // 9216
    constexpr int STG = ABYTES + 2 * BBYTES;  // 36864
    constexpr int NSTG = 3;

    const int row0 = blockIdx.y * BM, col0 = blockIdx.x * BN;
    extern __shared__ char smdyn[];
    const unsigned sbase = smem_u32(smdyn);
    const int tid = threadIdx.x, lane = tid & 31, warp = tid >> 5;
    const int wm = warp >> 1, wn = warp & 1;

    auto issue = [&](int it, int buf) {
        const int k0 = it * BK;
        const unsigned as = sbase + buf * STG;
        const unsigned b1s = as + ABYTES, b3s = b1s + BBYTES;
        #pragma unroll
        for (int i = 0; i < 4; i++) {
            int c = tid + i * 256;
            int r = c >> 3, kc = c & 7;
            int gk = k0 + kc * 8;
            bool ok = (row0 + r < M) && (gk < K);
            cpa16(as + r * RSB + kc * 16, ok ? A + (size_t)(row0 + r) * K + gk : A, ok);
        }
        #pragma unroll
        for (int i = 0; i < 2; i++) {
            int c = tid + i * 256;
            int r = c >> 3, kc = c & 7;
            int gk = k0 + kc * 8;
            bool ok = (col0 + r < N) && (gk < K);
            cpa16(b1s + r * RSB + kc * 16, ok ? W1 + (size_t)(col0 + r) * K + gk : W1, ok);
            cpa16(b3s + r * RSB + kc * 16, ok ? W3 + (size_t)(col0 + r) * K + gk : W3, ok);
        }
    };

    float acc1[2][4][4] = {}, acc3[2][4][4] = {};
    const int nIter = (K + BK - 1) / BK;
    issue(0, 0); CP_COMMIT;
    issue(1, 1); CP_COMMIT;

    const unsigned foff = (unsigned)((lane & 15) * RSB + (lane >> 4) * 16);
    const int gr = lane >> 2, gc = lane & 3;

    for (int it = 0; it < nIter; it++) {
        CP_WAITG(1);
        __syncthreads();
        if (it + 2 < nIter) issue(it + 2, (it + 2) % NSTG);
        CP_COMMIT;
        const unsigned as = sbase + (it % NSTG) * STG;
        const unsigned b1s = as + ABYTES, b3s = b1s + BBYTES;
        #pragma unroll
        for (int ks = 0; ks < 4; ks++) {
            unsigned ra[2][4];
            #pragma unroll
            for (int mi = 0; mi < 2; mi++)
                ldm4(as + (wm * 32 + mi * 16) * RSB + ks * 32 + foff, ra[mi]);
            unsigned r1[4][2], r3[4][2];
            #pragma unroll
            for (int nj = 0; nj < 2; nj++) {
                unsigned t[4];
                ldm4(b1s + (wn * 32 + nj * 16) * RSB + ks * 32 + foff, t);
                r1[nj * 2][0] = t[0]; r1[nj * 2 + 1][0] = t[1];
                r1[nj * 2][1] = t[2]; r1[nj * 2 + 1][1] = t[3];
                ldm4(b3s + (wn * 32 + nj * 16) * RSB + ks * 32 + foff, t);
                r3[nj * 2][0] = t[0]; r3[nj * 2 + 1][0] = t[1];
                r3[nj * 2][1] = t[2]; r3[nj * 2 + 1][1] = t[3];
            }
            #pragma unroll
            for (int mi = 0; mi < 2; mi++)
                #pragma unroll
                for (int ni = 0; ni < 4; ni++) {
                    MMA_BF16(acc1[mi][ni], ra[mi], r1[ni]);
                    MMA_BF16(acc3[mi][ni], ra[mi], r3[ni]);
                }
        }
    }

    #pragma unroll
    for (int mi = 0; mi < 2; mi++)
        #pragma unroll
        for (int ni = 0; ni < 4; ni++) {
            int c = col0 + wn * 32 + ni * 8 + gc * 2;
            #pragma unroll
            for (int rr = 0; rr < 2; rr++) {
                int r = row0 + wm * 32 + mi * 16 + gr + rr * 8;
                if (r < M) {
                    float x0 = acc1[mi][ni][rr * 2],     y0 = acc3[mi][ni][rr * 2];
                    float x1 = acc1[mi][ni][rr * 2 + 1], y1 = acc3[mi][ni][rr * 2 + 1];
                    float g0 = x0 / (1.f + expf(-x0)) * y0;
                    float g1 = x1 / (1.f + expf(-x1)) * y1;
                    size_t base = (size_t)r * N + c;
                    C[base]     = __float2bfloat16(g0);
                    C[base + 1] = __float2bfloat16(g1);
                }
            }
        }
}

// ---------------- bf16 GEMM, 64x128 tiles, BK=32 4-stage, 3 CTAs/SM ----------------
__global__ __launch_bounds__(128, 3) void gemm64(
    const bf16* __restrict__ A, const bf16* __restrict__ B0, bf16* __restrict__ Cb,
    int M, int N, int K, int lda, int ldb, int ldc)
{
    constexpr int BM = 64, BN = 128, BK = 32, RSB = 80;
    constexpr int ABYTES = BM * RSB;
    constexpr int BBYTES = BN * RSB;
    constexpr int STG = ABYTES + BBYTES;
    constexpr int NSTG = 4;

    const int row0 = blockIdx.y * BM, col0 = blockIdx.x * BN;
    extern __shared__ char smdyn[];
    const unsigned sbase = smem_u32(smdyn);
    const int tid = threadIdx.x, lane = tid & 31, warp = tid >> 5;
    const int wm = warp >> 1, wn = warp & 1;

    auto issue = [&](int it, int buf) {
        const int k0 = it * BK;
        const unsigned as = sbase + buf * STG;
        const unsigned bs = as + ABYTES;
        #pragma unroll
        for (int i = 0; i < 2; i++) {
            int c = tid + i * 128;
            int r = c >> 2, kc = c & 3;
            int gk = k0 + kc * 8;
            bool ok = (row0 + r < M) && (gk < K);
            cpa16(as + r * RSB + kc * 16, ok ? A + (size_t)(row0 + r) * lda + gk : A, ok);
        }
        #pragma unroll
        for (int i = 0; i < 4; i++) {
            int c = tid + i * 128;
            int r = c >> 2, kc = c & 3;
            int gk = k0 + kc * 8;
            bool ok = (col0 + r < N) && (gk < K);
            cpa16(bs + r * RSB + kc * 16, ok ? B0 + (size_t)(col0 + r) * ldb + gk : B0, ok);
        }
    };

    float acc[2][8][4] = {};
    const int nIter = (K + BK - 1) / BK;
    issue(0, 0); CP_COMMIT;
    issue(1, 1); CP_COMMIT;
    issue(2, 2); CP_COMMIT;

    const unsigned foff = (unsigned)((lane & 15) * RSB + (lane >> 4) * 16);
    const int gr = lane >> 2, gc = lane & 3;

    for (int it = 0; it < nIter; it++) {
        CP_WAITG(2);
        __syncthreads();
        if (it + 3 < nIter) issue(it + 3, (it + 3) % NSTG);
        CP_COMMIT;
        const unsigned as = sbase + (it % NSTG) * STG;
        const unsigned bs = as + ABYTES;
        #pragma unroll
        for (int ks = 0; ks < 2; ks++) {
            unsigned ra[2][4];
            #pragma unroll
            for (int mi = 0; mi < 2; mi++)
                ldm4(as + (wm * 32 + mi * 16) * RSB + ks * 32 + foff, ra[mi]);
            unsigned rb[8][2];
            #pragma unroll
            for (int nj = 0; nj < 4; nj++) {
                unsigned t[4];
                ldm4(bs + (wn * 64 + nj * 16) * RSB + ks * 32 + foff, t);
                rb[nj * 2][0] = t[0]; rb[nj * 2 + 1][0] = t[1];
                rb[nj * 2][1] = t[2]; rb[nj * 2 + 1][1] = t[3];
            }
            #pragma unroll
            for (int mi = 0; mi < 2; mi++)
                #pragma unroll
                for (int ni = 0; ni < 8; ni++)
                    MMA_BF16(acc[mi][ni], ra[mi], rb[ni]);
        }
    }

    #pragma unroll
    for (int mi = 0; mi < 2; mi++)
        #pragma unroll
        for (int ni = 0; ni < 8; ni++) {
            int c = col0 + wn * 64 + ni * 8 + gc * 2;
            #pragma unroll
            for (int rr = 0; rr < 2; rr++) {
                int r = row0 + wm * 32 + mi * 16 + gr + rr * 8;
                if (r < M && c < N) {
                    unsigned v = packbf2(acc[mi][ni][rr * 2], acc[mi][ni][rr * 2 + 1]);
                    *(unsigned*)(Cb + (size_t)r * ldc + c) = v;
                }
            }
        }
}

// ---------------- fused flash attention (prefix mask, FIXED-max softmax) ----------------
#define FL_ROWB 144
__global__ __launch_bounds__(256, 2) void k_flash() {
    extern __shared__ char smdyn[];
    const unsigned uQ = smem_u32(smdyn);
    const unsigned uK = uQ + 128 * FL_ROWB;
    const unsigned uV = uK + 2 * 128 * FL_ROWB;

    const int z = blockIdx.y;
    const int b = z >> 4, h = z & 15;
    const int row0 = blockIdx.x * 128;
    const int tid = threadIdx.x, lane = tid & 31, warp = tid >> 5;

    int sl, pl; scale_of(min(row0 + 127, T_ - 1), sl, pl);
    const int Lmax = c_bound[sl + 1];
    const int nkb = (Lmax + 127) >> 7;

    const size_t hoff = ((size_t)b * T_) * D_ + h * DH_;
    const bf16* qg = g_qb + hoff;
    const bf16* kg = g_kb + hoff;
    const bf16* vg = g_vb + hoff;
    bf16* og = g_ob + hoff;

    const int lr = tid >> 1, lc0 = (tid & 1) * 4;
    {
        bool ok = (row0 + lr) < T_;
        const bf16* s = qg + (size_t)(row0 + lr) * D_ + lc0 * 8;
        #pragma unroll
        for (int j = 0; j < 4; j++) cpa16(uQ + lr * FL_ROWB + (lc0 + j) * 16, s + j * 8, ok);
    }
    auto issueKV = [&](int kb, int buf) {
        int jr = kb * 128 + lr;
        bool ok = jr < T_;
        const bf16* sk = kg + (size_t)jr * D_ + lc0 * 8;
        const bf16* sv = vg + (size_t)jr * D_ + lc0 * 8;
        unsigned off = buf * (128 * FL_ROWB) + lr * FL_ROWB + lc0 * 16;
        #pragma unroll
        for (int j = 0; j < 4; j++) {
            cpa16(uK + off + j * 16, sk + j * 8, ok);
            cpa16(uV + off + j * 16, sv + j * 8, ok);
        }
    };
    issueKV(0, 0); CP_COMMIT;
    if (nkb > 1) issueKV(1, 1);
    CP_COMMIT;
    CP_WAITG(1);
    __syncthreads();

    const unsigned foff = (unsigned)((lane & 15) * FL_ROWB + (lane >> 4) * 16);
    unsigned aq[4][4];
    #pragma unroll
    for (int ks = 0; ks < 4; ks++)
        ldm4(uQ + (warp * 16) * FL_ROWB + ks * 32 + foff, aq[ks]);

    const int gr = lane >> 2, gc = lane & 3;
    const int r0g = row0 + warp * 16 + gr;
    int Li0 = 0, Li1 = 0;
    if (r0g < T_)     { int s2, p2; scale_of(r0g, s2, p2);     Li0 = c_bound[s2 + 1]; }
    if (r0g + 8 < T_) { int s2, p2; scale_of(r0g + 8, s2, p2); Li1 = c_bound[s2 + 1]; }

    float l0 = 0.f, l1 = 0.f;
    float oacc[8][4] = {};
    const float ALPHA = 0.125f * 1.4426950408889634f;

    for (int kb = 0; kb < nkb; kb++) {
        const unsigned bK = uK + (kb & 1) * (128 * FL_ROWB);
        const unsigned bV = uV + (kb & 1) * (128 * FL_ROWB);

        float sum0 = 0.f, sum1 = 0.f;
        #pragma unroll
        for (int half = 0; half < 2; half++) {
            float s[8][4];
            #pragma unroll
            for (int i = 0; i < 8; i++) { s[i][0] = s[i][1] = s[i][2] = s[i][3] = 0.f; }
            #pragma unroll
            for (int ks = 0; ks < 4; ks++) {
                #pragma unroll
                for (int n2 = 0; n2 < 4; n2++) {
                    unsigned t[4];
                    ldm4(bK + (half * 64 + n2 * 16) * FL_ROWB + ks * 32 + foff, t);
                    unsigned b0[2] = {t[0], t[2]}, b1[2] = {t[1], t[3]};
                    MMA_BF16(s[n2 * 2],     aq[ks], b0);
                    MMA_BF16(s[n2 * 2 + 1], aq[ks], b1);
                }
            }
            const int j0 = kb * 128 + half * 64;
            #pragma unroll
            for (int ni = 0; ni < 8; ni++) {
                int jc = j0 + ni * 8 + 2 * gc;
                float p0 = (jc     < Li0) ? exp2f(fmaf(s[ni][0], ALPHA, -12.f)) : 0.f;
                float p1 = (jc + 1 < Li0) ? exp2f(fmaf(s[ni][1], ALPHA, -12.f)) : 0.f;
                float p2 = (jc     < Li1) ? exp2f(fmaf(s[ni][2], ALPHA, -12.f)) : 0.f;
                float p3 = (jc + 1 < Li1) ? exp2f(fmaf(s[ni][3], ALPHA, -12.f)) : 0.f;
                s[ni][0] = p0; s[ni][1] = p1; s[ni][2] = p2; s[ni][3] = p3;
                sum0 += p0 + p1; sum1 += p2 + p3;
            }
            #pragma unroll
            for (int j = 0; j < 4; j++) {
                unsigned pa[4];
                pa[0] = packbf2(s[2 * j][0],     s[2 * j][1]);
                pa[1] = packbf2(s[2 * j][2],     s[2 * j][3]);
                pa[2] = packbf2(s[2 * j + 1][0], s[2 * j + 1][1]);
                pa[3] = packbf2(s[2 * j + 1][2], s[2 * j + 1][3]);
                unsigned vrow = bV + (half * 64 + j * 16 + (lane & 7)
                                       + 8 * ((lane >> 3) & 1)) * FL_ROWB
                                   + (lane >> 4) * 16;
                #pragma unroll
                for (int d2 = 0; d2 < 4; d2++) {
                    unsigned t[4];
                    ldm4t(vrow + d2 * 32, t);
                    unsigned vb0[2] = {t[0], t[1]}, vb1[2] = {t[2], t[3]};
                    MMA_BF16(oacc[d2 * 2],     pa, vb0);
                    MMA_BF16(oacc[d2 * 2 + 1], pa, vb1);
                }
            }
        }
        sum0 += __shfl_xor_sync(0xffffffffu, sum0, 1);
        sum0 += __shfl_xor_sync(0xffffffffu, sum0, 2);
        sum1 += __shfl_xor_sync(0xffffffffu, sum1, 1);
        sum1 += __shfl_xor_sync(0xffffffffu, sum1, 2);
        l0 += sum0; l1 += sum1;

        __syncthreads();
        if (kb + 2 < nkb) issueKV(kb + 2, kb & 1);
        CP_COMMIT;
        CP_WAITG(1);
        __syncthreads();
    }

    float li0 = 1.f / l0, li1 = 1.f / l1;
    #pragma unroll
    for (int t8 = 0; t8 < 8; t8++) {
        int c = t8 * 8 + 2 * gc;
        if (r0g < T_) {
            og[(size_t)r0g * D_ + c]     = __float2bfloat16(oacc[t8][0] * li0);
            og[(size_t)r0g * D_ + c + 1] = __float2bfloat16(oacc[t8][1] * li0);
        }
        if (r0g + 8 < T_) {
            og[(size_t)(r0g + 8) * D_ + c]     = __float2bfloat16(oacc[t8][2] * li1);
            og[(size_t)(r0g + 8) * D_ + c + 1] = __float2bfloat16(oacc[t8][3] * li1);
        }
    }
}

// ---------------- merged weight + embedding conversion ----------------
__global__ __launch_bounds__(256) void k_convW(
    const float* __restrict__ wq, const float* __restrict__ wk,
    const float* __restrict__ wv, const float* __restrict__ wo,
    const float* __restrict__ w1, const float* __restrict__ w3,
    const float* __restrict__ w2, const float* __restrict__ te) {
    __shared__ float t[64][65];
    int idx = blockIdx.x;
    int tx = threadIdx.x;
    if (idx >= 37056) {
        long long i = (long long)(idx - 37056) * 256 + tx;
        const float4* s4 = (const float4*)te + i * 2;
        float4 a = s4[0], b = s4[1];
        uint4 o;
        o.x = packbf2(a.x, a.y); o.y = packbf2(a.z, a.w);
        o.z = packbf2(b.x, b.y); o.w = packbf2(b.z, b.w);
        ((uint4*)g_embb)[i] = o;
        return;
    }
    const float* src; bf16* dst; int R, C, r0, c0;
    if (idx < 12288) {
        int tsel = idx / 3072, rem = idx % 3072;
        int zz = rem >> 8, tile = rem & 255;
        r0 = (tile >> 4) * 64; c0 = (tile & 15) * 64; R = 1024; C = 1024;
        const float* s4[4] = {wq, wk, wv, wo};
        bf16* d4[4] = {g_wqt, g_wkt, g_wvt, g_wot};
        src = s4[tsel] + (size_t)zz * DD_; dst = d4[tsel] + (size_t)zz * DD_;
    } else if (idx < 28800) {
        int rem = idx - 12288;
        int tsel = rem / 8256; rem %= 8256;
        int zz = rem / 688, tile = rem % 688;
        r0 = (tile / 43) * 64; c0 = (tile % 43) * 64; R = 1024; C = 2752;
        src = (tsel ? w3 : w1) + (size_t)zz * DF_;
        dst = (tsel ? g_w3t : g_w1t) + (size_t)zz * DF_;
    } else {
        int rem = idx - 28800;
        int zz = rem / 688, tile = rem % 688;
        r0 = (tile / 16) * 64; c0 = (tile % 16) * 64; R = 2752; C = 1024;
        src = w2 + (size_t)zz * DF_; dst = g_w2t + (size_t)zz * DF_;
    }
    int lr = tx >> 4, lc = (tx & 15) * 4;
    #pragma unroll
    for (int it = 0; it < 4; it++) {
        int r = it * 16 + lr;
        float4 v = *(const float4*)(src + (size_t)(r0 + r) * C + c0 + lc);
        t[r][lc] = v.x; t[r][lc + 1] = v.y; t[r][lc + 2] = v.z; t[r][lc + 3] = v.w;
    }
    __syncthreads();
    int sc = tx >> 5, sr = (tx & 31) * 2;
    #pragma unroll
    for (int it = 0; it < 8; it++) {
        int cc = it * 8 + sc;
        unsigned v = packbf2(t[sr][cc], t[sr + 1][cc]);
        *(unsigned*)(dst + (size_t)(c0 + cc) * R + r0 + sr) = v;
    }
}

// ---------------- merged setup ----------------
__global__ void k_setup(const int* i0, const int* i1, const int* i2,
                        const int* i3, const int* i4, const int* i5) {
    int t = blockIdx.x, d = threadIdx.x;
    int s, p; scale_of(t, s, p);
    if (d == 0) g_scl[t] = s;
    if (d < 2) {
        const int* arr[6] = {i0, i1, i2, i3, i4, i5};
        int sz = 1 << (2 * s);
        g_tok[d * T_ + t] = arr[s][d * sz + p];
    }
    int i = d & 31;
    float inv = powf(10000.f, -(float)(2 * i) / 64.f);
    float ang = (float)p * inv;
    g_cos[t * 64 + d] = cosf(ang);
    g_sin[t * 64 + d] = sinf(ang);
}

__global__ void k_embed(const float* __restrict__ E, const float* __restrict__ SE,
                        const float* __restrict__ start) {
    int row = blockIdx.x;
    int t = row % T_;
    int s = g_scl[t];
    const float* src = (t == 0) ? start : (E + (long long)g_tok[row] * D_);
    const float* se = SE + s * D_;
    bf16* hb = g_hb + (size_t)row * D_;
    for (int d = threadIdx.x; d < D_; d += blockDim.x)
        hb[d] = __float2bfloat16(src[d] + se[d]);
}

// hb = RMSNorm(hb + delta) * gain, bf16 trunk, fp32 math
__global__ void k_rms(const bf16* __restrict__ delta, const float* __restrict__ gain) {
    int row = blockIdx.x;
    bf16* hb = g_hb + (size_t)row * D_;
    const bf16* dp = delta + (size_t)row * D_;
    int tid = threadIdx.x;
    float x[4];
    float ss = 0.f;
    #pragma unroll
    for (int i = 0; i < 4; i++) {
        int d = tid + i * 256;
        x[i] = __bfloat162float(hb[d]) + __bfloat162float(dp[d]);
        ss += x[i] * x[i];
    }
    ss = blockReduceSum(ss);
    float r = rsqrtf(ss / (float)D_ + 1e-6f);
    #pragma unroll
    for (int i = 0; i < 4; i++) {
        int d = tid + i * 256;
        hb[d] = __float2bfloat16(x[i] * r * gain[d]);
    }
}

__global__ void k_loss_row() {
    int row = blockIdx.x * blockDim.x + threadIdx.x;
    if (row >= BT_) return;
    const float* pp = g_part + (size_t)row * 32;
    float s = 0.f;
    #pragma unroll
    for (int i = 0; i < 32; i++) s += pp[i];
    float lse = logf(s) + 32.f * 0.6931471805599453f;
    g_ce[row] = lse - g_tgt[row];
    g_zl[row] = lse * lse;
}

__global__ void k_loss_final(float* out) {
    float s1 = 0.f, s2 = 0.f;
    for (int j = threadIdx.x; j < BT_; j += blockDim.x) { s1 += g_ce[j]; s2 += g_zl[j]; }
    s1 = blockReduceSum(s1);
    s2 = blockReduceSum(s2);
    if (threadIdx.x == 0) out[0] = s1 / (float)BT_ + ZLOSSW * (s2 / (float)BT_);
}

// ---------------- entry point ----------------
extern "C" void kernel_launch(void* const* d_in, const int* in_sizes, int n_in,
                              void* d_out, int out_size) {
    const int* i0 = (const int*)d_in[0];
    const int* i1 = (const int*)d_in[1];
    const int* i2 = (const int*)d_in[2];
    const int* i3 = (const int*)d_in[3];
    const int* i4 = (const int*)d_in[4];
    const int* i5 = (const int*)d_in[5];
    const float* token_embed = (const float*)d_in[6];
    const float* scale_embed = (const float*)d_in[7];
    const float* start_token = (const float*)d_in[8];
    const float* wq = (const float*)d_in[9];
    const float* wk = (const float*)d_in[10];
    const float* wv = (const float*)d_in[11];
    const float* wo = (const float*)d_in[12];
    const float* qn = (const float*)d_in[13];
    const float* kn = (const float*)d_in[14];
    const float* n1 = (const float*)d_in[15];
    const float* n2 = (const float*)d_in[16];
    const float* w1 = (const float*)d_in[17];
    const float* w3 = (const float*)d_in[18];
    const float* w2 = (const float*)d_in[19];

    cudaFuncSetAttribute((const void*)gemm_bf<128, 2>,
                         cudaFuncAttributeMaxDynamicSharedMemorySize, 110592);
    cudaFuncSetAttribute((const void*)gemm_bf<128, 3>,
                         cudaFuncAttributeMaxDynamicSharedMemorySize, 110592);
    cudaFuncSetAttribute((const void*)gemm64,
                         cudaFuncAttributeMaxDynamicSharedMemorySize, 61440);
    cudaFuncSetAttribute((const void*)gemm_ffn,
                         cudaFuncAttributeMaxDynamicSharedMemorySize, 110592);
    cudaFuncSetAttribute((const void*)k_flash,
                         cudaFuncAttributeMaxDynamicSharedMemorySize, 92160);

    void* p;
    cudaGetSymbolAddress(&p, g_hb);     bf16* hb    = (bf16*)p;
    cudaGetSymbolAddress(&p, g_vb);     bf16* vb    = (bf16*)p;
    cudaGetSymbolAddress(&p, g_qb);     bf16* qb    = (bf16*)p;
    cudaGetSymbolAddress(&p, g_kb);     bf16* kb    = (bf16*)p;
    cudaGetSymbolAddress(&p, g_ob);     bf16* ob    = (bf16*)p;
    cudaGetSymbolAddress(&p, g_tmpb);   bf16* tmpb  = (bf16*)p;
    cudaGetSymbolAddress(&p, g_ggb);    bf16* ggb   = (bf16*)p;
    cudaGetSymbolAddress(&p, g_wqt);    bf16* wqt   = (bf16*)p;
    cudaGetSymbolAddress(&p, g_wkt);    bf16* wkt   = (bf16*)p;
    cudaGetSymbolAddress(&p, g_wvt);    bf16* wvt   = (bf16*)p;
    cudaGetSymbolAddress(&p, g_wot);    bf16* wot   = (bf16*)p;
    cudaGetSymbolAddress(&p, g_w1t);    bf16* w1t   = (bf16*)p;
    cudaGetSymbolAddress(&p, g_w3t);    bf16* w3t   = (bf16*)p;
    cudaGetSymbolAddress(&p, g_w2t);    bf16* w2t   = (bf16*)p;
    cudaGetSymbolAddress(&p, g_embb);   bf16* embb  = (bf16*)p;

    const long long DD = (long long)D_ * D_;
    const long long DF = (long long)D_ * DFF_;

    k_setup<<<T_, 64>>>(i0, i1, i2, i3, i4, i5);
    k_convW<<<39104, 256>>>(wq, wk, wv, wo, w1, w3, w2, token_embed);
    k_embed<<<BT_, 256>>>(token_embed, scale_embed, start_token);

    for (int l = 0; l < NL_; l++) {
        // fused QKV + per-head RMSNorm + RoPE epilogue
        gemm_bf<128, 2><<<dim3(8, 22, 3), 256, 110592>>>(
            hb, wqt + l * DD, wkt + l * DD, wvt + l * DD, vb,
            qb, kb, qn + l * DH_, kn + l * DH_,
            BT_, D_, D_, D_, D_, D_);

        k_flash<<<dim3(11, B_ * H_), 256, 92160>>>();

        gemm64<<<dim3(8, 43), 128, 61440>>>(
            ob, wot + l * DD, tmpb, BT_, D_, D_, D_, D_, D_);

        k_rms<<<BT_, 256>>>(tmpb, n1 + l * D_);

        gemm_ffn<<<dim3(43, 22, 1), 256, 110592>>>(
            hb, w1t + l * DF, w3t + l * DF, ggb, BT_, DFF_, D_);

        gemm64<<<dim3(8, 43), 128, 61440>>>(
            ggb, w2t + l * DF, tmpb, BT_, D_, DFF_, DFF_, DFF_, D_);

        k_rms<<<BT_, 256>>>(tmpb, n2 + l * D_);
    }

    // logits + fused loss partials
    gemm_bf<128, 3><<<dim3(32, 22, 1), 256, 110592>>>(
        hb, embb, nullptr, nullptr, nullptr, nullptr, nullptr, nullptr, nullptr,
        BT_, V_, D_, D_, D_, V_);

    k_loss_row<<<(BT_ + 255) / 256, 256>>>();
    k_loss_final<<<1, 256>>>((float*)d_out);
}

// round 14
// speedup vs baseline: 1.0811x; 1.0116x over previous
#include <cuda_runtime.h>
#include <cuda_bf16.h>
#include <math.h>
#include <float.h>

// ---------------- problem constants ----------------
#define V_  4096
#define D_  1024
#define H_  16
#define DH_ 64
#define NL_ 12
#define DFF_ 2752
#define B_  2
#define T_  1365
#define BT_ (B_*T_)          // 2730
#define ZLOSSW 1e-4f
#define DD_ ((size_t)D_ * D_)
#define DF_ ((size_t)D_ * DFF_)

typedef __nv_bfloat16 bf16;

__device__ __constant__ int c_bound[7] = {0, 1, 5, 21, 85, 341, 1365};

// ---------------- scratch (static device globals) ----------------
__device__ float g_part[(size_t)BT_ * 32];
__device__ float g_tgt[BT_];
__device__ float g_ce[BT_];
__device__ float g_zl[BT_];
__device__ int   g_tok[BT_];
__device__ int   g_scl[T_];
__device__ float g_cos[T_ * DH_];
__device__ float g_sin[T_ * DH_];

__device__ bf16 g_hb[BT_ * D_];
__device__ bf16 g_vb[BT_ * D_];
__device__ bf16 g_qb[BT_ * D_];
__device__ bf16 g_kb[BT_ * D_];
__device__ bf16 g_ob[BT_ * D_];
__device__ bf16 g_tmpb[BT_ * D_];
__device__ bf16 g_ggb[(size_t)BT_ * DFF_];
__device__ bf16 g_wqt[NL_ * D_ * D_];
__device__ bf16 g_wkt[NL_ * D_ * D_];
__device__ bf16 g_wvt[NL_ * D_ * D_];
__device__ bf16 g_wot[NL_ * D_ * D_];
__device__ bf16 g_w1t[(size_t)NL_ * DFF_ * D_];
__device__ bf16 g_w3t[(size_t)NL_ * DFF_ * D_];
__device__ bf16 g_w2t[(size_t)NL_ * D_ * DFF_];
__device__ bf16 g_embb[V_ * D_];

// ---------------- helpers ----------------
__device__ __forceinline__ void scale_of(int t, int& s, int& p) {
    if (t < 1)        { s = 0; p = t; }
    else if (t < 5)   { s = 1; p = t - 1; }
    else if (t < 21)  { s = 2; p = t - 5; }
    else if (t < 85)  { s = 3; p = t - 21; }
    else if (t < 341) { s = 4; p = t - 85; }
    else              { s = 5; p = t - 341; }
}

__device__ __forceinline__ float blockReduceSum(float v) {
    __shared__ float sm[32];
    __syncthreads();
    int lane = threadIdx.x & 31, w = threadIdx.x >> 5;
    #pragma unroll
    for (int o = 16; o; o >>= 1) v += __shfl_xor_sync(0xffffffffu, v, o);
    if (lane == 0) sm[w] = v;
    __syncthreads();
    int nw = (blockDim.x + 31) >> 5;
    v = (threadIdx.x < nw) ? sm[threadIdx.x] : 0.f;
    if (w == 0) {
        #pragma unroll
        for (int o = 16; o; o >>= 1) v += __shfl_xor_sync(0xffffffffu, v, o);
        if (lane == 0) sm[0] = v;
    }
    __syncthreads();
    return sm[0];
}

__device__ __forceinline__ unsigned smem_u32(const void* p) {
    return (unsigned)__cvta_generic_to_shared(p);
}
__device__ __forceinline__ void cpa16(unsigned dst, const void* src, bool ok) {
    int sz = ok ? 16 : 0;
    asm volatile("cp.async.cg.shared.global [%0], [%1], 16, %2;\n"
                 :: "r"(dst), "l"(src), "r"(sz));
}
#define CP_COMMIT   asm volatile("cp.async.commit_group;\n")
#define CP_WAITG(N) asm volatile("cp.async.wait_group %0;\n" :: "n"(N))

__device__ __forceinline__ void ldm4(unsigned addr, unsigned* r) {
    asm volatile("ldmatrix.sync.aligned.m8n8.x4.shared.b16 {%0,%1,%2,%3}, [%4];"
        : "=r"(r[0]), "=r"(r[1]), "=r"(r[2]), "=r"(r[3]) : "r"(addr));
}
__device__ __forceinline__ void ldm4t(unsigned addr, unsigned* r) {
    asm volatile("ldmatrix.sync.aligned.m8n8.x4.trans.shared.b16 {%0,%1,%2,%3}, [%4];"
        : "=r"(r[0]), "=r"(r[1]), "=r"(r[2]), "=r"(r[3]) : "r"(addr));
}
__device__ __forceinline__ unsigned packbf2(float lo, float hi) {
    unsigned r;
    asm("cvt.rn.bf16x2.f32 %0, %1, %2;" : "=r"(r) : "f"(hi), "f"(lo));
    return r;
}
#define MMA_BF16(d, a, b) asm volatile( \
  "mma.sync.aligned.m16n8k16.row.col.f32.bf16.bf16.f32 " \
  "{%0,%1,%2,%3},{%4,%5,%6,%7},{%8,%9},{%0,%1,%2,%3};\n" \
  : "+f"(d[0]), "+f"(d[1]), "+f"(d[2]), "+f"(d[3]) \
  : "r"(a[0]), "r"(a[1]), "r"(a[2]), "r"(a[3]), "r"(b[0]), "r"(b[1]))

// ---------------- bf16 tensor-core GEMM: BK=64, 3-stage cp.async pipeline ----------------
// EPI: 2 fused QKV (q rms+rope, k rms+rope, v bf16), 3 fused logits loss.
template<int BN, int EPI>
__global__ __launch_bounds__(256, 2) void gemm_bf(
    const bf16* __restrict__ A, const bf16* __restrict__ B0,
    const bf16* __restrict__ B1, const bf16* __restrict__ B2,
    bf16* __restrict__ Cb, bf16* __restrict__ Cq, bf16* __restrict__ Ck,
    const float* __restrict__ gq, const float* __restrict__ gk,
    int M, int N, int K, int lda, int ldb, int ldc)
{
    constexpr int BM = 128, BK = 64;
    constexpr int NI = BN / 16;
    constexpr int RSB = 144;
    constexpr int ABYTES = BM * RSB;
    constexpr int BBYTES = BN * RSB;
    constexpr int STG = ABYTES + BBYTES;
    constexpr int NSTG = 3;

    const int z = blockIdx.z;
    const bf16* Bp;
    if (B1) Bp = (z == 0) ? B0 : ((z == 1) ? B1 : B2);
    else    Bp = B0;

    const int row0 = blockIdx.y * BM, col0 = blockIdx.x * BN;

    extern __shared__ char smdyn[];
    const unsigned sbase = smem_u32(smdyn);
    const int tid = threadIdx.x, lane = tid & 31, warp = tid >> 5;
    const int wm = warp >> 1, wn = warp & 1;

    auto issue = [&](int it, int buf) {
        const int k0 = it * BK;
        const unsigned as = sbase + buf * STG;
        const unsigned bs = as + ABYTES;
        #pragma unroll
        for (int i = 0; i < 4; i++) {
            int c = tid + i * 256;
            int r = c >> 3, kc = c & 7;
            int gk0 = k0 + kc * 8;
            bool ok = (row0 + r < M) && (gk0 < K);
            const bf16* src = ok ? (A + (size_t)(row0 + r) * lda + gk0) : A;
            cpa16(as + r * RSB + kc * 16, src, ok);
        }
        constexpr int BCH = BN * 8;
        #pragma unroll
        for (int i = 0; i < BCH / 256; i++) {
            int c = tid + i * 256;
            int r = c >> 3, kc = c & 7;
            int gk0 = k0 + kc * 8;
            bool ok = (col0 + r < N) && (gk0 < K);
            const bf16* src = ok ? (Bp + (size_t)(col0 + r) * ldb + gk0) : Bp;
            cpa16(bs + r * RSB + kc * 16, src, ok);
        }
    };

    float acc[2][NI][4] = {};
    const int nIter = (K + BK - 1) / BK;

    issue(0, 0); CP_COMMIT;
    issue(1, 1); CP_COMMIT;

    const unsigned foff = (unsigned)((lane & 15) * RSB + (lane >> 4) * 16);
    const int gr = lane >> 2, gc = lane & 3;

    for (int it = 0; it < nIter; it++) {
        CP_WAITG(1);
        __syncthreads();
        if (it + 2 < nIter) issue(it + 2, (it + 2) % NSTG);
        CP_COMMIT;
        const unsigned as = sbase + (it % NSTG) * STG;
        const unsigned bs = as + ABYTES;
        #pragma unroll
        for (int ks = 0; ks < 4; ks++) {
            unsigned ra[2][4];
            #pragma unroll
            for (int mi = 0; mi < 2; mi++)
                ldm4(as + (wm * 32 + mi * 16) * RSB + ks * 32 + foff, ra[mi]);
            unsigned rb[NI][2];
            #pragma unroll
            for (int nj = 0; nj < NI / 2; nj++) {
                unsigned t[4];
                ldm4(bs + (wn * (BN / 2) + nj * 16) * RSB + ks * 32 + foff, t);
                rb[nj * 2][0] = t[0]; rb[nj * 2 + 1][0] = t[1];
                rb[nj * 2][1] = t[2]; rb[nj * 2 + 1][1] = t[3];
            }
            #pragma unroll
            for (int mi = 0; mi < 2; mi++)
                #pragma unroll
                for (int ni = 0; ni < NI; ni++)
                    MMA_BF16(acc[mi][ni], ra[mi], rb[ni]);
        }
    }

    if constexpr (EPI == 2) {
        if (z == 2) {
            #pragma unroll
            for (int mi = 0; mi < 2; mi++)
                #pragma unroll
                for (int ni = 0; ni < NI; ni++) {
                    int c = col0 + wn * (BN / 2) + ni * 8 + gc * 2;
                    #pragma unroll
                    for (int rr = 0; rr < 2; rr++) {
                        int r = row0 + wm * 32 + mi * 16 + gr + rr * 8;
                        if (r < M) {
                            unsigned v = packbf2(acc[mi][ni][rr * 2], acc[mi][ni][rr * 2 + 1]);
                            *(unsigned*)(Cb + (size_t)r * ldc + c) = v;
                        }
                    }
                }
        } else {
            const float* gg = (z == 0) ? gq : gk;
            bf16* outp = (z == 0) ? Cq : Ck;
            float gv[8][2];
            #pragma unroll
            for (int ni = 0; ni < 8; ni++) {
                gv[ni][0] = gg[ni * 8 + gc * 2];
                gv[ni][1] = gg[ni * 8 + gc * 2 + 1];
            }
            const int cbase = col0 + wn * 64;
            #pragma unroll
            for (int mi = 0; mi < 2; mi++)
                #pragma unroll
                for (int rr = 0; rr < 2; rr++) {
                    float ss = 0.f;
                    #pragma unroll
                    for (int ni = 0; ni < 8; ni++) {
                        float a0 = acc[mi][ni][rr * 2], a1 = acc[mi][ni][rr * 2 + 1];
                        ss += a0 * a0 + a1 * a1;
                    }
                    ss += __shfl_xor_sync(0xffffffffu, ss, 1);
                    ss += __shfl_xor_sync(0xffffffffu, ss, 2);
                    float rn = rsqrtf(ss * (1.f / 64.f) + 1e-6f);
                    int r = row0 + wm * 32 + mi * 16 + gr + rr * 8;
                    if (r < M) {
                        int t = r % T_;
                        const float* cp = g_cos + t * 64;
                        const float* sp = g_sin + t * 64;
                        #pragma unroll
                        for (int ni = 0; ni < 4; ni++) {
                            int d = ni * 8 + gc * 2;
                            float x1a = acc[mi][ni][rr * 2]     * rn * gv[ni][0];
                            float x1b = acc[mi][ni][rr * 2 + 1] * rn * gv[ni][1];
                            float x2a = acc[mi][ni + 4][rr * 2]     * rn * gv[ni + 4][0];
                            float x2b = acc[mi][ni + 4][rr * 2 + 1] * rn * gv[ni + 4][1];
                            unsigned o1 = packbf2(x1a * cp[d]     - x2a * sp[d],
                                                  x1b * cp[d + 1] - x2b * sp[d + 1]);
                            unsigned o2 = packbf2(x2a * cp[d + 32] + x1a * sp[d + 32],
                                                  x2b * cp[d + 33] + x1b * sp[d + 33]);
                            size_t base = (size_t)r * D_ + cbase + d;
                            *(unsigned*)(outp + base)      = o1;
                            *(unsigned*)(outp + base + 32) = o2;
                        }
                    }
                }
        }
    } else if constexpr (EPI == 3) {
        __shared__ float smr[128];
        if (tid < 128) smr[tid] = 0.f;
        __syncthreads();
        const float LOG2E = 1.4426950408889634f;
        #pragma unroll
        for (int mi = 0; mi < 2; mi++)
            #pragma unroll
            for (int rr = 0; rr < 2; rr++) {
                float rs = 0.f;
                #pragma unroll
                for (int ni = 0; ni < NI; ni++) {
                    rs += exp2f(fmaf(acc[mi][ni][rr * 2],     LOG2E, -32.f));
                    rs += exp2f(fmaf(acc[mi][ni][rr * 2 + 1], LOG2E, -32.f));
                }
                rs += __shfl_xor_sync(0xffffffffu, rs, 1);
                rs += __shfl_xor_sync(0xffffffffu, rs, 2);
                int rl = wm * 32 + mi * 16 + gr + rr * 8;
                if (gc == 0) atomicAdd(&smr[rl], rs);
                int r = row0 + rl;
                if (r < M) {
                    int t = g_tok[r];
                    int rel = t - (col0 + wn * (BN / 2));
                    if (rel >= 0 && rel < BN / 2) {
                        int ni = rel >> 3, within = rel & 7;
                        if ((within >> 1) == gc)
                            g_tgt[r] = acc[mi][ni][rr * 2 + (within & 1)];
                    }
                }
            }
        __syncthreads();
        if (tid < 128) {
            int r = row0 + tid;
            if (r < M) g_part[(size_t)r * 32 + blockIdx.x] = smr[tid];
        }
    }
}

// ---------------- fused SwiGLU FFN GEMM: BK=64, 3-stage ----------------
__global__ __launch_bounds__(256, 2) void gemm_ffn(
    const bf16* __restrict__ A, const bf16* __restrict__ W1, const bf16* __restrict__ W3,
    bf16* __restrict__ C, int M, int N, int K)
{
    constexpr int BM = 128, BN = 64, BK = 64, RSB = 144;
    constexpr int ABYTES = BM * RSB;
    constexpr int BBYTES = BN * RSB;
    constexpr int STG = ABYTES + 2 * BBYTES;
    constexpr int NSTG = 3;

    const int row0 = blockIdx.y * BM, col0 = blockIdx.x * BN;
    extern __shared__ char smdyn[];
    const unsigned sbase = smem_u32(smdyn);
    const int tid = threadIdx.x, lane = tid & 31, warp = tid >> 5;
    const int wm = warp >> 1, wn = warp & 1;

    auto issue = [&](int it, int buf) {
        const int k0 = it * BK;
        const unsigned as = sbase + buf * STG;
        const unsigned b1s = as + ABYTES, b3s = b1s + BBYTES;
        #pragma unroll
        for (int i = 0; i < 4; i++) {
            int c = tid + i * 256;
            int r = c >> 3, kc = c & 7;
            int gk = k0 + kc * 8;
            bool ok = (row0 + r < M) && (gk < K);
            cpa16(as + r * RSB + kc * 16, ok ? A + (size_t)(row0 + r) * K + gk : A, ok);
        }
        #pragma unroll
        for (int i = 0; i < 2; i++) {
            int c = tid + i * 256;
            int r = c >> 3, kc = c & 7;
            int gk = k0 + kc * 8;
            bool ok = (col0 + r < N) && (gk < K);
            cpa16(b1s + r * RSB + kc * 16, ok ? W1 + (size_t)(col0 + r) * K + gk : W1, ok);
            cpa16(b3s + r * RSB + kc * 16, ok ? W3 + (size_t)(col0 + r) * K + gk : W3, ok);
        }
    };

    float acc1[2][4][4] = {}, acc3[2][4][4] = {};
    const int nIter = (K + BK - 1) / BK;
    issue(0, 0); CP_COMMIT;
    issue(1, 1); CP_COMMIT;

    const unsigned foff = (unsigned)((lane & 15) * RSB + (lane >> 4) * 16);
    const int gr = lane >> 2, gc = lane & 3;

    for (int it = 0; it < nIter; it++) {
        CP_WAITG(1);
        __syncthreads();
        if (it + 2 < nIter) issue(it + 2, (it + 2) % NSTG);
        CP_COMMIT;
        const unsigned as = sbase + (it % NSTG) * STG;
        const unsigned b1s = as + ABYTES, b3s = b1s + BBYTES;
        #pragma unroll
        for (int ks = 0; ks < 4; ks++) {
            unsigned ra[2][4];
            #pragma unroll
            for (int mi = 0; mi < 2; mi++)
                ldm4(as + (wm * 32 + mi * 16) * RSB + ks * 32 + foff, ra[mi]);
            unsigned r1[4][2], r3[4][2];
            #pragma unroll
            for (int nj = 0; nj < 2; nj++) {
                unsigned t[4];
                ldm4(b1s + (wn * 32 + nj * 16) * RSB + ks * 32 + foff, t);
                r1[nj * 2][0] = t[0]; r1[nj * 2 + 1][0] = t[1];
                r1[nj * 2][1] = t[2]; r1[nj * 2 + 1][1] = t[3];
                ldm4(b3s + (wn * 32 + nj * 16) * RSB + ks * 32 + foff, t);
                r3[nj * 2][0] = t[0]; r3[nj * 2 + 1][0] = t[1];
                r3[nj * 2][1] = t[2]; r3[nj * 2 + 1][1] = t[3];
            }
            #pragma unroll
            for (int mi = 0; mi < 2; mi++)
                #pragma unroll
                for (int ni = 0; ni < 4; ni++) {
                    MMA_BF16(acc1[mi][ni], ra[mi], r1[ni]);
                    MMA_BF16(acc3[mi][ni], ra[mi], r3[ni]);
                }
        }
    }

    #pragma unroll
    for (int mi = 0; mi < 2; mi++)
        #pragma unroll
        for (int ni = 0; ni < 4; ni++) {
            int c = col0 + wn * 32 + ni * 8 + gc * 2;
            #pragma unroll
            for (int rr = 0; rr < 2; rr++) {
                int r = row0 + wm * 32 + mi * 16 + gr + rr * 8;
                if (r < M) {
                    float x0 = acc1[mi][ni][rr * 2],     y0 = acc3[mi][ni][rr * 2];
                    float x1 = acc1[mi][ni][rr * 2 + 1], y1 = acc3[mi][ni][rr * 2 + 1];
                    float g0 = x0 / (1.f + expf(-x0)) * y0;
                    float g1 = x1 / (1.f + expf(-x1)) * y1;
                    size_t base = (size_t)r * N + c;
                    C[base]     = __float2bfloat16(g0);
                    C[base + 1] = __float2bfloat16(g1);
                }
            }
        }
}

// ---------------- bf16 GEMM, 64x128 tiles, BK=32 4-stage, 3 CTAs/SM ----------------
__global__ __launch_bounds__(128, 3) void gemm64(
    const bf16* __restrict__ A, const bf16* __restrict__ B0, bf16* __restrict__ Cb,
    int M, int N, int K, int lda, int ldb, int ldc)
{
    constexpr int BM = 64, BN = 128, BK = 32, RSB = 80;
    constexpr int ABYTES = BM * RSB;
    constexpr int BBYTES = BN * RSB;
    constexpr int STG = ABYTES + BBYTES;
    constexpr int NSTG = 4;

    const int row0 = blockIdx.y * BM, col0 = blockIdx.x * BN;
    extern __shared__ char smdyn[];
    const unsigned sbase = smem_u32(smdyn);
    const int tid = threadIdx.x, lane = tid & 31, warp = tid >> 5;
    const int wm = warp >> 1, wn = warp & 1;

    auto issue = [&](int it, int buf) {
        const int k0 = it * BK;
        const unsigned as = sbase + buf * STG;
        const unsigned bs = as + ABYTES;
        #pragma unroll
        for (int i = 0; i < 2; i++) {
            int c = tid + i * 128;
            int r = c >> 2, kc = c & 3;
            int gk = k0 + kc * 8;
            bool ok = (row0 + r < M) && (gk < K);
            cpa16(as + r * RSB + kc * 16, ok ? A + (size_t)(row0 + r) * lda + gk : A, ok);
        }
        #pragma unroll
        for (int i = 0; i < 4; i++) {
            int c = tid + i * 128;
            int r = c >> 2, kc = c & 3;
            int gk = k0 + kc * 8;
            bool ok = (col0 + r < N) && (gk < K);
            cpa16(bs + r * RSB + kc * 16, ok ? B0 + (size_t)(col0 + r) * ldb + gk : B0, ok);
        }
    };

    float acc[2][8][4] = {};
    const int nIter = (K + BK - 1) / BK;
    issue(0, 0); CP_COMMIT;
    issue(1, 1); CP_COMMIT;
    issue(2, 2); CP_COMMIT;

    const unsigned foff = (unsigned)((lane & 15) * RSB + (lane >> 4) * 16);
    const int gr = lane >> 2, gc = lane & 3;

    for (int it = 0; it < nIter; it++) {
        CP_WAITG(2);
        __syncthreads();
        if (it + 3 < nIter) issue(it + 3, (it + 3) % NSTG);
        CP_COMMIT;
        const unsigned as = sbase + (it % NSTG) * STG;
        const unsigned bs = as + ABYTES;
        #pragma unroll
        for (int ks = 0; ks < 2; ks++) {
            unsigned ra[2][4];
            #pragma unroll
            for (int mi = 0; mi < 2; mi++)
                ldm4(as + (wm * 32 + mi * 16) * RSB + ks * 32 + foff, ra[mi]);
            unsigned rb[8][2];
            #pragma unroll
            for (int nj = 0; nj < 4; nj++) {
                unsigned t[4];
                ldm4(bs + (wn * 64 + nj * 16) * RSB + ks * 32 + foff, t);
                rb[nj * 2][0] = t[0]; rb[nj * 2 + 1][0] = t[1];
                rb[nj * 2][1] = t[2]; rb[nj * 2 + 1][1] = t[3];
            }
            #pragma unroll
            for (int mi = 0; mi < 2; mi++)
                #pragma unroll
                for (int ni = 0; ni < 8; ni++)
                    MMA_BF16(acc[mi][ni], ra[mi], rb[ni]);
        }
    }

    #pragma unroll
    for (int mi = 0; mi < 2; mi++)
        #pragma unroll
        for (int ni = 0; ni < 8; ni++) {
            int c = col0 + wn * 64 + ni * 8 + gc * 2;
            #pragma unroll
            for (int rr = 0; rr < 2; rr++) {
                int r = row0 + wm * 32 + mi * 16 + gr + rr * 8;
                if (r < M && c < N) {
                    unsigned v = packbf2(acc[mi][ni][rr * 2], acc[mi][ni][rr * 2 + 1]);
                    *(unsigned*)(Cb + (size_t)r * ldc + c) = v;
                }
            }
        }
}

// ---------------- fused flash attention (big-tiles-first scheduling) ----------------
// 1-D grid of 352: idx<288 -> big tiles (xb=2..10, nkb=11) first; idx>=288 -> small
// (xb=0,1, nkb=3) last. All big CTAs start in wave 1 (288<=296) => makespan ~halves.
#define FL_ROWB 144
__global__ __launch_bounds__(256, 2) void k_flash() {
    extern __shared__ char smdyn[];
    const unsigned uQ = smem_u32(smdyn);
    const unsigned uK = uQ + 128 * FL_ROWB;
    const unsigned uV = uK + 2 * 128 * FL_ROWB;

    int idx = blockIdx.x;
    int xb, z;
    if (idx < 288) { xb = 2 + idx % 9; z = idx / 9; }
    else           { int r = idx - 288; xb = r & 1; z = r >> 1; }
    const int b = z >> 4, h = z & 15;
    const int row0 = xb * 128;
    const int tid = threadIdx.x, lane = tid & 31, warp = tid >> 5;

    int sl, pl; scale_of(min(row0 + 127, T_ - 1), sl, pl);
    const int Lmax = c_bound[sl + 1];
    const int nkb = (Lmax + 127) >> 7;

    const size_t hoff = ((size_t)b * T_) * D_ + h * DH_;
    const bf16* qg = g_qb + hoff;
    const bf16* kg = g_kb + hoff;
    const bf16* vg = g_vb + hoff;
    bf16* og = g_ob + hoff;

    const int lr = tid >> 1, lc0 = (tid & 1) * 4;
    {
        bool ok = (row0 + lr) < T_;
        const bf16* s = qg + (size_t)(row0 + lr) * D_ + lc0 * 8;
        #pragma unroll
        for (int j = 0; j < 4; j++) cpa16(uQ + lr * FL_ROWB + (lc0 + j) * 16, s + j * 8, ok);
    }
    auto issueKV = [&](int kb, int buf) {
        int jr = kb * 128 + lr;
        bool ok = jr < T_;
        const bf16* sk = kg + (size_t)jr * D_ + lc0 * 8;
        const bf16* sv = vg + (size_t)jr * D_ + lc0 * 8;
        unsigned off = buf * (128 * FL_ROWB) + lr * FL_ROWB + lc0 * 16;
        #pragma unroll
        for (int j = 0; j < 4; j++) {
            cpa16(uK + off + j * 16, sk + j * 8, ok);
            cpa16(uV + off + j * 16, sv + j * 8, ok);
        }
    };
    issueKV(0, 0); CP_COMMIT;
    if (nkb > 1) issueKV(1, 1);
    CP_COMMIT;
    CP_WAITG(1);
    __syncthreads();

    const unsigned foff = (unsigned)((lane & 15) * FL_ROWB + (lane >> 4) * 16);
    unsigned aq[4][4];
    #pragma unroll
    for (int ks = 0; ks < 4; ks++)
        ldm4(uQ + (warp * 16) * FL_ROWB + ks * 32 + foff, aq[ks]);

    const int gr = lane >> 2, gc = lane & 3;
    const int r0g = row0 + warp * 16 + gr;
    int Li0 = 0, Li1 = 0;
    if (r0g < T_)     { int s2, p2; scale_of(r0g, s2, p2);     Li0 = c_bound[s2 + 1]; }
    if (r0g + 8 < T_) { int s2, p2; scale_of(r0g + 8, s2, p2); Li1 = c_bound[s2 + 1]; }

    float l0 = 0.f, l1 = 0.f;
    float oacc[8][4] = {};
    const float ALPHA = 0.125f * 1.4426950408889634f;

    for (int kb = 0; kb < nkb; kb++) {
        const unsigned bK = uK + (kb & 1) * (128 * FL_ROWB);
        const unsigned bV = uV + (kb & 1) * (128 * FL_ROWB);

        float sum0 = 0.f, sum1 = 0.f;
        #pragma unroll
        for (int half = 0; half < 2; half++) {
            float s[8][4];
            #pragma unroll
            for (int i = 0; i < 8; i++) { s[i][0] = s[i][1] = s[i][2] = s[i][3] = 0.f; }
            #pragma unroll
            for (int ks = 0; ks < 4; ks++) {
                #pragma unroll
                for (int n2 = 0; n2 < 4; n2++) {
                    unsigned t[4];
                    ldm4(bK + (half * 64 + n2 * 16) * FL_ROWB + ks * 32 + foff, t);
                    unsigned b0[2] = {t[0], t[2]}, b1[2] = {t[1], t[3]};
                    MMA_BF16(s[n2 * 2],     aq[ks], b0);
                    MMA_BF16(s[n2 * 2 + 1], aq[ks], b1);
                }
            }
            const int j0 = kb * 128 + half * 64;
            #pragma unroll
            for (int ni = 0; ni < 8; ni++) {
                int jc = j0 + ni * 8 + 2 * gc;
                float p0 = (jc     < Li0) ? exp2f(fmaf(s[ni][0], ALPHA, -12.f)) : 0.f;
                float p1 = (jc + 1 < Li0) ? exp2f(fmaf(s[ni][1], ALPHA, -12.f)) : 0.f;
                float p2 = (jc     < Li1) ? exp2f(fmaf(s[ni][2], ALPHA, -12.f)) : 0.f;
                float p3 = (jc + 1 < Li1) ? exp2f(fmaf(s[ni][3], ALPHA, -12.f)) : 0.f;
                s[ni][0] = p0; s[ni][1] = p1; s[ni][2] = p2; s[ni][3] = p3;
                sum0 += p0 + p1; sum1 += p2 + p3;
            }
            #pragma unroll
            for (int j = 0; j < 4; j++) {
                unsigned pa[4];
                pa[0] = packbf2(s[2 * j][0],     s[2 * j][1]);
                pa[1] = packbf2(s[2 * j][2],     s[2 * j][3]);
                pa[2] = packbf2(s[2 * j + 1][0], s[2 * j + 1][1]);
                pa[3] = packbf2(s[2 * j + 1][2], s[2 * j + 1][3]);
                unsigned vrow = bV + (half * 64 + j * 16 + (lane & 7)
                                       + 8 * ((lane >> 3) & 1)) * FL_ROWB
                                   + (lane >> 4) * 16;
                #pragma unroll
                for (int d2 = 0; d2 < 4; d2++) {
                    unsigned t[4];
                    ldm4t(vrow + d2 * 32, t);
                    unsigned vb0[2] = {t[0], t[1]}, vb1[2] = {t[2], t[3]};
                    MMA_BF16(oacc[d2 * 2],     pa, vb0);
                    MMA_BF16(oacc[d2 * 2 + 1], pa, vb1);
                }
            }
        }
        sum0 += __shfl_xor_sync(0xffffffffu, sum0, 1);
        sum0 += __shfl_xor_sync(0xffffffffu, sum0, 2);
        sum1 += __shfl_xor_sync(0xffffffffu, sum1, 1);
        sum1 += __shfl_xor_sync(0xffffffffu, sum1, 2);
        l0 += sum0; l1 += sum1;

        __syncthreads();
        if (kb + 2 < nkb) issueKV(kb + 2, kb & 1);
        CP_COMMIT;
        CP_WAITG(1);
        __syncthreads();
    }

    float li0 = 1.f / l0, li1 = 1.f / l1;
    #pragma unroll
    for (int t8 = 0; t8 < 8; t8++) {
        int c = t8 * 8 + 2 * gc;
        if (r0g < T_) {
            og[(size_t)r0g * D_ + c]     = __float2bfloat16(oacc[t8][0] * li0);
            og[(size_t)r0g * D_ + c + 1] = __float2bfloat16(oacc[t8][1] * li0);
        }
        if (r0g + 8 < T_) {
            og[(size_t)(r0g + 8) * D_ + c]     = __float2bfloat16(oacc[t8][2] * li1);
            og[(size_t)(r0g + 8) * D_ + c + 1] = __float2bfloat16(oacc[t8][3] * li1);
        }
    }
}

// ---------------- merged weight + embedding conversion ----------------
__global__ __launch_bounds__(256) void k_convW(
    const float* __restrict__ wq, const float* __restrict__ wk,
    const float* __restrict__ wv, const float* __restrict__ wo,
    const float* __restrict__ w1, const float* __restrict__ w3,
    const float* __restrict__ w2, const float* __restrict__ te) {
    __shared__ float t[64][65];
    int idx = blockIdx.x;
    int tx = threadIdx.x;
    if (idx >= 37056) {
        long long i = (long long)(idx - 37056) * 256 + tx;
        const float4* s4 = (const float4*)te + i * 2;
        float4 a = s4[0], b = s4[1];
        uint4 o;
        o.x = packbf2(a.x, a.y); o.y = packbf2(a.z, a.w);
        o.z = packbf2(b.x, b.y); o.w = packbf2(b.z, b.w);
        ((uint4*)g_embb)[i] = o;
        return;
    }
    const float* src; bf16* dst; int R, C, r0, c0;
    if (idx < 12288) {
        int tsel = idx / 3072, rem = idx % 3072;
        int zz = rem >> 8, tile = rem & 255;
        r0 = (tile >> 4) * 64; c0 = (tile & 15) * 64; R = 1024; C = 1024;
        const float* s4[4] = {wq, wk, wv, wo};
        bf16* d4[4] = {g_wqt, g_wkt, g_wvt, g_wot};
        src = s4[tsel] + (size_t)zz * DD_; dst = d4[tsel] + (size_t)zz * DD_;
    } else if (idx < 28800) {
        int rem = idx - 12288;
        int tsel = rem / 8256; rem %= 8256;
        int zz = rem / 688, tile = rem % 688;
        r0 = (tile / 43) * 64; c0 = (tile % 43) * 64; R = 1024; C = 2752;
        src = (tsel ? w3 : w1) + (size_t)zz * DF_;
        dst = (tsel ? g_w3t : g_w1t) + (size_t)zz * DF_;
    } else {
        int rem = idx - 28800;
        int zz = rem / 688, tile = rem % 688;
        r0 = (tile / 16) * 64; c0 = (tile % 16) * 64; R = 2752; C = 1024;
        src = w2 + (size_t)zz * DF_; dst = g_w2t + (size_t)zz * DF_;
    }
    int lr = tx >> 4, lc = (tx & 15) * 4;
    #pragma unroll
    for (int it = 0; it < 4; it++) {
        int r = it * 16 + lr;
        float4 v = *(const float4*)(src + (size_t)(r0 + r) * C + c0 + lc);
        t[r][lc] = v.x; t[r][lc + 1] = v.y; t[r][lc + 2] = v.z; t[r][lc + 3] = v.w;
    }
    __syncthreads();
    int sc = tx >> 5, sr = (tx & 31) * 2;
    #pragma unroll
    for (int it = 0; it < 8; it++) {
        int cc = it * 8 + sc;
        unsigned v = packbf2(t[sr][cc], t[sr + 1][cc]);
        *(unsigned*)(dst + (size_t)(c0 + cc) * R + r0 + sr) = v;
    }
}

// ---------------- merged setup ----------------
__global__ void k_setup(const int* i0, const int* i1, const int* i2,
                        const int* i3, const int* i4, const int* i5) {
    int t = blockIdx.x, d = threadIdx.x;
    int s, p; scale_of(t, s, p);
    if (d == 0) g_scl[t] = s;
    if (d < 2) {
        const int* arr[6] = {i0, i1, i2, i3, i4, i5};
        int sz = 1 << (2 * s);
        g_tok[d * T_ + t] = arr[s][d * sz + p];
    }
    int i = d & 31;
    float inv = powf(10000.f, -(float)(2 * i) / 64.f);
    float ang = (float)p * inv;
    g_cos[t * 64 + d] = cosf(ang);
    g_sin[t * 64 + d] = sinf(ang);
}

__global__ void k_embed(const float* __restrict__ E, const float* __restrict__ SE,
                        const float* __restrict__ start) {
    int row = blockIdx.x;
    int t = row % T_;
    int s = g_scl[t];
    const float* src = (t == 0) ? start : (E + (long long)g_tok[row] * D_);
    const float* se = SE + s * D_;
    bf16* hb = g_hb + (size_t)row * D_;
    for (int d = threadIdx.x; d < D_; d += blockDim.x)
        hb[d] = __float2bfloat16(src[d] + se[d]);
}

// hb = RMSNorm(hb + delta) * gain
__global__ void k_rms(const bf16* __restrict__ delta, const float* __restrict__ gain) {
    int row = blockIdx.x;
    bf16* hb = g_hb + (size_t)row * D_;
    const bf16* dp = delta + (size_t)row * D_;
    int tid = threadIdx.x;
    float x[4];
    float ss = 0.f;
    #pragma unroll
    for (int i = 0; i < 4; i++) {
        int d = tid + i * 256;
        x[i] = __bfloat162float(hb[d]) + __bfloat162float(dp[d]);
        ss += x[i] * x[i];
    }
    ss = blockReduceSum(ss);
    float r = rsqrtf(ss / (float)D_ + 1e-6f);
    #pragma unroll
    for (int i = 0; i < 4; i++) {
        int d = tid + i * 256;
        hb[d] = __float2bfloat16(x[i] * r * gain[d]);
    }
}

__global__ void k_loss_row() {
    int row = blockIdx.x * blockDim.x + threadIdx.x;
    if (row >= BT_) return;
    const float* pp = g_part + (size_t)row * 32;
    float s = 0.f;
    #pragma unroll
    for (int i = 0; i < 32; i++) s += pp[i];
    float lse = logf(s) + 32.f * 0.6931471805599453f;
    g_ce[row] = lse - g_tgt[row];
    g_zl[row] = lse * lse;
}

__global__ void k_loss_final(float* out) {
    float s1 = 0.f, s2 = 0.f;
    for (int j = threadIdx.x; j < BT_; j += blockDim.x) { s1 += g_ce[j]; s2 += g_zl[j]; }
    s1 = blockReduceSum(s1);
    s2 = blockReduceSum(s2);
    if (threadIdx.x == 0) out[0] = s1 / (float)BT_ + ZLOSSW * (s2 / (float)BT_);
}

// ---------------- entry point ----------------
extern "C" void kernel_launch(void* const* d_in, const int* in_sizes, int n_in,
                              void* d_out, int out_size) {
    const int* i0 = (const int*)d_in[0];
    const int* i1 = (const int*)d_in[1];
    const int* i2 = (const int*)d_in[2];
    const int* i3 = (const int*)d_in[3];
    const int* i4 = (const int*)d_in[4];
    const int* i5 = (const int*)d_in[5];
    const float* token_embed = (const float*)d_in[6];
    const float* scale_embed = (const float*)d_in[7];
    const float* start_token = (const float*)d_in[8];
    const float* wq = (const float*)d_in[9];
    const float* wk = (const float*)d_in[10];
    const float* wv = (const float*)d_in[11];
    const float* wo = (const float*)d_in[12];
    const float* qn = (const float*)d_in[13];
    const float* kn = (const float*)d_in[14];
    const float* n1 = (const float*)d_in[15];
    const float* n2 = (const float*)d_in[16];
    const float* w1 = (const float*)d_in[17];
    const float* w3 = (const float*)d_in[18];
    const float* w2 = (const float*)d_in[19];

    cudaFuncSetAttribute((const void*)gemm_bf<128, 2>,
                         cudaFuncAttributeMaxDynamicSharedMemorySize, 110592);
    cudaFuncSetAttribute((const void*)gemm_bf<128, 3>,
                         cudaFuncAttributeMaxDynamicSharedMemorySize, 110592);
    cudaFuncSetAttribute((const void*)gemm64,
                         cudaFuncAttributeMaxDynamicSharedMemorySize, 61440);
    cudaFuncSetAttribute((const void*)gemm_ffn,
                         cudaFuncAttributeMaxDynamicSharedMemorySize, 110592);
    cudaFuncSetAttribute((const void*)k_flash,
                         cudaFuncAttributeMaxDynamicSharedMemorySize, 92160);

    void* p;
    cudaGetSymbolAddress(&p, g_hb);     bf16* hb    = (bf16*)p;
    cudaGetSymbolAddress(&p, g_vb);     bf16* vb    = (bf16*)p;
    cudaGetSymbolAddress(&p, g_qb);     bf16* qb    = (bf16*)p;
    cudaGetSymbolAddress(&p, g_kb);     bf16* kb    = (bf16*)p;
    cudaGetSymbolAddress(&p, g_ob);     bf16* ob    = (bf16*)p;
    cudaGetSymbolAddress(&p, g_tmpb);   bf16* tmpb  = (bf16*)p;
    cudaGetSymbolAddress(&p, g_ggb);    bf16* ggb   = (bf16*)p;
    cudaGetSymbolAddress(&p, g_wqt);    bf16* wqt   = (bf16*)p;
    cudaGetSymbolAddress(&p, g_wkt);    bf16* wkt   = (bf16*)p;
    cudaGetSymbolAddress(&p, g_wvt);    bf16* wvt   = (bf16*)p;
    cudaGetSymbolAddress(&p, g_wot);    bf16* wot   = (bf16*)p;
    cudaGetSymbolAddress(&p, g_w1t);    bf16* w1t   = (bf16*)p;
    cudaGetSymbolAddress(&p, g_w3t);    bf16* w3t   = (bf16*)p;
    cudaGetSymbolAddress(&p, g_w2t);    bf16* w2t   = (bf16*)p;
    cudaGetSymbolAddress(&p, g_embb);   bf16* embb  = (bf16*)p;

    const long long DD = (long long)D_ * D_;
    const long long DF = (long long)D_ * DFF_;

    k_setup<<<T_, 64>>>(i0, i1, i2, i3, i4, i5);
    k_convW<<<39104, 256>>>(wq, wk, wv, wo, w1, w3, w2, token_embed);
    k_embed<<<BT_, 256>>>(token_embed, scale_embed, start_token);

    for (int l = 0; l < NL_; l++) {
        gemm_bf<128, 2><<<dim3(8, 22, 3), 256, 110592>>>(
            hb, wqt + l * DD, wkt + l * DD, wvt + l * DD, vb,
            qb, kb, qn + l * DH_, kn + l * DH_,
            BT_, D_, D_, D_, D_, D_);

        k_flash<<<352, 256, 92160>>>();

        gemm64<<<dim3(8, 43), 128, 61440>>>(
            ob, wot + l * DD, tmpb, BT_, D_, D_, D_, D_, D_);

        k_rms<<<BT_, 256>>>(tmpb, n1 + l * D_);

        gemm_ffn<<<dim3(43, 22, 1), 256, 110592>>>(
            hb, w1t + l * DF, w3t + l * DF, ggb, BT_, DFF_, D_);

        gemm64<<<dim3(8, 43), 128, 61440>>>(
            ggb, w2t + l * DF, tmpb, BT_, D_, DFF_, DFF_, DFF_, D_);

        k_rms<<<BT_, 256>>>(tmpb, n2 + l * D_);
    }

    gemm_bf<128, 3><<<dim3(32, 22, 1), 256, 110592>>>(
        hb, embb, nullptr, nullptr, nullptr, nullptr, nullptr, nullptr, nullptr,
        BT_, V_, D_, D_, D_, V_);

    k_loss_row<<<(BT_ + 255) / 256, 256>>>();
    k_loss_final<<<1, 256>>>((float*)d_out);
}

// round 15
// speedup vs baseline: 1.0949x; 1.0127x over previous
#include <cuda_runtime.h>
#include <cuda_bf16.h>
#include <math.h>
#include <float.h>

// ---------------- problem constants ----------------
#define V_  4096
#define D_  1024
#define H_  16
#define DH_ 64
#define NL_ 12
#define DFF_ 2752
#define B_  2
#define T_  1365
#define BT_ (B_*T_)          // 2730
#define ZLOSSW 1e-4f
#define DD_ ((size_t)D_ * D_)
#define DF_ ((size_t)D_ * DFF_)

typedef __nv_bfloat16 bf16;

__device__ __constant__ int c_bound[7] = {0, 1, 5, 21, 85, 341, 1365};

// ---------------- scratch (static device globals) ----------------
__device__ float g_part[(size_t)BT_ * 32];
__device__ float g_tgt[BT_];
__device__ float g_ce[BT_];
__device__ float g_zl[BT_];
__device__ int   g_tok[BT_];
__device__ int   g_scl[T_];
__device__ float g_cos[T_ * DH_];
__device__ float g_sin[T_ * DH_];

__device__ bf16 g_hb[BT_ * D_];
__device__ bf16 g_vb[BT_ * D_];
__device__ bf16 g_qb[BT_ * D_];
__device__ bf16 g_kb[BT_ * D_];
__device__ bf16 g_ob[BT_ * D_];
__device__ bf16 g_tmpb[BT_ * D_];
__device__ bf16 g_ggb[(size_t)BT_ * DFF_];
__device__ bf16 g_wqt[NL_ * D_ * D_];
__device__ bf16 g_wkt[NL_ * D_ * D_];
__device__ bf16 g_wvt[NL_ * D_ * D_];
__device__ bf16 g_wot[NL_ * D_ * D_];
__device__ bf16 g_w1t[(size_t)NL_ * DFF_ * D_];
__device__ bf16 g_w3t[(size_t)NL_ * DFF_ * D_];
__device__ bf16 g_w2t[(size_t)NL_ * D_ * DFF_];
__device__ bf16 g_embb[V_ * D_];

// ---------------- helpers ----------------
__device__ __forceinline__ void scale_of(int t, int& s, int& p) {
    if (t < 1)        { s = 0; p = t; }
    else if (t < 5)   { s = 1; p = t - 1; }
    else if (t < 21)  { s = 2; p = t - 5; }
    else if (t < 85)  { s = 3; p = t - 21; }
    else if (t < 341) { s = 4; p = t - 85; }
    else              { s = 5; p = t - 341; }
}

__device__ __forceinline__ float blockReduceSum(float v) {
    __shared__ float sm[32];
    __syncthreads();
    int lane = threadIdx.x & 31, w = threadIdx.x >> 5;
    #pragma unroll
    for (int o = 16; o; o >>= 1) v += __shfl_xor_sync(0xffffffffu, v, o);
    if (lane == 0) sm[w] = v;
    __syncthreads();
    int nw = (blockDim.x + 31) >> 5;
    v = (threadIdx.x < nw) ? sm[threadIdx.x] : 0.f;
    if (w == 0) {
        #pragma unroll
        for (int o = 16; o; o >>= 1) v += __shfl_xor_sync(0xffffffffu, v, o);
        if (lane == 0) sm[0] = v;
    }
    __syncthreads();
    return sm[0];
}

__device__ __forceinline__ unsigned smem_u32(const void* p) {
    return (unsigned)__cvta_generic_to_shared(p);
}
__device__ __forceinline__ void cpa16(unsigned dst, const void* src, bool ok) {
    int sz = ok ? 16 : 0;
    asm volatile("cp.async.cg.shared.global [%0], [%1], 16, %2;\n"
                 :: "r"(dst), "l"(src), "r"(sz));
}
#define CP_COMMIT   asm volatile("cp.async.commit_group;\n")
#define CP_WAITG(N) asm volatile("cp.async.wait_group %0;\n" :: "n"(N))

__device__ __forceinline__ void ldm4(unsigned addr, unsigned* r) {
    asm volatile("ldmatrix.sync.aligned.m8n8.x4.shared.b16 {%0,%1,%2,%3}, [%4];"
        : "=r"(r[0]), "=r"(r[1]), "=r"(r[2]), "=r"(r[3]) : "r"(addr));
}
__device__ __forceinline__ void ldm4t(unsigned addr, unsigned* r) {
    asm volatile("ldmatrix.sync.aligned.m8n8.x4.trans.shared.b16 {%0,%1,%2,%3}, [%4];"
        : "=r"(r[0]), "=r"(r[1]), "=r"(r[2]), "=r"(r[3]) : "r"(addr));
}
__device__ __forceinline__ unsigned packbf2(float lo, float hi) {
    unsigned r;
    asm("cvt.rn.bf16x2.f32 %0, %1, %2;" : "=r"(r) : "f"(hi), "f"(lo));
    return r;
}
#define MMA_BF16(d, a, b) asm volatile( \
  "mma.sync.aligned.m16n8k16.row.col.f32.bf16.bf16.f32 " \
  "{%0,%1,%2,%3},{%4,%5,%6,%7},{%8,%9},{%0,%1,%2,%3};\n" \
  : "+f"(d[0]), "+f"(d[1]), "+f"(d[2]), "+f"(d[3]) \
  : "r"(a[0]), "r"(a[1]), "r"(a[2]), "r"(a[3]), "r"(b[0]), "r"(b[1]))

// ---------------- bf16 tensor-core GEMM: BK=64, 3-stage, hoisted load addressing ----
// Requires K % 64 == 0 (true for all call sites: 1024, 2752).
// EPI: 2 fused QKV (q rms+rope, k rms+rope, v bf16), 3 fused logits loss.
template<int BN, int EPI>
__global__ __launch_bounds__(256, 2) void gemm_bf(
    const bf16* __restrict__ A, const bf16* __restrict__ B0,
    const bf16* __restrict__ B1, const bf16* __restrict__ B2,
    bf16* __restrict__ Cb, bf16* __restrict__ Cq, bf16* __restrict__ Ck,
    const float* __restrict__ gq, const float* __restrict__ gk,
    int M, int N, int K, int lda, int ldb, int ldc)
{
    constexpr int BM = 128, BK = 64;
    constexpr int NI = BN / 16;
    constexpr int RSB = 144;
    constexpr int ABYTES = BM * RSB;
    constexpr int BBYTES = BN * RSB;
    constexpr int STG = ABYTES + BBYTES;
    constexpr int NSTG = 3;

    const int z = blockIdx.z;
    const bf16* Bp;
    if (B1) Bp = (z == 0) ? B0 : ((z == 1) ? B1 : B2);
    else    Bp = B0;

    const int row0 = blockIdx.y * BM, col0 = blockIdx.x * BN;

    extern __shared__ char smdyn[];
    const unsigned sbase = smem_u32(smdyn);
    const int tid = threadIdx.x, lane = tid & 31, warp = tid >> 5;
    const int wm = warp >> 1, wn = warp & 1;

    // hoisted load mapping: chunk rows = (tid>>3) + i*32, byte col = (tid&7)*16
    const int rA = tid >> 3;
    const unsigned dst0 = (unsigned)rA * RSB + (tid & 7) * 16;
    const bf16* aPtr = A + (size_t)(row0 + rA) * lda + (tid & 7) * 8;
    const bf16* bPtr = Bp + (size_t)(col0 + rA) * ldb + (tid & 7) * 8;
    const size_t stA = (size_t)32 * lda;
    const size_t stB = (size_t)32 * ldb;
    bool okA[4], okB[4];
    #pragma unroll
    for (int i = 0; i < 4; i++) {
        okA[i] = (row0 + rA + i * 32) < M;
        okB[i] = (col0 + rA + i * 32) < N;
    }

    auto issue = [&](int buf) {
        const unsigned as = sbase + buf * STG;
        const unsigned bs = as + ABYTES;
        #pragma unroll
        for (int i = 0; i < 4; i++)
            cpa16(as + dst0 + i * (32 * RSB), okA[i] ? aPtr + i * stA : A, okA[i]);
        #pragma unroll
        for (int i = 0; i < 4; i++)
            cpa16(bs + dst0 + i * (32 * RSB), okB[i] ? bPtr + i * stB : Bp, okB[i]);
        aPtr += BK; bPtr += BK;
    };

    float acc[2][NI][4] = {};
    const int nIter = K / BK;

    issue(0); CP_COMMIT;
    issue(1); CP_COMMIT;

    const unsigned foff = (unsigned)((lane & 15) * RSB + (lane >> 4) * 16);
    const int gr = lane >> 2, gc = lane & 3;

    for (int it = 0; it < nIter; it++) {
        CP_WAITG(1);
        __syncthreads();
        if (it + 2 < nIter) issue((it + 2) % NSTG);
        CP_COMMIT;
        const unsigned as = sbase + (it % NSTG) * STG;
        const unsigned bs = as + ABYTES;
        #pragma unroll
        for (int ks = 0; ks < 4; ks++) {
            unsigned ra[2][4];
            #pragma unroll
            for (int mi = 0; mi < 2; mi++)
                ldm4(as + (wm * 32 + mi * 16) * RSB + ks * 32 + foff, ra[mi]);
            unsigned rb[NI][2];
            #pragma unroll
            for (int nj = 0; nj < NI / 2; nj++) {
                unsigned t[4];
                ldm4(bs + (wn * (BN / 2) + nj * 16) * RSB + ks * 32 + foff, t);
                rb[nj * 2][0] = t[0]; rb[nj * 2 + 1][0] = t[1];
                rb[nj * 2][1] = t[2]; rb[nj * 2 + 1][1] = t[3];
            }
            #pragma unroll
            for (int mi = 0; mi < 2; mi++)
                #pragma unroll
                for (int ni = 0; ni < NI; ni++)
                    MMA_BF16(acc[mi][ni], ra[mi], rb[ni]);
        }
    }

    if constexpr (EPI == 2) {
        if (z == 2) {
            #pragma unroll
            for (int mi = 0; mi < 2; mi++)
                #pragma unroll
                for (int ni = 0; ni < NI; ni++) {
                    int c = col0 + wn * (BN / 2) + ni * 8 + gc * 2;
                    #pragma unroll
                    for (int rr = 0; rr < 2; rr++) {
                        int r = row0 + wm * 32 + mi * 16 + gr + rr * 8;
                        if (r < M) {
                            unsigned v = packbf2(acc[mi][ni][rr * 2], acc[mi][ni][rr * 2 + 1]);
                            *(unsigned*)(Cb + (size_t)r * ldc + c) = v;
                        }
                    }
                }
        } else {
            const float* gg = (z == 0) ? gq : gk;
            bf16* outp = (z == 0) ? Cq : Ck;
            float gv[8][2];
            #pragma unroll
            for (int ni = 0; ni < 8; ni++) {
                gv[ni][0] = gg[ni * 8 + gc * 2];
                gv[ni][1] = gg[ni * 8 + gc * 2 + 1];
            }
            const int cbase = col0 + wn * 64;
            #pragma unroll
            for (int mi = 0; mi < 2; mi++)
                #pragma unroll
                for (int rr = 0; rr < 2; rr++) {
                    float ss = 0.f;
                    #pragma unroll
                    for (int ni = 0; ni < 8; ni++) {
                        float a0 = acc[mi][ni][rr * 2], a1 = acc[mi][ni][rr * 2 + 1];
                        ss += a0 * a0 + a1 * a1;
                    }
                    ss += __shfl_xor_sync(0xffffffffu, ss, 1);
                    ss += __shfl_xor_sync(0xffffffffu, ss, 2);
                    float rn = rsqrtf(ss * (1.f / 64.f) + 1e-6f);
                    int r = row0 + wm * 32 + mi * 16 + gr + rr * 8;
                    if (r < M) {
                        int t = r % T_;
                        const float* cp = g_cos + t * 64;
                        const float* sp = g_sin + t * 64;
                        #pragma unroll
                        for (int ni = 0; ni < 4; ni++) {
                            int d = ni * 8 + gc * 2;
                            float x1a = acc[mi][ni][rr * 2]     * rn * gv[ni][0];
                            float x1b = acc[mi][ni][rr * 2 + 1] * rn * gv[ni][1];
                            float x2a = acc[mi][ni + 4][rr * 2]     * rn * gv[ni + 4][0];
                            float x2b = acc[mi][ni + 4][rr * 2 + 1] * rn * gv[ni + 4][1];
                            unsigned o1 = packbf2(x1a * cp[d]     - x2a * sp[d],
                                                  x1b * cp[d + 1] - x2b * sp[d + 1]);
                            unsigned o2 = packbf2(x2a * cp[d + 32] + x1a * sp[d + 32],
                                                  x2b * cp[d + 33] + x1b * sp[d + 33]);
                            size_t base = (size_t)r * D_ + cbase + d;
                            *(unsigned*)(outp + base)      = o1;
                            *(unsigned*)(outp + base + 32) = o2;
                        }
                    }
                }
        }
    } else if constexpr (EPI == 3) {
        __shared__ float smr[128];
        if (tid < 128) smr[tid] = 0.f;
        __syncthreads();
        const float LOG2E = 1.4426950408889634f;
        #pragma unroll
        for (int mi = 0; mi < 2; mi++)
            #pragma unroll
            for (int rr = 0; rr < 2; rr++) {
                float rs = 0.f;
                #pragma unroll
                for (int ni = 0; ni < NI; ni++) {
                    rs += exp2f(fmaf(acc[mi][ni][rr * 2],     LOG2E, -32.f));
                    rs += exp2f(fmaf(acc[mi][ni][rr * 2 + 1], LOG2E, -32.f));
                }
                rs += __shfl_xor_sync(0xffffffffu, rs, 1);
                rs += __shfl_xor_sync(0xffffffffu, rs, 2);
                int rl = wm * 32 + mi * 16 + gr + rr * 8;
                if (gc == 0) atomicAdd(&smr[rl], rs);
                int r = row0 + rl;
                if (r < M) {
                    int t = g_tok[r];
                    int rel = t - (col0 + wn * (BN / 2));
                    if (rel >= 0 && rel < BN / 2) {
                        int ni = rel >> 3, within = rel & 7;
                        if ((within >> 1) == gc)
                            g_tgt[r] = acc[mi][ni][rr * 2 + (within & 1)];
                    }
                }
            }
        __syncthreads();
        if (tid < 128) {
            int r = row0 + tid;
            if (r < M) g_part[(size_t)r * 32 + blockIdx.x] = smr[tid];
        }
    }
}

// ---------------- fused SwiGLU FFN GEMM: BK=64, 3-stage, hoisted addressing ----------------
__global__ __launch_bounds__(256, 2) void gemm_ffn(
    const bf16* __restrict__ A, const bf16* __restrict__ W1, const bf16* __restrict__ W3,
    bf16* __restrict__ C, int M, int N, int K)
{
    constexpr int BM = 128, BN = 64, BK = 64, RSB = 144;
    constexpr int ABYTES = BM * RSB;
    constexpr int BBYTES = BN * RSB;
    constexpr int STG = ABYTES + 2 * BBYTES;
    constexpr int NSTG = 3;

    const int row0 = blockIdx.y * BM, col0 = blockIdx.x * BN;
    extern __shared__ char smdyn[];
    const unsigned sbase = smem_u32(smdyn);
    const int tid = threadIdx.x, lane = tid & 31, warp = tid >> 5;
    const int wm = warp >> 1, wn = warp & 1;

    const int rA = tid >> 3;
    const unsigned dst0 = (unsigned)rA * RSB + (tid & 7) * 16;
    const bf16* aPtr = A + (size_t)(row0 + rA) * K + (tid & 7) * 8;
    const bf16* w1Ptr = W1 + (size_t)(col0 + rA) * K + (tid & 7) * 8;
    const bf16* w3Ptr = W3 + (size_t)(col0 + rA) * K + (tid & 7) * 8;
    const size_t st = (size_t)32 * K;
    bool okA[4], okB[2];
    #pragma unroll
    for (int i = 0; i < 4; i++) okA[i] = (row0 + rA + i * 32) < M;
    #pragma unroll
    for (int i = 0; i < 2; i++) okB[i] = (col0 + rA + i * 32) < N;

    auto issue = [&](int buf) {
        const unsigned as = sbase + buf * STG;
        const unsigned b1s = as + ABYTES, b3s = b1s + BBYTES;
        #pragma unroll
        for (int i = 0; i < 4; i++)
            cpa16(as + dst0 + i * (32 * RSB), okA[i] ? aPtr + i * st : A, okA[i]);
        #pragma unroll
        for (int i = 0; i < 2; i++) {
            cpa16(b1s + dst0 + i * (32 * RSB), okB[i] ? w1Ptr + i * st : W1, okB[i]);
            cpa16(b3s + dst0 + i * (32 * RSB), okB[i] ? w3Ptr + i * st : W3, okB[i]);
        }
        aPtr += BK; w1Ptr += BK; w3Ptr += BK;
    };

    float acc1[2][4][4] = {}, acc3[2][4][4] = {};
    const int nIter = K / BK;
    issue(0); CP_COMMIT;
    issue(1); CP_COMMIT;

    const unsigned foff = (unsigned)((lane & 15) * RSB + (lane >> 4) * 16);
    const int gr = lane >> 2, gc = lane & 3;

    for (int it = 0; it < nIter; it++) {
        CP_WAITG(1);
        __syncthreads();
        if (it + 2 < nIter) issue((it + 2) % NSTG);
        CP_COMMIT;
        const unsigned as = sbase + (it % NSTG) * STG;
        const unsigned b1s = as + ABYTES, b3s = b1s + BBYTES;
        #pragma unroll
        for (int ks = 0; ks < 4; ks++) {
            unsigned ra[2][4];
            #pragma unroll
            for (int mi = 0; mi < 2; mi++)
                ldm4(as + (wm * 32 + mi * 16) * RSB + ks * 32 + foff, ra[mi]);
            unsigned r1[4][2], r3[4][2];
            #pragma unroll
            for (int nj = 0; nj < 2; nj++) {
                unsigned t[4];
                ldm4(b1s + (wn * 32 + nj * 16) * RSB + ks * 32 + foff, t);
                r1[nj * 2][0] = t[0]; r1[nj * 2 + 1][0] = t[1];
                r1[nj * 2][1] = t[2]; r1[nj * 2 + 1][1] = t[3];
                ldm4(b3s + (wn * 32 + nj * 16) * RSB + ks * 32 + foff, t);
                r3[nj * 2][0] = t[0]; r3[nj * 2 + 1][0] = t[1];
                r3[nj * 2][1] = t[2]; r3[nj * 2 + 1][1] = t[3];
            }
            #pragma unroll
            for (int mi = 0; mi < 2; mi++)
                #pragma unroll
                for (int ni = 0; ni < 4; ni++) {
                    MMA_BF16(acc1[mi][ni], ra[mi], r1[ni]);
                    MMA_BF16(acc3[mi][ni], ra[mi], r3[ni]);
                }
        }
    }

    #pragma unroll
    for (int mi = 0; mi < 2; mi++)
        #pragma unroll
        for (int ni = 0; ni < 4; ni++) {
            int c = col0 + wn * 32 + ni * 8 + gc * 2;
            #pragma unroll
            for (int rr = 0; rr < 2; rr++) {
                int r = row0 + wm * 32 + mi * 16 + gr + rr * 8;
                if (r < M) {
                    float x0 = acc1[mi][ni][rr * 2],     y0 = acc3[mi][ni][rr * 2];
                    float x1 = acc1[mi][ni][rr * 2 + 1], y1 = acc3[mi][ni][rr * 2 + 1];
                    float g0 = x0 / (1.f + __expf(-x0)) * y0;
                    float g1 = x1 / (1.f + __expf(-x1)) * y1;
                    size_t base = (size_t)r * N + c;
                    C[base]     = __float2bfloat16(g0);
                    C[base + 1] = __float2bfloat16(g1);
                }
            }
        }
}

// ---------------- bf16 GEMM, 64x128 tiles, BK=32 4-stage, 3 CTAs/SM, hoisted ----------------
__global__ __launch_bounds__(128, 3) void gemm64(
    const bf16* __restrict__ A, const bf16* __restrict__ B0, bf16* __restrict__ Cb,
    int M, int N, int K, int lda, int ldb, int ldc)
{
    constexpr int BM = 64, BN = 128, BK = 32, RSB = 80;
    constexpr int ABYTES = BM * RSB;
    constexpr int BBYTES = BN * RSB;
    constexpr int STG = ABYTES + BBYTES;
    constexpr int NSTG = 4;

    const int row0 = blockIdx.y * BM, col0 = blockIdx.x * BN;
    extern __shared__ char smdyn[];
    const unsigned sbase = smem_u32(smdyn);
    const int tid = threadIdx.x, lane = tid & 31, warp = tid >> 5;
    const int wm = warp >> 1, wn = warp & 1;

    const int rA = tid >> 2;
    const unsigned dst0 = (unsigned)rA * RSB + (tid & 3) * 16;
    const bf16* aPtr = A + (size_t)(row0 + rA) * lda + (tid & 3) * 8;
    const bf16* bPtr = B0 + (size_t)(col0 + rA) * ldb + (tid & 3) * 8;
    const size_t stA = (size_t)32 * lda;
    const size_t stB = (size_t)32 * ldb;
    bool okA[2], okB[4];
    #pragma unroll
    for (int i = 0; i < 2; i++) okA[i] = (row0 + rA + i * 32) < M;
    #pragma unroll
    for (int i = 0; i < 4; i++) okB[i] = (col0 + rA + i * 32) < N;

    auto issue = [&](int buf) {
        const unsigned as = sbase + buf * STG;
        const unsigned bs = as + ABYTES;
        #pragma unroll
        for (int i = 0; i < 2; i++)
            cpa16(as + dst0 + i * (32 * RSB), okA[i] ? aPtr + i * stA : A, okA[i]);
        #pragma unroll
        for (int i = 0; i < 4; i++)
            cpa16(bs + dst0 + i * (32 * RSB), okB[i] ? bPtr + i * stB : B0, okB[i]);
        aPtr += BK; bPtr += BK;
    };

    float acc[2][8][4] = {};
    const int nIter = K / BK;
    issue(0); CP_COMMIT;
    issue(1); CP_COMMIT;
    issue(2); CP_COMMIT;

    const unsigned foff = (unsigned)((lane & 15) * RSB + (lane >> 4) * 16);
    const int gr = lane >> 2, gc = lane & 3;

    for (int it = 0; it < nIter; it++) {
        CP_WAITG(2);
        __syncthreads();
        if (it + 3 < nIter) issue((it + 3) % NSTG);
        CP_COMMIT;
        const unsigned as = sbase + (it % NSTG) * STG;
        const unsigned bs = as + ABYTES;
        #pragma unroll
        for (int ks = 0; ks < 2; ks++) {
            unsigned ra[2][4];
            #pragma unroll
            for (int mi = 0; mi < 2; mi++)
                ldm4(as + (wm * 32 + mi * 16) * RSB + ks * 32 + foff, ra[mi]);
            unsigned rb[8][2];
            #pragma unroll
            for (int nj = 0; nj < 4; nj++) {
                unsigned t[4];
                ldm4(bs + (wn * 64 + nj * 16) * RSB + ks * 32 + foff, t);
                rb[nj * 2][0] = t[0]; rb[nj * 2 + 1][0] = t[1];
                rb[nj * 2][1] = t[2]; rb[nj * 2 + 1][1] = t[3];
            }
            #pragma unroll
            for (int mi = 0; mi < 2; mi++)
                #pragma unroll
                for (int ni = 0; ni < 8; ni++)
                    MMA_BF16(acc[mi][ni], ra[mi], rb[ni]);
        }
    }

    #pragma unroll
    for (int mi = 0; mi < 2; mi++)
        #pragma unroll
        for (int ni = 0; ni < 8; ni++) {
            int c = col0 + wn * 64 + ni * 8 + gc * 2;
            #pragma unroll
            for (int rr = 0; rr < 2; rr++) {
                int r = row0 + wm * 32 + mi * 16 + gr + rr * 8;
                if (r < M && c < N) {
                    unsigned v = packbf2(acc[mi][ni][rr * 2], acc[mi][ni][rr * 2 + 1]);
                    *(unsigned*)(Cb + (size_t)r * ldc + c) = v;
                }
            }
        }
}

// ---------------- fused flash attention (big-tiles-first scheduling) ----------------
#define FL_ROWB 144
__global__ __launch_bounds__(256, 2) void k_flash() {
    extern __shared__ char smdyn[];
    const unsigned uQ = smem_u32(smdyn);
    const unsigned uK = uQ + 128 * FL_ROWB;
    const unsigned uV = uK + 2 * 128 * FL_ROWB;

    int idx = blockIdx.x;
    int xb, z;
    if (idx < 288) { xb = 2 + idx % 9; z = idx / 9; }
    else           { int r = idx - 288; xb = r & 1; z = r >> 1; }
    const int b = z >> 4, h = z & 15;
    const int row0 = xb * 128;
    const int tid = threadIdx.x, lane = tid & 31, warp = tid >> 5;

    int sl, pl; scale_of(min(row0 + 127, T_ - 1), sl, pl);
    const int Lmax = c_bound[sl + 1];
    const int nkb = (Lmax + 127) >> 7;

    const size_t hoff = ((size_t)b * T_) * D_ + h * DH_;
    const bf16* qg = g_qb + hoff;
    const bf16* kg = g_kb + hoff;
    const bf16* vg = g_vb + hoff;
    bf16* og = g_ob + hoff;

    const int lr = tid >> 1, lc0 = (tid & 1) * 4;
    {
        bool ok = (row0 + lr) < T_;
        const bf16* s = qg + (size_t)(row0 + lr) * D_ + lc0 * 8;
        #pragma unroll
        for (int j = 0; j < 4; j++) cpa16(uQ + lr * FL_ROWB + (lc0 + j) * 16, s + j * 8, ok);
    }
    auto issueKV = [&](int kb, int buf) {
        int jr = kb * 128 + lr;
        bool ok = jr < T_;
        const bf16* sk = kg + (size_t)jr * D_ + lc0 * 8;
        const bf16* sv = vg + (size_t)jr * D_ + lc0 * 8;
        unsigned off = buf * (128 * FL_ROWB) + lr * FL_ROWB + lc0 * 16;
        #pragma unroll
        for (int j = 0; j < 4; j++) {
            cpa16(uK + off + j * 16, sk + j * 8, ok);
            cpa16(uV + off + j * 16, sv + j * 8, ok);
        }
    };
    issueKV(0, 0); CP_COMMIT;
    if (nkb > 1) issueKV(1, 1);
    CP_COMMIT;
    CP_WAITG(1);
    __syncthreads();

    const unsigned foff = (unsigned)((lane & 15) * FL_ROWB + (lane >> 4) * 16);
    unsigned aq[4][4];
    #pragma unroll
    for (int ks = 0; ks < 4; ks++)
        ldm4(uQ + (warp * 16) * FL_ROWB + ks * 32 + foff, aq[ks]);

    const int gr = lane >> 2, gc = lane & 3;
    const int r0g = row0 + warp * 16 + gr;
    int Li0 = 0, Li1 = 0;
    if (r0g < T_)     { int s2, p2; scale_of(r0g, s2, p2);     Li0 = c_bound[s2 + 1]; }
    if (r0g + 8 < T_) { int s2, p2; scale_of(r0g + 8, s2, p2); Li1 = c_bound[s2 + 1]; }

    float l0 = 0.f, l1 = 0.f;
    float oacc[8][4] = {};
    const float ALPHA = 0.125f * 1.4426950408889634f;

    for (int kb = 0; kb < nkb; kb++) {
        const unsigned bK = uK + (kb & 1) * (128 * FL_ROWB);
        const unsigned bV = uV + (kb & 1) * (128 * FL_ROWB);

        float sum0 = 0.f, sum1 = 0.f;
        #pragma unroll
        for (int half = 0; half < 2; half++) {
            float s[8][4];
            #pragma unroll
            for (int i = 0; i < 8; i++) { s[i][0] = s[i][1] = s[i][2] = s[i][3] = 0.f; }
            #pragma unroll
            for (int ks = 0; ks < 4; ks++) {
                #pragma unroll
                for (int n2 = 0; n2 < 4; n2++) {
                    unsigned t[4];
                    ldm4(bK + (half * 64 + n2 * 16) * FL_ROWB + ks * 32 + foff, t);
                    unsigned b0[2] = {t[0], t[2]}, b1[2] = {t[1], t[3]};
                    MMA_BF16(s[n2 * 2],     aq[ks], b0);
                    MMA_BF16(s[n2 * 2 + 1], aq[ks], b1);
                }
            }
            const int j0 = kb * 128 + half * 64;
            #pragma unroll
            for (int ni = 0; ni < 8; ni++) {
                int jc = j0 + ni * 8 + 2 * gc;
                float p0 = (jc     < Li0) ? exp2f(fmaf(s[ni][0], ALPHA, -12.f)) : 0.f;
                float p1 = (jc + 1 < Li0) ? exp2f(fmaf(s[ni][1], ALPHA, -12.f)) : 0.f;
                float p2 = (jc     < Li1) ? exp2f(fmaf(s[ni][2], ALPHA, -12.f)) : 0.f;
                float p3 = (jc + 1 < Li1) ? exp2f(fmaf(s[ni][3], ALPHA, -12.f)) : 0.f;
                s[ni][0] = p0; s[ni][1] = p1; s[ni][2] = p2; s[ni][3] = p3;
                sum0 += p0 + p1; sum1 += p2 + p3;
            }
            #pragma unroll
            for (int j = 0; j < 4; j++) {
                unsigned pa[4];
                pa[0] = packbf2(s[2 * j][0],     s[2 * j][1]);
                pa[1] = packbf2(s[2 * j][2],     s[2 * j][3]);
                pa[2] = packbf2(s[2 * j + 1][0], s[2 * j + 1][1]);
                pa[3] = packbf2(s[2 * j + 1][2], s[2 * j + 1][3]);
                unsigned vrow = bV + (half * 64 + j * 16 + (lane & 7)
                                       + 8 * ((lane >> 3) & 1)) * FL_ROWB
                                   + (lane >> 4) * 16;
                #pragma unroll
                for (int d2 = 0; d2 < 4; d2++) {
                    unsigned t[4];
                    ldm4t(vrow + d2 * 32, t);
                    unsigned vb0[2] = {t[0], t[1]}, vb1[2] = {t[2], t[3]};
                    MMA_BF16(oacc[d2 * 2],     pa, vb0);
                    MMA_BF16(oacc[d2 * 2 + 1], pa, vb1);
                }
            }
        }
        sum0 += __shfl_xor_sync(0xffffffffu, sum0, 1);
        sum0 += __shfl_xor_sync(0xffffffffu, sum0, 2);
        sum1 += __shfl_xor_sync(0xffffffffu, sum1, 1);
        sum1 += __shfl_xor_sync(0xffffffffu, sum1, 2);
        l0 += sum0; l1 += sum1;

        __syncthreads();
        if (kb + 2 < nkb) issueKV(kb + 2, kb & 1);
        CP_COMMIT;
        CP_WAITG(1);
        __syncthreads();
    }

    float li0 = 1.f / l0, li1 = 1.f / l1;
    #pragma unroll
    for (int t8 = 0; t8 < 8; t8++) {
        int c = t8 * 8 + 2 * gc;
        if (r0g < T_) {
            og[(size_t)r0g * D_ + c]     = __float2bfloat16(oacc[t8][0] * li0);
            og[(size_t)r0g * D_ + c + 1] = __float2bfloat16(oacc[t8][1] * li0);
        }
        if (r0g + 8 < T_) {
            og[(size_t)(r0g + 8) * D_ + c]     = __float2bfloat16(oacc[t8][2] * li1);
            og[(size_t)(r0g + 8) * D_ + c + 1] = __float2bfloat16(oacc[t8][3] * li1);
        }
    }
}

// ---------------- merged weight + embedding conversion ----------------
__global__ __launch_bounds__(256) void k_convW(
    const float* __restrict__ wq, const float* __restrict__ wk,
    const float* __restrict__ wv, const float* __restrict__ wo,
    const float* __restrict__ w1, const float* __restrict__ w3,
    const float* __restrict__ w2, const float* __restrict__ te) {
    __shared__ float t[64][65];
    int idx = blockIdx.x;
    int tx = threadIdx.x;
    if (idx >= 37056) {
        long long i = (long long)(idx - 37056) * 256 + tx;
        const float4* s4 = (const float4*)te + i * 2;
        float4 a = s4[0], b = s4[1];
        uint4 o;
        o.x = packbf2(a.x, a.y); o.y = packbf2(a.z, a.w);
        o.z = packbf2(b.x, b.y); o.w = packbf2(b.z, b.w);
        ((uint4*)g_embb)[i] = o;
        return;
    }
    const float* src; bf16* dst; int R, C, r0, c0;
    if (idx < 12288) {
        int tsel = idx / 3072, rem = idx % 3072;
        int zz = rem >> 8, tile = rem & 255;
        r0 = (tile >> 4) * 64; c0 = (tile & 15) * 64; R = 1024; C = 1024;
        const float* s4[4] = {wq, wk, wv, wo};
        bf16* d4[4] = {g_wqt, g_wkt, g_wvt, g_wot};
        src = s4[tsel] + (size_t)zz * DD_; dst = d4[tsel] + (size_t)zz * DD_;
    } else if (idx < 28800) {
        int rem = idx - 12288;
        int tsel = rem / 8256; rem %= 8256;
        int zz = rem / 688, tile = rem % 688;
        r0 = (tile / 43) * 64; c0 = (tile % 43) * 64; R = 1024; C = 2752;
        src = (tsel ? w3 : w1) + (size_t)zz * DF_;
        dst = (tsel ? g_w3t : g_w1t) + (size_t)zz * DF_;
    } else {
        int rem = idx - 28800;
        int zz = rem / 688, tile = rem % 688;
        r0 = (tile / 16) * 64; c0 = (tile % 16) * 64; R = 2752; C = 1024;
        src = w2 + (size_t)zz * DF_; dst = g_w2t + (size_t)zz * DF_;
    }
    int lr = tx >> 4, lc = (tx & 15) * 4;
    #pragma unroll
    for (int it = 0; it < 4; it++) {
        int r = it * 16 + lr;
        float4 v = *(const float4*)(src + (size_t)(r0 + r) * C + c0 + lc);
        t[r][lc] = v.x; t[r][lc + 1] = v.y; t[r][lc + 2] = v.z; t[r][lc + 3] = v.w;
    }
    __syncthreads();
    int sc = tx >> 5, sr = (tx & 31) * 2;
    #pragma unroll
    for (int it = 0; it < 8; it++) {
        int cc = it * 8 + sc;
        unsigned v = packbf2(t[sr][cc], t[sr + 1][cc]);
        *(unsigned*)(dst + (size_t)(c0 + cc) * R + r0 + sr) = v;
    }
}

// ---------------- merged setup ----------------
__global__ void k_setup(const int* i0, const int* i1, const int* i2,
                        const int* i3, const int* i4, const int* i5) {
    int t = blockIdx.x, d = threadIdx.x;
    int s, p; scale_of(t, s, p);
    if (d == 0) g_scl[t] = s;
    if (d < 2) {
        const int* arr[6] = {i0, i1, i2, i3, i4, i5};
        int sz = 1 << (2 * s);
        g_tok[d * T_ + t] = arr[s][d * sz + p];
    }
    int i = d & 31;
    float inv = powf(10000.f, -(float)(2 * i) / 64.f);
    float ang = (float)p * inv;
    g_cos[t * 64 + d] = cosf(ang);
    g_sin[t * 64 + d] = sinf(ang);
}

__global__ void k_embed(const float* __restrict__ E, const float* __restrict__ SE,
                        const float* __restrict__ start) {
    int row = blockIdx.x;
    int t = row % T_;
    int s = g_scl[t];
    const float* src = (t == 0) ? start : (E + (long long)g_tok[row] * D_);
    const float* se = SE + s * D_;
    bf16* hb = g_hb + (size_t)row * D_;
    for (int d = threadIdx.x; d < D_; d += blockDim.x)
        hb[d] = __float2bfloat16(src[d] + se[d]);
}

// hb = RMSNorm(hb + delta) * gain
__global__ void k_rms(const bf16* __restrict__ delta, const float* __restrict__ gain) {
    int row = blockIdx.x;
    bf16* hb = g_hb + (size_t)row * D_;
    const bf16* dp = delta + (size_t)row * D_;
    int tid = threadIdx.x;
    float x[4];
    float ss = 0.f;
    #pragma unroll
    for (int i = 0; i < 4; i++) {
        int d = tid + i * 256;
        x[i] = __bfloat162float(hb[d]) + __bfloat162float(dp[d]);
        ss += x[i] * x[i];
    }
    ss = blockReduceSum(ss);
    float r = rsqrtf(ss / (float)D_ + 1e-6f);
    #pragma unroll
    for (int i = 0; i < 4; i++) {
        int d = tid + i * 256;
        hb[d] = __float2bfloat16(x[i] * r * gain[d]);
    }
}

__global__ void k_loss_row() {
    int row = blockIdx.x * blockDim.x + threadIdx.x;
    if (row >= BT_) return;
    const float* pp = g_part + (size_t)row * 32;
    float s = 0.f;
    #pragma unroll
    for (int i = 0; i < 32; i++) s += pp[i];
    float lse = logf(s) + 32.f * 0.6931471805599453f;
    g_ce[row] = lse - g_tgt[row];
    g_zl[row] = lse * lse;
}

__global__ void k_loss_final(float* out) {
    float s1 = 0.f, s2 = 0.f;
    for (int j = threadIdx.x; j < BT_; j += blockDim.x) { s1 += g_ce[j]; s2 += g_zl[j]; }
    s1 = blockReduceSum(s1);
    s2 = blockReduceSum(s2);
    if (threadIdx.x == 0) out[0] = s1 / (float)BT_ + ZLOSSW * (s2 / (float)BT_);
}

// ---------------- entry point ----------------
extern "C" void kernel_launch(void* const* d_in, const int* in_sizes, int n_in,
                              void* d_out, int out_size) {
    const int* i0 = (const int*)d_in[0];
    const int* i1 = (const int*)d_in[1];
    const int* i2 = (const int*)d_in[2];
    const int* i3 = (const int*)d_in[3];
    const int* i4 = (const int*)d_in[4];
    const int* i5 = (const int*)d_in[5];
    const float* token_embed = (const float*)d_in[6];
    const float* scale_embed = (const float*)d_in[7];
    const float* start_token = (const float*)d_in[8];
    const float* wq = (const float*)d_in[9];
    const float* wk = (const float*)d_in[10];
    const float* wv = (const float*)d_in[11];
    const float* wo = (const float*)d_in[12];
    const float* qn = (const float*)d_in[13];
    const float* kn = (const float*)d_in[14];
    const float* n1 = (const float*)d_in[15];
    const float* n2 = (const float*)d_in[16];
    const float* w1 = (const float*)d_in[17];
    const float* w3 = (const float*)d_in[18];
    const float* w2 = (const float*)d_in[19];

    cudaFuncSetAttribute((const void*)gemm_bf<128, 2>,
                         cudaFuncAttributeMaxDynamicSharedMemorySize, 110592);
    cudaFuncSetAttribute((const void*)gemm_bf<128, 3>,
                         cudaFuncAttributeMaxDynamicSharedMemorySize, 110592);
    cudaFuncSetAttribute((const void*)gemm64,
                         cudaFuncAttributeMaxDynamicSharedMemorySize, 61440);
    cudaFuncSetAttribute((const void*)gemm_ffn,
                         cudaFuncAttributeMaxDynamicSharedMemorySize, 110592);
    cudaFuncSetAttribute((const void*)k_flash,
                         cudaFuncAttributeMaxDynamicSharedMemorySize, 92160);

    void* p;
    cudaGetSymbolAddress(&p, g_hb);     bf16* hb    = (bf16*)p;
    cudaGetSymbolAddress(&p, g_vb);     bf16* vb    = (bf16*)p;
    cudaGetSymbolAddress(&p, g_qb);     bf16* qb    = (bf16*)p;
    cudaGetSymbolAddress(&p, g_kb);     bf16* kb    = (bf16*)p;
    cudaGetSymbolAddress(&p, g_ob);     bf16* ob    = (bf16*)p;
    cudaGetSymbolAddress(&p, g_tmpb);   bf16* tmpb  = (bf16*)p;
    cudaGetSymbolAddress(&p, g_ggb);    bf16* ggb   = (bf16*)p;
    cudaGetSymbolAddress(&p, g_wqt);    bf16* wqt   = (bf16*)p;
    cudaGetSymbolAddress(&p, g_wkt);    bf16* wkt   = (bf16*)p;
    cudaGetSymbolAddress(&p, g_wvt);    bf16* wvt   = (bf16*)p;
    cudaGetSymbolAddress(&p, g_wot);    bf16* wot   = (bf16*)p;
    cudaGetSymbolAddress(&p, g_w1t);    bf16* w1t   = (bf16*)p;
    cudaGetSymbolAddress(&p, g_w3t);    bf16* w3t   = (bf16*)p;
    cudaGetSymbolAddress(&p, g_w2t);    bf16* w2t   = (bf16*)p;
    cudaGetSymbolAddress(&p, g_embb);   bf16* embb  = (bf16*)p;

    const long long DD = (long long)D_ * D_;
    const long long DF = (long long)D_ * DFF_;

    k_setup<<<T_, 64>>>(i0, i1, i2, i3, i4, i5);
    k_convW<<<39104, 256>>>(wq, wk, wv, wo, w1, w3, w2, token_embed);
    k_embed<<<BT_, 256>>>(token_embed, scale_embed, start_token);

    for (int l = 0; l < NL_; l++) {
        gemm_bf<128, 2><<<dim3(8, 22, 3), 256, 110592>>>(
            hb, wqt + l * DD, wkt + l * DD, wvt + l * DD, vb,
            qb, kb, qn + l * DH_, kn + l * DH_,
            BT_, D_, D_, D_, D_, D_);

        k_flash<<<352, 256, 92160>>>();

        gemm64<<<dim3(8, 43), 128, 61440>>>(
            ob, wot + l * DD, tmpb, BT_, D_, D_, D_, D_, D_);

        k_rms<<<BT_, 256>>>(tmpb, n1 + l * D_);

        gemm_ffn<<<dim3(43, 22, 1), 256, 110592>>>(
            hb, w1t + l * DF, w3t + l * DF, ggb, BT_, DFF_, D_);

        gemm64<<<dim3(8, 43), 128, 61440>>>(
            ggb, w2t + l * DF, tmpb, BT_, D_, DFF_, DFF_, DFF_, D_);

        k_rms<<<BT_, 256>>>(tmpb, n2 + l * D_);
    }

    gemm_bf<128, 3><<<dim3(32, 22, 1), 256, 110592>>>(
        hb, embb, nullptr, nullptr, nullptr, nullptr, nullptr, nullptr, nullptr,
        BT_, V_, D_, D_, D_, V_);

    k_loss_row<<<(BT_ + 255) / 256, 256>>>();
    k_loss_final<<<1, 256>>>((float*)d_out);
}